// round 10
// baseline (speedup 1.0000x reference)
#include <cuda_runtime.h>
#include <cuda_fp16.h>
#include <math.h>
#include <stdint.h>

#define EPSV 1e-5f

// ---- dims ----
#define BB   16
#define CC   32
#define FF   64
#define TT   1024
#define LL   1024
#define HH   512
#define PP   256
#define FEAT2 2048
#define DD   1024
#define NROWS (LL*BB)   // 16384

extern __shared__ char dynsmem[];

// ---- scratch ----
__device__ float g_bufA[BB*CC*FF*TT];
__device__ float g_bufB[BB*CC*FF*TT];
__device__ float g_xn[NROWS*FEAT2];
__device__ float g_xnT[NROWS*FEAT2];       // k-permuted tf32 LN out
__device__ float g_tmp[NROWS*PP];          // k-permuted tf32 GEMM1 out
__device__ float g_U[NROWS*4096];
__device__ float g_sa[NROWS*DD];
__device__ float g_sb[NROWS*DD];
__device__ uint32_t g_w1[6*32*152];        // conv fp16 hi weights [layer][co][kk'] pad152
__device__ uint32_t g_w2[6*32*152];
__device__ float g_bias2[6*32];
__device__ uint32_t g_h1A[BB*FF*TT*16];    // packed fp16-hi, word order ksperm'ed
__device__ uint32_t g_h2A[BB*FF*TT*16];
__device__ uint32_t g_h1B[BB*FF*TT*16];
__device__ uint32_t g_h2B[BB*FF*TT*16];
__device__ float g_wpT[2048*256 + 3*1024*256];
__device__ float g_wwT[4096*256 + 3*3072*256];

__device__ __forceinline__ void cpa16(void* smem, const void* gmem) {
    uint32_t s = (uint32_t)__cvta_generic_to_shared(smem);
    asm volatile("cp.async.cg.shared.global [%0], [%1], 16;\n" :: "r"(s), "l"(gmem));
}
__device__ __forceinline__ void cpa16z(void* smem, const void* gmem, bool ok) {
    uint32_t s = (uint32_t)__cvta_generic_to_shared(smem);
    int sz = ok ? 16 : 0;
    asm volatile("cp.async.cg.shared.global [%0], [%1], 16, %2;\n" :: "r"(s), "l"(gmem), "r"(sz));
}
__device__ __forceinline__ uint32_t f2tf(float x) {
    uint32_t u;
    asm("cvt.rna.tf32.f32 %0, %1;" : "=r"(u) : "f"(x));
    return u;
}
// stored position of logical k within its 8-block: order 0,4,1,5,2,6,3,7
__device__ __forceinline__ int ksperm(int k) {
    return (k & ~7) | (((k & 3) << 1) | ((k >> 2) & 1));
}
__device__ __forceinline__ uint32_t packhi(float a, float b) {
    __half2 h = __halves2half2(__float2half_rn(a), __float2half_rn(b));
    return *(uint32_t*)&h;
}
__device__ __forceinline__ uint32_t packlo(float a, float b) {
    __half ha = __float2half_rn(a), hb = __float2half_rn(b);
    __half2 l = __halves2half2(__float2half_rn(a - __half2float(ha)),
                               __float2half_rn(b - __half2float(hb)));
    return *(uint32_t*)&l;
}

// ============================================================
// ALL weight transposes in one launch (GEMM weights)
// ============================================================
__global__ void trT_all_kernel(const float* __restrict__ wproj0,
                               const float* __restrict__ w0,
                               const float* __restrict__ wproj,
                               const float* __restrict__ w,
                               float* __restrict__ wpT,
                               float* __restrict__ wwT) {
    int bid = blockIdx.x;
    const float* W; float* WT; int K, N, nx, base;
    if (bid < 512)        { W = wproj0; WT = wpT;  K = 2048; N = 256;  nx = 8;   base = 0; }
    else if (bid < 1536)  { W = w0;     WT = wwT;  K = 256;  N = 4096; nx = 128; base = 512; }
    else if (bid < 2304)  {
        int i = (bid - 1536) >> 8;
        W = wproj + (size_t)i*262144; WT = wpT + 524288 + i*262144;
        K = 1024; N = 256; nx = 8; base = 1536 + i*256;
    } else {
        int i = (bid - 2304) / 768;
        W = w + (size_t)i*786432; WT = wwT + 1048576 + i*786432;
        K = 256; N = 3072; nx = 96; base = 2304 + i*768;
    }
    int r = bid - base;
    int n0 = (r % nx) * 32, k0 = (r / nx) * 32;

    __shared__ float tile[32][33];
    int tx = threadIdx.x, ty = threadIdx.y;  // (32,8)
#pragma unroll
    for (int i = 0; i < 4; i++)
        tile[ty + 8*i][tx] = W[(size_t)(k0 + ty + 8*i)*N + n0 + tx];
    __syncthreads();
    int kst = k0 + ksperm(tx);
#pragma unroll
    for (int i = 0; i < 4; i++) {
        int n = n0 + ty + 8*i;
        WT[(size_t)n*K + kst] = __uint_as_float(f2tf(tile[tx][ty + 8*i]));
    }
}

// ============================================================
// conv0 -> NHWC fp32 + packed fp16 hi/lo (word order permuted)
// ============================================================
__global__ void conv0_kernel(const float* __restrict__ x,
                             const float* __restrict__ w,
                             const float* __restrict__ cb,
                             float* __restrict__ out,
                             uint32_t* __restrict__ oh1,
                             uint32_t* __restrict__ oh2) {
    __shared__ float ws[288];
    __shared__ float bs[32];
    int tid = threadIdx.x;
    for (int i = tid; i < 288; i += 256) {
        int co = i / 9, j = i % 9;
        ws[j*32 + co] = w[i];
    }
    if (tid < 32) bs[tid] = cb[tid];
    __syncthreads();

    int to = blockIdx.x * 256 + tid;
    int fo = blockIdx.y;
    int b  = blockIdx.z;

    float acc[32];
#pragma unroll
    for (int q = 0; q < 32; q++) acc[q] = bs[q];

#pragma unroll
    for (int df = 0; df < 3; df++) {
        int xi = 2*fo + df - 1;
        if (xi < 0 || xi >= 128) continue;
#pragma unroll
        for (int dt = 0; dt < 3; dt++) {
            int ti = 2*to + dt - 1;
            if (ti < 0 || ti >= 2048) continue;
            float v = x[((size_t)b*128 + xi)*2048 + ti];
            int j = df*3 + dt;
#pragma unroll
            for (int q = 0; q < 8; q++) {
                float4 w4 = *(const float4*)&ws[j*32 + q*4];
                acc[q*4+0] = fmaf(v, w4.x, acc[q*4+0]);
                acc[q*4+1] = fmaf(v, w4.y, acc[q*4+1]);
                acc[q*4+2] = fmaf(v, w4.z, acc[q*4+2]);
                acc[q*4+3] = fmaf(v, w4.w, acc[q*4+3]);
            }
        }
    }
    size_t pos = ((size_t)b*64 + fo)*1024 + to;
#pragma unroll
    for (int q = 0; q < 8; q++)
        *(float4*)&out[pos*32 + q*4] = make_float4(acc[q*4], acc[q*4+1], acc[q*4+2], acc[q*4+3]);

    uint32_t hw_[16], lw_[16];
#pragma unroll
    for (int p = 0; p < 16; p++) {
        int ps = ksperm(p);
        hw_[ps] = packhi(acc[2*p], acc[2*p+1]);
        lw_[ps] = packlo(acc[2*p], acc[2*p+1]);
    }
#pragma unroll
    for (int q = 0; q < 4; q++) {
        *(uint4*)&oh1[pos*16 + q*4] = *(uint4*)&hw_[q*4];
        *(uint4*)&oh2[pos*16 + q*4] = *(uint4*)&lw_[q*4];
    }
}

// ============================================================
// prep ALL 6 conv layers: [co][kk'] layout, stride 152
// ============================================================
__global__ void prep_conv_all_kernel(const float* __restrict__ rc1w,
                                     const float* __restrict__ rc1b,
                                     const float* __restrict__ rb1g,
                                     const float* __restrict__ rb1b,
                                     const float* __restrict__ rb1m,
                                     const float* __restrict__ rb1v,
                                     const float* __restrict__ rc2w,
                                     const float* __restrict__ rc2b,
                                     const float* __restrict__ rb2g,
                                     const float* __restrict__ rb2b,
                                     const float* __restrict__ rb2m,
                                     const float* __restrict__ rb2v,
                                     uint32_t* __restrict__ w1,
                                     uint32_t* __restrict__ w2,
                                     float* __restrict__ bias2) {
    int layer = blockIdx.y;
    int bi = layer >> 1, sec = layer & 1;
    const float* w   = (sec ? rc2w : rc1w) + bi*9216;
    const float* cb  = (sec ? rc2b : rc1b) + bi*32;
    const float* g   = (sec ? rb2g : rb1g) + bi*32;
    const float* bt  = (sec ? rb2b : rb1b) + bi*32;
    const float* m   = (sec ? rb2m : rb1m) + bi*32;
    const float* v   = (sec ? rb2v : rb1v) + bi*32;
    uint32_t* o1 = w1 + layer*4864;
    uint32_t* o2 = w2 + layer*4864;
    float* ob = bias2 + layer*32;

    int i = blockIdx.x * blockDim.x + threadIdx.x;
    if (i < 4608) {
        int co  = i & 31;
        int kk  = i >> 5;              // logical kk = j*16 + ci2
        int j   = kk >> 4;
        int ci2 = kk & 15;
        float scale = g[co] * rsqrtf(v[co] + EPSV);
        float f0 = w[co*288 + (2*ci2    )*9 + j] * scale;
        float f1 = w[co*288 + (2*ci2 + 1)*9 + j] * scale;
        int kks = ksperm(kk);
        o1[co*152 + kks] = packhi(f0, f1);
        o2[co*152 + kks] = packlo(f0, f1);
    }
    if (i < 32) {
        float scale = g[i] * rsqrtf(v[i] + EPSV);
        ob[i] = bt[i] + (cb[i] - m[i]) * scale;
    }
}

// ============================================================
// residual conv v3: 512 thr, 2 f-rows, LDS.64 fragments
// A slabs [4][130][24]; W [32][152]
// ============================================================
__device__ __forceinline__ void mma_f16(float* c, const uint32_t* a, const uint32_t* b) {
    asm volatile(
        "mma.sync.aligned.m16n8k16.row.col.f32.f16.f16.f32 "
        "{%0,%1,%2,%3}, {%4,%5,%6,%7}, {%8,%9}, {%0,%1,%2,%3};\n"
        : "+f"(c[0]), "+f"(c[1]), "+f"(c[2]), "+f"(c[3])
        : "r"(a[0]), "r"(a[1]), "r"(a[2]), "r"(a[3]),
          "r"(b[0]), "r"(b[1]));
}

#define RC_SLAB  3120          // 130*24 words per slab
#define RC_A1 0                // [4][130][24] = 12480
#define RC_A2 12480
#define RC_W1 24960            // [32][152] = 4864
#define RC_W2 29824
#define RC_WORDS 34688         // *4 = 138752 bytes

__global__ __launch_bounds__(512)
void resconv_mma_kernel(const uint32_t* __restrict__ ih1,
                        const uint32_t* __restrict__ ih2,
                        const uint32_t* __restrict__ w1g,
                        const uint32_t* __restrict__ w2g,
                        const float* __restrict__ bias2,
                        const float* __restrict__ res,
                        float* __restrict__ out,
                        uint32_t* __restrict__ oh1,
                        uint32_t* __restrict__ oh2) {
    uint32_t* sm = (uint32_t*)dynsmem;
    uint32_t* A1 = sm + RC_A1;
    uint32_t* A2 = sm + RC_A2;
    uint32_t* W1 = sm + RC_W1;
    uint32_t* W2 = sm + RC_W2;
    __shared__ float bs[32];

    int tid = threadIdx.x;
    int t0 = blockIdx.x * 128;
    int f0 = blockIdx.y * 2;
    int b  = blockIdx.z;

    if (tid < 32) bs[tid] = bias2[tid];

    // weights: 1216 granules each
    for (int i = tid; i < 1216; i += 512) {
        cpa16(W1 + i*4, w1g + i*4);
        cpa16(W2 + i*4, w2g + i*4);
    }
    // 4 halo slabs; 520 granules per slab (130 rows x 4)
    for (int idx = tid; idx < 2080; idx += 512) {
        int s   = idx / 520;
        int rem = idx - s*520;
        int r = rem >> 2, gq = rem & 3;
        int xi = f0 - 1 + s;
        int t  = t0 - 1 + r;
        bool ok = (xi >= 0) && (xi < 64) && (t >= 0) && (t < 1024);
        size_t off = ok ? ((((size_t)b*64 + xi)*1024 + t)*16 + gq*4) : 0;
        int dst = s*RC_SLAB + r*24 + gq*4;
        cpa16z(A1 + dst, ih1 + off, ok);
        cpa16z(A2 + dst, ih2 + off, ok);
    }
    asm volatile("cp.async.commit_group;\n");
    asm volatile("cp.async.wait_group 0;\n");
    __syncthreads();

    int lane = tid & 31, wid = tid >> 5;
    int fi = wid >> 3;              // plane 0/1
    int w8 = wid & 7;
    int f  = f0 + fi;
    int g = lane >> 2, tg = lane & 3;
    int rowA = w8 * 16;

    float acc[4][4];
#pragma unroll
    for (int nt = 0; nt < 4; nt++)
#pragma unroll
        for (int i = 0; i < 4; i++) acc[nt][i] = 0.f;

#pragma unroll
    for (int j = 0; j < 9; j++) {
        const int df = j / 3, dt = j % 3;
        const uint32_t* a1s = A1 + (fi + df)*RC_SLAB + (rowA + dt)*24;
        const uint32_t* a2s = A2 + (fi + df)*RC_SLAB + (rowA + dt)*24;
        const int wcol = j*16;
#pragma unroll
        for (int h = 0; h < 2; h++) {
            int kb = h*8 + 2*tg;
            uint32_t a1f[4], a2f[4];
            {
                uint2 lo1 = *(const uint2*)&a1s[(g    )*24 + kb];
                uint2 hi1 = *(const uint2*)&a1s[(g + 8)*24 + kb];
                a1f[0] = lo1.x; a1f[2] = lo1.y;
                a1f[1] = hi1.x; a1f[3] = hi1.y;
                uint2 lo2 = *(const uint2*)&a2s[(g    )*24 + kb];
                uint2 hi2 = *(const uint2*)&a2s[(g + 8)*24 + kb];
                a2f[0] = lo2.x; a2f[2] = lo2.y;
                a2f[1] = hi2.x; a2f[3] = hi2.y;
            }
#pragma unroll
            for (int nt = 0; nt < 4; nt++) {
                int co = nt*8 + g;
                uint2 b1 = *(const uint2*)&W1[co*152 + wcol + kb];
                uint2 b2 = *(const uint2*)&W2[co*152 + wcol + kb];
                uint32_t b1f[2] = {b1.x, b1.y};
                uint32_t b2f[2] = {b2.x, b2.y};
                mma_f16(acc[nt], a1f, b1f);
                mma_f16(acc[nt], a2f, b1f);
                mma_f16(acc[nt], a1f, b2f);
            }
        }
    }

    bool hasres = (res != nullptr);
    bool hash   = (oh1 != nullptr);
    __syncthreads();   // done reading slabs; reuse A1/A2 for packing

    float vv[4][4];
#pragma unroll
    for (int nt = 0; nt < 4; nt++) {
        int co = nt*8 + tg*2;
#pragma unroll
        for (int half = 0; half < 2; half++) {
            int t = t0 + rowA + g + half*8;
            size_t addr = (((size_t)b*64 + f)*1024 + t)*32 + co;
            float v0 = acc[nt][half*2 + 0] + bs[co];
            float v1 = acc[nt][half*2 + 1] + bs[co + 1];
            if (hasres) {
                float2 rv = *(const float2*)(res + addr);
                v0 += rv.x; v1 += rv.y;
            }
            v0 = fmaxf(v0, 0.f); v1 = fmaxf(v1, 0.f);
            *(float2*)(out + addr) = make_float2(v0, v1);
            vv[nt][half*2]   = v0;
            vv[nt][half*2+1] = v1;
        }
    }

    if (hash) {
        // pack (permuted word order) into A1/A2 plane regions
#pragma unroll
        for (int nt = 0; nt < 4; nt++) {
            int wd = ksperm(nt*4 + tg);
#pragma unroll
            for (int half = 0; half < 2; half++) {
                int tl = rowA + g + half*8;
                A1[fi*RC_SLAB + tl*24 + wd] = packhi(vv[nt][half*2], vv[nt][half*2+1]);
                A2[fi*RC_SLAB + tl*24 + wd] = packlo(vv[nt][half*2], vv[nt][half*2+1]);
            }
        }
        __syncthreads();
#pragma unroll
        for (int l = 0; l < 2; l++) {
            int idx = tid + l*512;          // 0..1023
            int pf  = idx >> 9;
            int rr  = (idx >> 2) & 127;
            int q   = idx & 3;
            size_t posb = ((size_t)b*64 + f0 + pf)*1024 + t0;
            *(uint4*)&oh1[(posb + rr)*16 + q*4] = *(uint4*)&A1[pf*RC_SLAB + rr*24 + q*4];
            *(uint4*)&oh2[(posb + rr)*16 + q*4] = *(uint4*)&A2[pf*RC_SLAB + rr*24 + q*4];
        }
    }
}

// ============================================================
// fused transpose + LN(2048) -> xnT (tf32, k-permuted)
// ============================================================
__global__ void transpose_ln_kernel(const float* __restrict__ in,
                                    const float* __restrict__ g,
                                    const float* __restrict__ bb,
                                    float* __restrict__ outT) {
    __shared__ float tile[64][33];
    __shared__ float rs[256], rs2[256];
    int t = blockIdx.x, b = blockIdx.y;
    int tid = threadIdx.x;
    float s = 0.f, s2 = 0.f;
    for (int i = tid; i < 512; i += 256) {
        int fq = i >> 3, c4 = (i & 7)*4;
        float4 v = *(const float4*)(in + (((size_t)b*64 + fq)*1024 + t)*32 + c4);
        tile[fq][c4]   = v.x; tile[fq][c4+1] = v.y;
        tile[fq][c4+2] = v.z; tile[fq][c4+3] = v.w;
        s  += v.x + v.y + v.z + v.w;
        s2 += v.x*v.x + v.y*v.y + v.z*v.z + v.w*v.w;
    }
    rs[tid] = s; rs2[tid] = s2;
    __syncthreads();
    for (int o = 128; o > 0; o >>= 1) {
        if (tid < o) { rs[tid] += rs[tid+o]; rs2[tid] += rs2[tid+o]; }
        __syncthreads();
    }
    float mean = rs[0] * (1.f/2048.f);
    float var  = rs2[0] * (1.f/2048.f) - mean*mean;
    float inv  = rsqrtf(var + EPSV);

    size_t ob = ((size_t)t*16 + b)*2048;
    for (int i = tid; i < 2048; i += 256) {
        int c = i >> 6, ff = i & 63;
        float vv = (tile[ff][c] - mean)*inv*g[i] + bb[i];
        outT[ob + ksperm(i)] = __uint_as_float(f2tf(vv));
    }
}

// ============================================================
// LN(1024): fp32 (rx path) + tf32 k-permuted (GEMM A)
// ============================================================
__global__ void ln_kernel(const float* __restrict__ in,
                          const float* __restrict__ g,
                          const float* __restrict__ bb,
                          float* __restrict__ out,
                          float* __restrict__ outT) {
    const int W = 1024;
    int row = blockIdx.x;
    int tid = threadIdx.x;
    const float* x = in + (size_t)row * W;

    float4 v4 = *(const float4*)(x + tid*4);
    float s  = v4.x + v4.y + v4.z + v4.w;
    float s2 = v4.x*v4.x + v4.y*v4.y + v4.z*v4.z + v4.w*v4.w;

    __shared__ float rs[256], rs2[256];
    rs[tid] = s; rs2[tid] = s2;
    __syncthreads();
    for (int o = 128; o > 0; o >>= 1) {
        if (tid < o) { rs[tid] += rs[tid+o]; rs2[tid] += rs2[tid+o]; }
        __syncthreads();
    }
    float mean = rs[0] * (1.f/1024.f);
    float var  = rs2[0] * (1.f/1024.f) - mean * mean;
    float inv  = rsqrtf(var + EPSV);

    int i = tid*4;
    float4 gg = *(const float4*)(g + i);
    float4 bv = *(const float4*)(bb + i);
    float r0 = (v4.x - mean)*inv*gg.x + bv.x;
    float r1 = (v4.y - mean)*inv*gg.y + bv.y;
    float r2 = (v4.z - mean)*inv*gg.z + bv.z;
    float r3 = (v4.w - mean)*inv*gg.w + bv.w;
    *(float4*)(out + (size_t)row*W + i) = make_float4(r0, r1, r2, r3);
    float* oT = outT + (size_t)row*W;
    oT[ksperm(i  )] = __uint_as_float(f2tf(r0));
    oT[ksperm(i+1)] = __uint_as_float(f2tf(r1));
    oT[ksperm(i+2)] = __uint_as_float(f2tf(r2));
    oT[ksperm(i+3)] = __uint_as_float(f2tf(r3));
}

// ============================================================
// TF32 GEMM (R7 config: 2-stage, k-interleaved LDS.64)
// ============================================================
__device__ __forceinline__ void mma_tf32(float* c, const uint32_t* a, const uint32_t* b) {
    asm volatile(
        "mma.sync.aligned.m16n8k8.row.col.f32.tf32.tf32.f32 "
        "{%0,%1,%2,%3}, {%4,%5,%6,%7}, {%8,%9}, {%0,%1,%2,%3};\n"
        : "+f"(c[0]), "+f"(c[1]), "+f"(c[2]), "+f"(c[3])
        : "r"(a[0]), "r"(a[1]), "r"(a[2]), "r"(a[3]),
          "r"(b[0]), "r"(b[1]));
}

#define GA_WORDS (128*40)
#define GB_WORDS (128*40)
#define GBUF (GA_WORDS + GB_WORDS)   // 10240 words; 2 stages = 81920 B

__global__ __launch_bounds__(256)
void mma_gemm_kernel(const float* __restrict__ A,
                     const float* __restrict__ BT,
                     float* __restrict__ Cm,
                     int M, int N, int K, int round_out) {
    uint32_t* gsm = (uint32_t*)dynsmem;

    int tid  = threadIdx.x;
    int lane = tid & 31, warp = tid >> 5;
    int m0 = blockIdx.y * 128, n0 = blockIdx.x * 128;
    int wm = (warp >> 1) * 32;
    int wn = (warp & 1) * 64;
    int g  = lane >> 2, tg = lane & 3;

    float acc[2][8][4];
#pragma unroll
    for (int mt = 0; mt < 2; mt++)
#pragma unroll
        for (int nt = 0; nt < 8; nt++)
#pragma unroll
            for (int i = 0; i < 4; i++) acc[mt][nt][i] = 0.f;

#define GEMM_STAGE(k0_, buf_) do {                                            \
    uint32_t* as_ = gsm + (buf_)*GBUF;                                        \
    uint32_t* bs_ = as_ + GA_WORDS;                                           \
    _Pragma("unroll")                                                         \
    for (int l = 0; l < 4; l++) {                                             \
        int idx = tid + l*256;                                                \
        int r = idx >> 3, gq = idx & 7;                                       \
        cpa16(as_ + r*40 + gq*4, A + (size_t)(m0 + r)*K + (k0_) + gq*4);      \
    }                                                                         \
    _Pragma("unroll")                                                         \
    for (int l = 0; l < 4; l++) {                                             \
        int idx = tid + l*256;                                                \
        int c = idx >> 3, gq = idx & 7;                                       \
        cpa16(bs_ + c*40 + gq*4, BT + (size_t)(n0 + c)*K + (k0_) + gq*4);     \
    }                                                                         \
    asm volatile("cp.async.commit_group;\n");                                 \
} while (0)

    GEMM_STAGE(0, 0);

    int cur = 0;
    for (int k0 = 0; k0 < K; k0 += 32) {
        bool hn = (k0 + 32) < K;
        if (hn) {
            GEMM_STAGE(k0 + 32, cur ^ 1);
            asm volatile("cp.async.wait_group 1;\n");
        } else {
            asm volatile("cp.async.wait_group 0;\n");
        }
        __syncthreads();

        const uint32_t* asc = gsm + cur*GBUF;
        const uint32_t* bsc = asc + GA_WORDS;

#pragma unroll
        for (int kc = 0; kc < 4; kc++) {
            int kb = kc * 8;
            uint32_t af[2][4];
#pragma unroll
            for (int mt = 0; mt < 2; mt++) {
                int row = wm + mt*16 + g;
                uint2 aA = *(const uint2*)&asc[(row    )*40 + kb + 2*tg];
                uint2 aB = *(const uint2*)&asc[(row + 8)*40 + kb + 2*tg];
                af[mt][0] = aA.x; af[mt][2] = aA.y;
                af[mt][1] = aB.x; af[mt][3] = aB.y;
            }
            uint32_t bf[8][2];
#pragma unroll
            for (int nt = 0; nt < 8; nt++) {
                int col = wn + nt*8 + g;
                uint2 bb = *(const uint2*)&bsc[col*40 + kb + 2*tg];
                bf[nt][0] = bb.x; bf[nt][1] = bb.y;
            }
#pragma unroll
            for (int mt = 0; mt < 2; mt++)
#pragma unroll
                for (int nt = 0; nt < 8; nt++)
                    mma_tf32(acc[mt][nt], af[mt], bf[nt]);
        }
        __syncthreads();
        cur ^= 1;
    }
#undef GEMM_STAGE

#pragma unroll
    for (int mt = 0; mt < 2; mt++) {
        int row = m0 + wm + mt*16 + g;
#pragma unroll
        for (int nt = 0; nt < 8; nt++) {
            int base = n0 + wn + nt*8;
            float o0 = acc[mt][nt][0], o1 = acc[mt][nt][1];
            float o2 = acc[mt][nt][2], o3 = acc[mt][nt][3];
            if (round_out) {
                int p0 = ksperm(2*tg), p1 = ksperm(2*tg + 1);
                Cm[(size_t)row * N + base + p0]       = __uint_as_float(f2tf(o0));
                Cm[(size_t)row * N + base + p1]       = __uint_as_float(f2tf(o1));
                Cm[(size_t)(row + 8) * N + base + p0] = __uint_as_float(f2tf(o2));
                Cm[(size_t)(row + 8) * N + base + p1] = __uint_as_float(f2tf(o3));
            } else {
                int col = base + tg*2;
                *(float2*)&Cm[(size_t)row * N + col]       = make_float2(o0, o1);
                *(float2*)&Cm[(size_t)(row + 8) * N + col] = make_float2(o2, o3);
            }
        }
    }
}

// ============================================================
// SRU (R7 config): block per (d,b,jhalf) = 64 blocks x 256 thr
// ============================================================
__device__ __forceinline__ float sigmf(float x) {
    return __fdividef(1.f, 1.f + __expf(-x));
}

template <int KK>
__global__ __launch_bounds__(256)
void sru2_kernel(const float* __restrict__ U,
                 const float* __restrict__ xn,
                 const float* __restrict__ vc,
                 const float* __restrict__ bias,
                 float* __restrict__ out) {
    float* sm = (float*)dynsmem;
    float* ub = sm;                       // [2][8][KK*256]
    float* xb = sm + 2*8*KK*256;          // [2][8][256] (KK==3)

    const int tj = threadIdx.x;
    const int bx = blockIdx.x;
    const int d  = bx >> 5;
    const int b  = (bx >> 1) & 15;
    const int jh = bx & 1;
    const int j  = jh*256 + tj;
    const int RW = 2*KK*512;

    float vf = vc[d*1024 + j],   vr = vc[d*1024 + 512 + j];
    float bf = bias[d*1024 + j], br = bias[d*1024 + 512 + j];

#define SRU_LOAD_CHUNK(cc, buf) do {                                          \
    int s0 = (cc)*8;                                                          \
    for (int idx = tj; idx < 8*KK*64; idx += 256) {                           \
        int i = idx / (KK*64);                                                \
        int o = idx - i*(KK*64);                                              \
        int gi = o >> 6, gw = o & 63;                                         \
        int t = d ? (1023 - (s0+i)) : (s0+i);                                 \
        const float* src = U + ((size_t)t*16 + b)*RW + d*KK*512               \
                             + gi*512 + jh*256 + gw*4;                        \
        cpa16(ub + ((size_t)((buf)*8 + i)*KK + gi)*256 + gw*4, src);          \
    }                                                                         \
    if (KK == 3) {                                                            \
        for (int idx = tj; idx < 512; idx += 256) {                           \
            int i = idx >> 6, gw = idx & 63;                                  \
            int t = d ? (1023 - (s0+i)) : (s0+i);                             \
            const float* src = xn + ((size_t)t*16 + b)*1024 + d*512           \
                                  + jh*256 + gw*4;                            \
            cpa16(xb + ((buf)*8 + i)*256 + gw*4, src);                        \
        }                                                                     \
    }                                                                         \
    asm volatile("cp.async.commit_group;\n");                                 \
} while (0)

    SRU_LOAD_CHUNK(0, 0);

    float c = 0.f;
    for (int ch = 0; ch < 128; ch++) {
        int buf = ch & 1;
        if (ch < 127) {
            SRU_LOAD_CHUNK(ch + 1, buf ^ 1);
            asm volatile("cp.async.wait_group 1;\n");
        } else {
            asm volatile("cp.async.wait_group 0;\n");
        }
        __syncthreads();
#pragma unroll
        for (int i = 0; i < 8; i++) {
            int s = ch*8 + i;
            int t = d ? (1023 - s) : s;
            const float* us = ub + (size_t)(buf*8 + i)*KK*256;
            float a0 = us[tj], a1 = us[256 + tj], a2 = us[512 + tj];
            float rx = (KK == 4) ? us[768 + tj] : xb[(buf*8 + i)*256 + tj];
            float f = sigmf(fmaf(vf, c, a1) + bf);
            c = fmaf(f, c - a0, a0);
            float r = sigmf(fmaf(vr, c, a2) + br);
            out[((size_t)t*16 + b)*1024 + d*512 + j] = fmaf(r, c - rx, rx);
        }
        __syncthreads();
    }
#undef SRU_LOAD_CHUNK
}

// ============================================================
// final: per row LN(1024) + @cls_w(1024,30)
// ============================================================
__global__ void final_kernel(const float* __restrict__ s,
                             const float* __restrict__ g,
                             const float* __restrict__ bb,
                             const float* __restrict__ cw,
                             float* __restrict__ out) {
    int row = blockIdx.x;
    int t = row >> 4, b = row & 15;
    int tid = threadIdx.x;
    const float* x = s + (size_t)row * 1024;

    float4 v4 = *(const float4*)(x + tid*4);
    float sm = v4.x + v4.y + v4.z + v4.w;
    float s2 = v4.x*v4.x + v4.y*v4.y + v4.z*v4.z + v4.w*v4.w;

    __shared__ float rs[256], rs2[256];
    rs[tid] = sm; rs2[tid] = s2;
    __syncthreads();
    for (int o = 128; o > 0; o >>= 1) {
        if (tid < o) { rs[tid] += rs[tid+o]; rs2[tid] += rs2[tid+o]; }
        __syncthreads();
    }
    float mean = rs[0] * (1.f/1024.f);
    float var  = rs2[0] * (1.f/1024.f) - mean*mean;
    float inv  = rsqrtf(var + EPSV);

    float acc[30];
#pragma unroll
    for (int k = 0; k < 30; k++) acc[k] = 0.f;

    for (int dd = tid; dd < 1024; dd += 256) {
        float v = (x[dd] - mean)*inv*g[dd] + bb[dd];
        const float* cwr = cw + dd*30;
#pragma unroll
        for (int k = 0; k < 30; k++)
            acc[k] = fmaf(v, cwr[k], acc[k]);
    }

    __shared__ float sacc[30];
    if (tid < 30) sacc[tid] = 0.f;
    __syncthreads();
#pragma unroll
    for (int k = 0; k < 30; k++) {
        float v = acc[k];
#pragma unroll
        for (int o = 16; o > 0; o >>= 1)
            v += __shfl_down_sync(0xffffffffu, v, o);
        if ((tid & 31) == 0) atomicAdd(&sacc[k], v);
    }
    __syncthreads();
    if (tid < 30)
        out[((size_t)b*1024 + t)*30 + tid] = sacc[tid];
}

// ============================================================
// host orchestration
// ============================================================
extern "C" void kernel_launch(void* const* d_in, const int* in_sizes, int n_in,
                              void* d_out, int out_size) {
    const float* x       = (const float*)d_in[0];
    const float* conv0_w = (const float*)d_in[1];
    const float* conv0_b = (const float*)d_in[2];
    const float* rc1w = (const float*)d_in[3];
    const float* rc1b = (const float*)d_in[4];
    const float* rb1g = (const float*)d_in[5];
    const float* rb1b = (const float*)d_in[6];
    const float* rb1m = (const float*)d_in[7];
    const float* rb1v = (const float*)d_in[8];
    const float* rc2w = (const float*)d_in[9];
    const float* rc2b = (const float*)d_in[10];
    const float* rb2g = (const float*)d_in[11];
    const float* rb2b = (const float*)d_in[12];
    const float* rb2m = (const float*)d_in[13];
    const float* rb2v = (const float*)d_in[14];
    const float* ln0g = (const float*)d_in[15];
    const float* ln0b = (const float*)d_in[16];
    const float* wproj0 = (const float*)d_in[17];
    const float* w0   = (const float*)d_in[18];
    const float* vc0  = (const float*)d_in[19];
    const float* bias0= (const float*)d_in[20];
    const float* lng  = (const float*)d_in[21];
    const float* lnb  = (const float*)d_in[22];
    const float* wproj= (const float*)d_in[23];
    const float* w    = (const float*)d_in[24];
    const float* vc   = (const float*)d_in[25];
    const float* bias = (const float*)d_in[26];
    const float* clng = (const float*)d_in[27];
    const float* clnb = (const float*)d_in[28];
    const float* clsw = (const float*)d_in[29];

    float *bufA, *bufB, *xn, *xnT, *tmp, *U, *sa, *sb, *bias2, *wpT, *wwT;
    uint32_t *w1, *w2, *h1A, *h2A, *h1B, *h2B;
    cudaGetSymbolAddress((void**)&bufA,  g_bufA);
    cudaGetSymbolAddress((void**)&bufB,  g_bufB);
    cudaGetSymbolAddress((void**)&xn,    g_xn);
    cudaGetSymbolAddress((void**)&xnT,   g_xnT);
    cudaGetSymbolAddress((void**)&tmp,   g_tmp);
    cudaGetSymbolAddress((void**)&U,     g_U);
    cudaGetSymbolAddress((void**)&sa,    g_sa);
    cudaGetSymbolAddress((void**)&sb,    g_sb);
    cudaGetSymbolAddress((void**)&w1,    g_w1);
    cudaGetSymbolAddress((void**)&w2,    g_w2);
    cudaGetSymbolAddress((void**)&bias2, g_bias2);
    cudaGetSymbolAddress((void**)&h1A,   g_h1A);
    cudaGetSymbolAddress((void**)&h2A,   g_h2A);
    cudaGetSymbolAddress((void**)&h1B,   g_h1B);
    cudaGetSymbolAddress((void**)&h2B,   g_h2B);
    cudaGetSymbolAddress((void**)&wpT,   g_wpT);
    cudaGetSymbolAddress((void**)&wwT,   g_wwT);

    cudaFuncSetAttribute(resconv_mma_kernel,
                         cudaFuncAttributeMaxDynamicSharedMemorySize, RC_WORDS*4);
    cudaFuncSetAttribute(mma_gemm_kernel,
                         cudaFuncAttributeMaxDynamicSharedMemorySize, 2*GBUF*4);
    cudaFuncSetAttribute(sru2_kernel<4>,
                         cudaFuncAttributeMaxDynamicSharedMemorySize, 65536);
    cudaFuncSetAttribute(sru2_kernel<3>,
                         cudaFuncAttributeMaxDynamicSharedMemorySize, 65536);

    // ---- weight prep: 2 launches ----
    trT_all_kernel<<<4608, dim3(32, 8)>>>(wproj0, w0, wproj, w, wpT, wwT);
    prep_conv_all_kernel<<<dim3(5, 6), 1024>>>(rc1w, rc1b, rb1g, rb1b, rb1m, rb1v,
                                               rc2w, rc2b, rb2g, rb2b, rb2m, rb2v,
                                               w1, w2, bias2);

    // ---- conv front-end ----
    conv0_kernel<<<dim3(4, 64, 16), 256>>>(x, conv0_w, conv0_b, bufA, h1A, h2A);

    dim3 rcgrid(8, 32, 16);   // 2 f-rows per block
    for (int i = 0; i < 3; i++) {
        resconv_mma_kernel<<<rcgrid, 512, RC_WORDS*4>>>(h1A, h2A,
            w1 + (2*i)*4864, w2 + (2*i)*4864, bias2 + (2*i)*32,
            nullptr, bufB, h1B, h2B);
        resconv_mma_kernel<<<rcgrid, 512, RC_WORDS*4>>>(h1B, h2B,
            w1 + (2*i+1)*4864, w2 + (2*i+1)*4864, bias2 + (2*i+1)*32,
            bufA, bufA, h1A, h2A);
    }

    // ---- transpose+LN(2048) ----
    transpose_ln_kernel<<<dim3(1024, 16), 256>>>(bufA, ln0g, ln0b, xnT);

    // ---- SRU layer 0 (k=4) ----
    mma_gemm_kernel<<<dim3(2, 128), 256, 2*GBUF*4>>>(xnT, wpT, tmp, NROWS, 256, 2048, 1);
    mma_gemm_kernel<<<dim3(32, 128), 256, 2*GBUF*4>>>(tmp, wwT, U, NROWS, 4096, 256, 0);
    sru2_kernel<4><<<64, 256, 65536>>>(U, xn, vc0, bias0, sa);

    // ---- SRU layers 1-3 (k=3) ----
    float* cur = sa;
    float* nxt = sb;
    for (int i = 0; i < 3; i++) {
        ln_kernel<<<NROWS, 256>>>(cur, lng + i*1024, lnb + i*1024, xn, xnT);
        mma_gemm_kernel<<<dim3(2, 128), 256, 2*GBUF*4>>>(xnT, wpT + 524288 + i*262144,
                                                         tmp, NROWS, 256, 1024, 1);
        mma_gemm_kernel<<<dim3(24, 128), 256, 2*GBUF*4>>>(tmp, wwT + 1048576 + i*786432,
                                                          U, NROWS, 3072, 256, 0);
        sru2_kernel<3><<<64, 256, 65536>>>(U, xn, vc + i*2048, bias + i*2048, nxt);
        float* t2 = cur; cur = nxt; nxt = t2;
    }

    // ---- final LN + classifier ----
    final_kernel<<<NROWS, 256>>>(cur, clng, clnb, clsw, (float*)d_out);
}

// round 11
// speedup vs baseline: 1.0087x; 1.0087x over previous
#include <cuda_runtime.h>
#include <cuda_fp16.h>
#include <math.h>
#include <stdint.h>

#define EPSV 1e-5f

// ---- dims ----
#define BB   16
#define CC   32
#define FF   64
#define TT   1024
#define LL   1024
#define HH   512
#define PP   256
#define FEAT2 2048
#define DD   1024
#define NROWS (LL*BB)   // 16384

extern __shared__ char dynsmem[];

// ---- scratch ----
__device__ float g_bufA[BB*CC*FF*TT];
__device__ float g_bufB[BB*CC*FF*TT];
__device__ float g_xn[NROWS*FEAT2];
__device__ float g_xnT[NROWS*FEAT2];       // k-permuted tf32 LN out
__device__ float g_tmp[NROWS*PP];          // k-permuted tf32 GEMM1 out
__device__ float g_U[NROWS*4096];
__device__ float g_sa[NROWS*DD];
__device__ float g_sb[NROWS*DD];
__device__ uint32_t g_w1[6*32*152];        // conv fp16 hi weights [layer][co][kk'] pad152
__device__ uint32_t g_w2[6*32*152];
__device__ float g_bias2[6*32];
__device__ uint32_t g_h1A[BB*FF*TT*16];    // packed fp16-hi, word order ksperm'ed
__device__ uint32_t g_h2A[BB*FF*TT*16];
__device__ uint32_t g_h1B[BB*FF*TT*16];
__device__ uint32_t g_h2B[BB*FF*TT*16];
__device__ float g_wpT[2048*256 + 3*1024*256];
__device__ float g_wwT[4096*256 + 3*3072*256];

__device__ __forceinline__ void cpa16(void* smem, const void* gmem) {
    uint32_t s = (uint32_t)__cvta_generic_to_shared(smem);
    asm volatile("cp.async.cg.shared.global [%0], [%1], 16;\n" :: "r"(s), "l"(gmem));
}
__device__ __forceinline__ void cpa16z(void* smem, const void* gmem, bool ok) {
    uint32_t s = (uint32_t)__cvta_generic_to_shared(smem);
    int sz = ok ? 16 : 0;
    asm volatile("cp.async.cg.shared.global [%0], [%1], 16, %2;\n" :: "r"(s), "l"(gmem), "r"(sz));
}
__device__ __forceinline__ uint32_t f2tf(float x) {
    uint32_t u;
    asm("cvt.rna.tf32.f32 %0, %1;" : "=r"(u) : "f"(x));
    return u;
}
// stored position of logical k within its 8-block: order 0,4,1,5,2,6,3,7
__device__ __forceinline__ int ksperm(int k) {
    return (k & ~7) | (((k & 3) << 1) | ((k >> 2) & 1));
}
__device__ __forceinline__ uint32_t packhi(float a, float b) {
    __half2 h = __halves2half2(__float2half_rn(a), __float2half_rn(b));
    return *(uint32_t*)&h;
}
__device__ __forceinline__ uint32_t packlo(float a, float b) {
    __half ha = __float2half_rn(a), hb = __float2half_rn(b);
    __half2 l = __halves2half2(__float2half_rn(a - __half2float(ha)),
                               __float2half_rn(b - __half2float(hb)));
    return *(uint32_t*)&l;
}

// ============================================================
// ALL weight transposes in one launch (GEMM weights)
// ============================================================
__global__ void trT_all_kernel(const float* __restrict__ wproj0,
                               const float* __restrict__ w0,
                               const float* __restrict__ wproj,
                               const float* __restrict__ w,
                               float* __restrict__ wpT,
                               float* __restrict__ wwT) {
    int bid = blockIdx.x;
    const float* W; float* WT; int K, N, nx, base;
    if (bid < 512)        { W = wproj0; WT = wpT;  K = 2048; N = 256;  nx = 8;   base = 0; }
    else if (bid < 1536)  { W = w0;     WT = wwT;  K = 256;  N = 4096; nx = 128; base = 512; }
    else if (bid < 2304)  {
        int i = (bid - 1536) >> 8;
        W = wproj + (size_t)i*262144; WT = wpT + 524288 + i*262144;
        K = 1024; N = 256; nx = 8; base = 1536 + i*256;
    } else {
        int i = (bid - 2304) / 768;
        W = w + (size_t)i*786432; WT = wwT + 1048576 + i*786432;
        K = 256; N = 3072; nx = 96; base = 2304 + i*768;
    }
    int r = bid - base;
    int n0 = (r % nx) * 32, k0 = (r / nx) * 32;

    __shared__ float tile[32][33];
    int tx = threadIdx.x, ty = threadIdx.y;  // (32,8)
#pragma unroll
    for (int i = 0; i < 4; i++)
        tile[ty + 8*i][tx] = W[(size_t)(k0 + ty + 8*i)*N + n0 + tx];
    __syncthreads();
    int kst = k0 + ksperm(tx);
#pragma unroll
    for (int i = 0; i < 4; i++) {
        int n = n0 + ty + 8*i;
        WT[(size_t)n*K + kst] = __uint_as_float(f2tf(tile[tx][ty + 8*i]));
    }
}

// ============================================================
// conv0 -> NHWC fp32 + packed fp16 hi/lo (word order permuted)
// ============================================================
__global__ void conv0_kernel(const float* __restrict__ x,
                             const float* __restrict__ w,
                             const float* __restrict__ cb,
                             float* __restrict__ out,
                             uint32_t* __restrict__ oh1,
                             uint32_t* __restrict__ oh2) {
    __shared__ float ws[288];
    __shared__ float bs[32];
    int tid = threadIdx.x;
    for (int i = tid; i < 288; i += 256) {
        int co = i / 9, j = i % 9;
        ws[j*32 + co] = w[i];
    }
    if (tid < 32) bs[tid] = cb[tid];
    __syncthreads();

    int to = blockIdx.x * 256 + tid;
    int fo = blockIdx.y;
    int b  = blockIdx.z;

    float acc[32];
#pragma unroll
    for (int q = 0; q < 32; q++) acc[q] = bs[q];

#pragma unroll
    for (int df = 0; df < 3; df++) {
        int xi = 2*fo + df - 1;
        if (xi < 0 || xi >= 128) continue;
#pragma unroll
        for (int dt = 0; dt < 3; dt++) {
            int ti = 2*to + dt - 1;
            if (ti < 0 || ti >= 2048) continue;
            float v = x[((size_t)b*128 + xi)*2048 + ti];
            int j = df*3 + dt;
#pragma unroll
            for (int q = 0; q < 8; q++) {
                float4 w4 = *(const float4*)&ws[j*32 + q*4];
                acc[q*4+0] = fmaf(v, w4.x, acc[q*4+0]);
                acc[q*4+1] = fmaf(v, w4.y, acc[q*4+1]);
                acc[q*4+2] = fmaf(v, w4.z, acc[q*4+2]);
                acc[q*4+3] = fmaf(v, w4.w, acc[q*4+3]);
            }
        }
    }
    size_t pos = ((size_t)b*64 + fo)*1024 + to;
#pragma unroll
    for (int q = 0; q < 8; q++)
        *(float4*)&out[pos*32 + q*4] = make_float4(acc[q*4], acc[q*4+1], acc[q*4+2], acc[q*4+3]);

    uint32_t hw_[16], lw_[16];
#pragma unroll
    for (int p = 0; p < 16; p++) {
        int ps = ksperm(p);
        hw_[ps] = packhi(acc[2*p], acc[2*p+1]);
        lw_[ps] = packlo(acc[2*p], acc[2*p+1]);
    }
#pragma unroll
    for (int q = 0; q < 4; q++) {
        *(uint4*)&oh1[pos*16 + q*4] = *(uint4*)&hw_[q*4];
        *(uint4*)&oh2[pos*16 + q*4] = *(uint4*)&lw_[q*4];
    }
}

// ============================================================
// prep ALL 6 conv layers: [co][kk'] layout, stride 152
// ============================================================
__global__ void prep_conv_all_kernel(const float* __restrict__ rc1w,
                                     const float* __restrict__ rc1b,
                                     const float* __restrict__ rb1g,
                                     const float* __restrict__ rb1b,
                                     const float* __restrict__ rb1m,
                                     const float* __restrict__ rb1v,
                                     const float* __restrict__ rc2w,
                                     const float* __restrict__ rc2b,
                                     const float* __restrict__ rb2g,
                                     const float* __restrict__ rb2b,
                                     const float* __restrict__ rb2m,
                                     const float* __restrict__ rb2v,
                                     uint32_t* __restrict__ w1,
                                     uint32_t* __restrict__ w2,
                                     float* __restrict__ bias2) {
    int layer = blockIdx.y;
    int bi = layer >> 1, sec = layer & 1;
    const float* w   = (sec ? rc2w : rc1w) + bi*9216;
    const float* cb  = (sec ? rc2b : rc1b) + bi*32;
    const float* g   = (sec ? rb2g : rb1g) + bi*32;
    const float* bt  = (sec ? rb2b : rb1b) + bi*32;
    const float* m   = (sec ? rb2m : rb1m) + bi*32;
    const float* v   = (sec ? rb2v : rb1v) + bi*32;
    uint32_t* o1 = w1 + layer*4864;
    uint32_t* o2 = w2 + layer*4864;
    float* ob = bias2 + layer*32;

    int i = blockIdx.x * blockDim.x + threadIdx.x;
    if (i < 4608) {
        int co  = i & 31;
        int kk  = i >> 5;              // logical kk = j*16 + ci2
        int j   = kk >> 4;
        int ci2 = kk & 15;
        float scale = g[co] * rsqrtf(v[co] + EPSV);
        float f0 = w[co*288 + (2*ci2    )*9 + j] * scale;
        float f1 = w[co*288 + (2*ci2 + 1)*9 + j] * scale;
        int kks = ksperm(kk);
        o1[co*152 + kks] = packhi(f0, f1);
        o2[co*152 + kks] = packlo(f0, f1);
    }
    if (i < 32) {
        float scale = g[i] * rsqrtf(v[i] + EPSV);
        ob[i] = bt[i] + (cb[i] - m[i]) * scale;
    }
}

// ============================================================
// residual conv v4: 256 thr (8 warps), warp tile 32x32
// B fragments reused across 2 M-tiles -> 5.3 B smem/mma
// ============================================================
__device__ __forceinline__ void mma_f16(float* c, const uint32_t* a, const uint32_t* b) {
    asm volatile(
        "mma.sync.aligned.m16n8k16.row.col.f32.f16.f16.f32 "
        "{%0,%1,%2,%3}, {%4,%5,%6,%7}, {%8,%9}, {%0,%1,%2,%3};\n"
        : "+f"(c[0]), "+f"(c[1]), "+f"(c[2]), "+f"(c[3])
        : "r"(a[0]), "r"(a[1]), "r"(a[2]), "r"(a[3]),
          "r"(b[0]), "r"(b[1]));
}

#define RC_SLAB  3120          // 130*24 words per slab
#define RC_A1 0                // [4][130][24] = 12480
#define RC_A2 12480
#define RC_W1 24960            // [32][152] = 4864
#define RC_W2 29824
#define RC_WORDS 34688         // *4 = 138752 bytes

__global__ __launch_bounds__(256)
void resconv_mma_kernel(const uint32_t* __restrict__ ih1,
                        const uint32_t* __restrict__ ih2,
                        const uint32_t* __restrict__ w1g,
                        const uint32_t* __restrict__ w2g,
                        const float* __restrict__ bias2,
                        const float* __restrict__ res,
                        float* __restrict__ out,
                        uint32_t* __restrict__ oh1,
                        uint32_t* __restrict__ oh2) {
    uint32_t* sm = (uint32_t*)dynsmem;
    uint32_t* A1 = sm + RC_A1;
    uint32_t* A2 = sm + RC_A2;
    uint32_t* W1 = sm + RC_W1;
    uint32_t* W2 = sm + RC_W2;
    __shared__ float bs[32];

    int tid = threadIdx.x;
    int t0 = blockIdx.x * 128;
    int f0 = blockIdx.y * 2;
    int b  = blockIdx.z;

    if (tid < 32) bs[tid] = bias2[tid];

    // weights: 1216 granules each
    for (int i = tid; i < 1216; i += 256) {
        cpa16(W1 + i*4, w1g + i*4);
        cpa16(W2 + i*4, w2g + i*4);
    }
    // 4 halo slabs; 520 granules per slab
    for (int idx = tid; idx < 2080; idx += 256) {
        int s   = idx / 520;
        int rem = idx - s*520;
        int r = rem >> 2, gq = rem & 3;
        int xi = f0 - 1 + s;
        int t  = t0 - 1 + r;
        bool ok = (xi >= 0) && (xi < 64) && (t >= 0) && (t < 1024);
        size_t off = ok ? ((((size_t)b*64 + xi)*1024 + t)*16 + gq*4) : 0;
        int dst = s*RC_SLAB + r*24 + gq*4;
        cpa16z(A1 + dst, ih1 + off, ok);
        cpa16z(A2 + dst, ih2 + off, ok);
    }
    asm volatile("cp.async.commit_group;\n");
    asm volatile("cp.async.wait_group 0;\n");
    __syncthreads();

    int lane = tid & 31, wid = tid >> 5;
    int fi = wid >> 2;              // plane 0/1 (warps 0-3 / 4-7)
    int w4 = wid & 3;
    int f  = f0 + fi;
    int g = lane >> 2, tg = lane & 3;
    int rowA = w4 * 32;             // warp covers 32 t-rows

    float acc[2][4][4];
#pragma unroll
    for (int mt = 0; mt < 2; mt++)
#pragma unroll
        for (int nt = 0; nt < 4; nt++)
#pragma unroll
            for (int i = 0; i < 4; i++) acc[mt][nt][i] = 0.f;

#pragma unroll
    for (int j = 0; j < 9; j++) {
        const int df = j / 3, dt = j % 3;
        const uint32_t* a1s = A1 + (fi + df)*RC_SLAB + (rowA + dt)*24;
        const uint32_t* a2s = A2 + (fi + df)*RC_SLAB + (rowA + dt)*24;
        const int wcol = j*16;
#pragma unroll
        for (int h = 0; h < 2; h++) {
            int kb = h*8 + 2*tg;
            // B fragments once, reused across both M-tiles
            uint32_t b1f[4][2], b2f[4][2];
#pragma unroll
            for (int nt = 0; nt < 4; nt++) {
                int co = nt*8 + g;
                uint2 b1 = *(const uint2*)&W1[co*152 + wcol + kb];
                uint2 b2 = *(const uint2*)&W2[co*152 + wcol + kb];
                b1f[nt][0] = b1.x; b1f[nt][1] = b1.y;
                b2f[nt][0] = b2.x; b2f[nt][1] = b2.y;
            }
#pragma unroll
            for (int mt = 0; mt < 2; mt++) {
                int rb = mt*16;
                uint32_t a1f[4], a2f[4];
                uint2 lo1 = *(const uint2*)&a1s[(rb + g    )*24 + kb];
                uint2 hi1 = *(const uint2*)&a1s[(rb + g + 8)*24 + kb];
                a1f[0] = lo1.x; a1f[2] = lo1.y;
                a1f[1] = hi1.x; a1f[3] = hi1.y;
                uint2 lo2 = *(const uint2*)&a2s[(rb + g    )*24 + kb];
                uint2 hi2 = *(const uint2*)&a2s[(rb + g + 8)*24 + kb];
                a2f[0] = lo2.x; a2f[2] = lo2.y;
                a2f[1] = hi2.x; a2f[3] = hi2.y;
#pragma unroll
                for (int nt = 0; nt < 4; nt++) {
                    mma_f16(acc[mt][nt], a1f, b1f[nt]);
                    mma_f16(acc[mt][nt], a2f, b1f[nt]);
                    mma_f16(acc[mt][nt], a1f, b2f[nt]);
                }
            }
        }
    }

    bool hasres = (res != nullptr);
    bool hash   = (oh1 != nullptr);
    __syncthreads();   // done reading slabs; reuse A1/A2 for packing

    float vv[2][4][4];
#pragma unroll
    for (int mt = 0; mt < 2; mt++) {
#pragma unroll
        for (int nt = 0; nt < 4; nt++) {
            int co = nt*8 + tg*2;
#pragma unroll
            for (int half = 0; half < 2; half++) {
                int t = t0 + rowA + mt*16 + g + half*8;
                size_t addr = (((size_t)b*64 + f)*1024 + t)*32 + co;
                float v0 = acc[mt][nt][half*2 + 0] + bs[co];
                float v1 = acc[mt][nt][half*2 + 1] + bs[co + 1];
                if (hasres) {
                    float2 rv = *(const float2*)(res + addr);
                    v0 += rv.x; v1 += rv.y;
                }
                v0 = fmaxf(v0, 0.f); v1 = fmaxf(v1, 0.f);
                *(float2*)(out + addr) = make_float2(v0, v1);
                vv[mt][nt][half*2]   = v0;
                vv[mt][nt][half*2+1] = v1;
            }
        }
    }

    if (hash) {
#pragma unroll
        for (int mt = 0; mt < 2; mt++) {
#pragma unroll
            for (int nt = 0; nt < 4; nt++) {
                int wd = ksperm(nt*4 + tg);
#pragma unroll
                for (int half = 0; half < 2; half++) {
                    int tl = rowA + mt*16 + g + half*8;
                    A1[fi*RC_SLAB + tl*24 + wd] = packhi(vv[mt][nt][half*2], vv[mt][nt][half*2+1]);
                    A2[fi*RC_SLAB + tl*24 + wd] = packlo(vv[mt][nt][half*2], vv[mt][nt][half*2+1]);
                }
            }
        }
        __syncthreads();
#pragma unroll
        for (int l = 0; l < 4; l++) {
            int idx = tid + l*256;          // 0..1023
            int pf  = idx >> 9;
            int rr  = (idx >> 2) & 127;
            int q   = idx & 3;
            size_t posb = ((size_t)b*64 + f0 + pf)*1024 + t0;
            *(uint4*)&oh1[(posb + rr)*16 + q*4] = *(uint4*)&A1[pf*RC_SLAB + rr*24 + q*4];
            *(uint4*)&oh2[(posb + rr)*16 + q*4] = *(uint4*)&A2[pf*RC_SLAB + rr*24 + q*4];
        }
    }
}

// ============================================================
// fused transpose + LN(2048) -> xnT (tf32, k-permuted)
// ============================================================
__global__ void transpose_ln_kernel(const float* __restrict__ in,
                                    const float* __restrict__ g,
                                    const float* __restrict__ bb,
                                    float* __restrict__ outT) {
    __shared__ float tile[64][33];
    __shared__ float rs[256], rs2[256];
    int t = blockIdx.x, b = blockIdx.y;
    int tid = threadIdx.x;
    float s = 0.f, s2 = 0.f;
    for (int i = tid; i < 512; i += 256) {
        int fq = i >> 3, c4 = (i & 7)*4;
        float4 v = *(const float4*)(in + (((size_t)b*64 + fq)*1024 + t)*32 + c4);
        tile[fq][c4]   = v.x; tile[fq][c4+1] = v.y;
        tile[fq][c4+2] = v.z; tile[fq][c4+3] = v.w;
        s  += v.x + v.y + v.z + v.w;
        s2 += v.x*v.x + v.y*v.y + v.z*v.z + v.w*v.w;
    }
    rs[tid] = s; rs2[tid] = s2;
    __syncthreads();
    for (int o = 128; o > 0; o >>= 1) {
        if (tid < o) { rs[tid] += rs[tid+o]; rs2[tid] += rs2[tid+o]; }
        __syncthreads();
    }
    float mean = rs[0] * (1.f/2048.f);
    float var  = rs2[0] * (1.f/2048.f) - mean*mean;
    float inv  = rsqrtf(var + EPSV);

    size_t ob = ((size_t)t*16 + b)*2048;
    for (int i = tid; i < 2048; i += 256) {
        int c = i >> 6, ff = i & 63;
        float vv = (tile[ff][c] - mean)*inv*g[i] + bb[i];
        outT[ob + ksperm(i)] = __uint_as_float(f2tf(vv));
    }
}

// ============================================================
// LN(1024): fp32 (rx path) + tf32 k-permuted (GEMM A)
// ============================================================
__global__ void ln_kernel(const float* __restrict__ in,
                          const float* __restrict__ g,
                          const float* __restrict__ bb,
                          float* __restrict__ out,
                          float* __restrict__ outT) {
    const int W = 1024;
    int row = blockIdx.x;
    int tid = threadIdx.x;
    const float* x = in + (size_t)row * W;

    float4 v4 = *(const float4*)(x + tid*4);
    float s  = v4.x + v4.y + v4.z + v4.w;
    float s2 = v4.x*v4.x + v4.y*v4.y + v4.z*v4.z + v4.w*v4.w;

    __shared__ float rs[256], rs2[256];
    rs[tid] = s; rs2[tid] = s2;
    __syncthreads();
    for (int o = 128; o > 0; o >>= 1) {
        if (tid < o) { rs[tid] += rs[tid+o]; rs2[tid] += rs2[tid+o]; }
        __syncthreads();
    }
    float mean = rs[0] * (1.f/1024.f);
    float var  = rs2[0] * (1.f/1024.f) - mean * mean;
    float inv  = rsqrtf(var + EPSV);

    int i = tid*4;
    float4 gg = *(const float4*)(g + i);
    float4 bv = *(const float4*)(bb + i);
    float r0 = (v4.x - mean)*inv*gg.x + bv.x;
    float r1 = (v4.y - mean)*inv*gg.y + bv.y;
    float r2 = (v4.z - mean)*inv*gg.z + bv.z;
    float r3 = (v4.w - mean)*inv*gg.w + bv.w;
    *(float4*)(out + (size_t)row*W + i) = make_float4(r0, r1, r2, r3);
    float* oT = outT + (size_t)row*W;
    oT[ksperm(i  )] = __uint_as_float(f2tf(r0));
    oT[ksperm(i+1)] = __uint_as_float(f2tf(r1));
    oT[ksperm(i+2)] = __uint_as_float(f2tf(r2));
    oT[ksperm(i+3)] = __uint_as_float(f2tf(r3));
}

// ============================================================
// TF32 GEMM (R7 config: 2-stage, k-interleaved LDS.64)
// ============================================================
__device__ __forceinline__ void mma_tf32(float* c, const uint32_t* a, const uint32_t* b) {
    asm volatile(
        "mma.sync.aligned.m16n8k8.row.col.f32.tf32.tf32.f32 "
        "{%0,%1,%2,%3}, {%4,%5,%6,%7}, {%8,%9}, {%0,%1,%2,%3};\n"
        : "+f"(c[0]), "+f"(c[1]), "+f"(c[2]), "+f"(c[3])
        : "r"(a[0]), "r"(a[1]), "r"(a[2]), "r"(a[3]),
          "r"(b[0]), "r"(b[1]));
}

#define GA_WORDS (128*40)
#define GB_WORDS (128*40)
#define GBUF (GA_WORDS + GB_WORDS)   // 10240 words; 2 stages = 81920 B

__global__ __launch_bounds__(256)
void mma_gemm_kernel(const float* __restrict__ A,
                     const float* __restrict__ BT,
                     float* __restrict__ Cm,
                     int M, int N, int K, int round_out) {
    uint32_t* gsm = (uint32_t*)dynsmem;

    int tid  = threadIdx.x;
    int lane = tid & 31, warp = tid >> 5;
    int m0 = blockIdx.y * 128, n0 = blockIdx.x * 128;
    int wm = (warp >> 1) * 32;
    int wn = (warp & 1) * 64;
    int g  = lane >> 2, tg = lane & 3;

    float acc[2][8][4];
#pragma unroll
    for (int mt = 0; mt < 2; mt++)
#pragma unroll
        for (int nt = 0; nt < 8; nt++)
#pragma unroll
            for (int i = 0; i < 4; i++) acc[mt][nt][i] = 0.f;

#define GEMM_STAGE(k0_, buf_) do {                                            \
    uint32_t* as_ = gsm + (buf_)*GBUF;                                        \
    uint32_t* bs_ = as_ + GA_WORDS;                                           \
    _Pragma("unroll")                                                         \
    for (int l = 0; l < 4; l++) {                                             \
        int idx = tid + l*256;                                                \
        int r = idx >> 3, gq = idx & 7;                                       \
        cpa16(as_ + r*40 + gq*4, A + (size_t)(m0 + r)*K + (k0_) + gq*4);      \
    }                                                                         \
    _Pragma("unroll")                                                         \
    for (int l = 0; l < 4; l++) {                                             \
        int idx = tid + l*256;                                                \
        int c = idx >> 3, gq = idx & 7;                                       \
        cpa16(bs_ + c*40 + gq*4, BT + (size_t)(n0 + c)*K + (k0_) + gq*4);     \
    }                                                                         \
    asm volatile("cp.async.commit_group;\n");                                 \
} while (0)

    GEMM_STAGE(0, 0);

    int cur = 0;
    for (int k0 = 0; k0 < K; k0 += 32) {
        bool hn = (k0 + 32) < K;
        if (hn) {
            GEMM_STAGE(k0 + 32, cur ^ 1);
            asm volatile("cp.async.wait_group 1;\n");
        } else {
            asm volatile("cp.async.wait_group 0;\n");
        }
        __syncthreads();

        const uint32_t* asc = gsm + cur*GBUF;
        const uint32_t* bsc = asc + GA_WORDS;

#pragma unroll
        for (int kc = 0; kc < 4; kc++) {
            int kb = kc * 8;
            uint32_t af[2][4];
#pragma unroll
            for (int mt = 0; mt < 2; mt++) {
                int row = wm + mt*16 + g;
                uint2 aA = *(const uint2*)&asc[(row    )*40 + kb + 2*tg];
                uint2 aB = *(const uint2*)&asc[(row + 8)*40 + kb + 2*tg];
                af[mt][0] = aA.x; af[mt][2] = aA.y;
                af[mt][1] = aB.x; af[mt][3] = aB.y;
            }
            uint32_t bf[8][2];
#pragma unroll
            for (int nt = 0; nt < 8; nt++) {
                int col = wn + nt*8 + g;
                uint2 bb = *(const uint2*)&bsc[col*40 + kb + 2*tg];
                bf[nt][0] = bb.x; bf[nt][1] = bb.y;
            }
#pragma unroll
            for (int mt = 0; mt < 2; mt++)
#pragma unroll
                for (int nt = 0; nt < 8; nt++)
                    mma_tf32(acc[mt][nt], af[mt], bf[nt]);
        }
        __syncthreads();
        cur ^= 1;
    }
#undef GEMM_STAGE

#pragma unroll
    for (int mt = 0; mt < 2; mt++) {
        int row = m0 + wm + mt*16 + g;
#pragma unroll
        for (int nt = 0; nt < 8; nt++) {
            int base = n0 + wn + nt*8;
            float o0 = acc[mt][nt][0], o1 = acc[mt][nt][1];
            float o2 = acc[mt][nt][2], o3 = acc[mt][nt][3];
            if (round_out) {
                int p0 = ksperm(2*tg), p1 = ksperm(2*tg + 1);
                Cm[(size_t)row * N + base + p0]       = __uint_as_float(f2tf(o0));
                Cm[(size_t)row * N + base + p1]       = __uint_as_float(f2tf(o1));
                Cm[(size_t)(row + 8) * N + base + p0] = __uint_as_float(f2tf(o2));
                Cm[(size_t)(row + 8) * N + base + p1] = __uint_as_float(f2tf(o3));
            } else {
                int col = base + tg*2;
                *(float2*)&Cm[(size_t)row * N + col]       = make_float2(o0, o1);
                *(float2*)&Cm[(size_t)(row + 8) * N + col] = make_float2(o2, o3);
            }
        }
    }
}

// ============================================================
// SRU (R7 config): block per (d,b,jhalf) = 64 blocks x 256 thr
// ============================================================
__device__ __forceinline__ float sigmf(float x) {
    return __fdividef(1.f, 1.f + __expf(-x));
}

template <int KK>
__global__ __launch_bounds__(256)
void sru2_kernel(const float* __restrict__ U,
                 const float* __restrict__ xn,
                 const float* __restrict__ vc,
                 const float* __restrict__ bias,
                 float* __restrict__ out) {
    float* sm = (float*)dynsmem;
    float* ub = sm;                       // [2][8][KK*256]
    float* xb = sm + 2*8*KK*256;          // [2][8][256] (KK==3)

    const int tj = threadIdx.x;
    const int bx = blockIdx.x;
    const int d  = bx >> 5;
    const int b  = (bx >> 1) & 15;
    const int jh = bx & 1;
    const int j  = jh*256 + tj;
    const int RW = 2*KK*512;

    float vf = vc[d*1024 + j],   vr = vc[d*1024 + 512 + j];
    float bf = bias[d*1024 + j], br = bias[d*1024 + 512 + j];

#define SRU_LOAD_CHUNK(cc, buf) do {                                          \
    int s0 = (cc)*8;                                                          \
    for (int idx = tj; idx < 8*KK*64; idx += 256) {                           \
        int i = idx / (KK*64);                                                \
        int o = idx - i*(KK*64);                                              \
        int gi = o >> 6, gw = o & 63;                                         \
        int t = d ? (1023 - (s0+i)) : (s0+i);                                 \
        const float* src = U + ((size_t)t*16 + b)*RW + d*KK*512               \
                             + gi*512 + jh*256 + gw*4;                        \
        cpa16(ub + ((size_t)((buf)*8 + i)*KK + gi)*256 + gw*4, src);          \
    }                                                                         \
    if (KK == 3) {                                                            \
        for (int idx = tj; idx < 512; idx += 256) {                           \
            int i = idx >> 6, gw = idx & 63;                                  \
            int t = d ? (1023 - (s0+i)) : (s0+i);                             \
            const float* src = xn + ((size_t)t*16 + b)*1024 + d*512           \
                                  + jh*256 + gw*4;                            \
            cpa16(xb + ((buf)*8 + i)*256 + gw*4, src);                        \
        }                                                                     \
    }                                                                         \
    asm volatile("cp.async.commit_group;\n");                                 \
} while (0)

    SRU_LOAD_CHUNK(0, 0);

    float c = 0.f;
    for (int ch = 0; ch < 128; ch++) {
        int buf = ch & 1;
        if (ch < 127) {
            SRU_LOAD_CHUNK(ch + 1, buf ^ 1);
            asm volatile("cp.async.wait_group 1;\n");
        } else {
            asm volatile("cp.async.wait_group 0;\n");
        }
        __syncthreads();
#pragma unroll
        for (int i = 0; i < 8; i++) {
            int s = ch*8 + i;
            int t = d ? (1023 - s) : s;
            const float* us = ub + (size_t)(buf*8 + i)*KK*256;
            float a0 = us[tj], a1 = us[256 + tj], a2 = us[512 + tj];
            float rx = (KK == 4) ? us[768 + tj] : xb[(buf*8 + i)*256 + tj];
            float f = sigmf(fmaf(vf, c, a1) + bf);
            c = fmaf(f, c - a0, a0);
            float r = sigmf(fmaf(vr, c, a2) + br);
            out[((size_t)t*16 + b)*1024 + d*512 + j] = fmaf(r, c - rx, rx);
        }
        __syncthreads();
    }
#undef SRU_LOAD_CHUNK
}

// ============================================================
// final: per row LN(1024) + @cls_w(1024,30)
// ============================================================
__global__ void final_kernel(const float* __restrict__ s,
                             const float* __restrict__ g,
                             const float* __restrict__ bb,
                             const float* __restrict__ cw,
                             float* __restrict__ out) {
    int row = blockIdx.x;
    int t = row >> 4, b = row & 15;
    int tid = threadIdx.x;
    const float* x = s + (size_t)row * 1024;

    float4 v4 = *(const float4*)(x + tid*4);
    float sm = v4.x + v4.y + v4.z + v4.w;
    float s2 = v4.x*v4.x + v4.y*v4.y + v4.z*v4.z + v4.w*v4.w;

    __shared__ float rs[256], rs2[256];
    rs[tid] = sm; rs2[tid] = s2;
    __syncthreads();
    for (int o = 128; o > 0; o >>= 1) {
        if (tid < o) { rs[tid] += rs[tid+o]; rs2[tid] += rs2[tid+o]; }
        __syncthreads();
    }
    float mean = rs[0] * (1.f/1024.f);
    float var  = rs2[0] * (1.f/1024.f) - mean*mean;
    float inv  = rsqrtf(var + EPSV);

    float acc[30];
#pragma unroll
    for (int k = 0; k < 30; k++) acc[k] = 0.f;

    for (int dd = tid; dd < 1024; dd += 256) {
        float v = (x[dd] - mean)*inv*g[dd] + bb[dd];
        const float* cwr = cw + dd*30;
#pragma unroll
        for (int k = 0; k < 30; k++)
            acc[k] = fmaf(v, cwr[k], acc[k]);
    }

    __shared__ float sacc[30];
    if (tid < 30) sacc[tid] = 0.f;
    __syncthreads();
#pragma unroll
    for (int k = 0; k < 30; k++) {
        float v = acc[k];
#pragma unroll
        for (int o = 16; o > 0; o >>= 1)
            v += __shfl_down_sync(0xffffffffu, v, o);
        if ((tid & 31) == 0) atomicAdd(&sacc[k], v);
    }
    __syncthreads();
    if (tid < 30)
        out[((size_t)b*1024 + t)*30 + tid] = sacc[tid];
}

// ============================================================
// host orchestration
// ============================================================
extern "C" void kernel_launch(void* const* d_in, const int* in_sizes, int n_in,
                              void* d_out, int out_size) {
    const float* x       = (const float*)d_in[0];
    const float* conv0_w = (const float*)d_in[1];
    const float* conv0_b = (const float*)d_in[2];
    const float* rc1w = (const float*)d_in[3];
    const float* rc1b = (const float*)d_in[4];
    const float* rb1g = (const float*)d_in[5];
    const float* rb1b = (const float*)d_in[6];
    const float* rb1m = (const float*)d_in[7];
    const float* rb1v = (const float*)d_in[8];
    const float* rc2w = (const float*)d_in[9];
    const float* rc2b = (const float*)d_in[10];
    const float* rb2g = (const float*)d_in[11];
    const float* rb2b = (const float*)d_in[12];
    const float* rb2m = (const float*)d_in[13];
    const float* rb2v = (const float*)d_in[14];
    const float* ln0g = (const float*)d_in[15];
    const float* ln0b = (const float*)d_in[16];
    const float* wproj0 = (const float*)d_in[17];
    const float* w0   = (const float*)d_in[18];
    const float* vc0  = (const float*)d_in[19];
    const float* bias0= (const float*)d_in[20];
    const float* lng  = (const float*)d_in[21];
    const float* lnb  = (const float*)d_in[22];
    const float* wproj= (const float*)d_in[23];
    const float* w    = (const float*)d_in[24];
    const float* vc   = (const float*)d_in[25];
    const float* bias = (const float*)d_in[26];
    const float* clng = (const float*)d_in[27];
    const float* clnb = (const float*)d_in[28];
    const float* clsw = (const float*)d_in[29];

    float *bufA, *bufB, *xn, *xnT, *tmp, *U, *sa, *sb, *bias2, *wpT, *wwT;
    uint32_t *w1, *w2, *h1A, *h2A, *h1B, *h2B;
    cudaGetSymbolAddress((void**)&bufA,  g_bufA);
    cudaGetSymbolAddress((void**)&bufB,  g_bufB);
    cudaGetSymbolAddress((void**)&xn,    g_xn);
    cudaGetSymbolAddress((void**)&xnT,   g_xnT);
    cudaGetSymbolAddress((void**)&tmp,   g_tmp);
    cudaGetSymbolAddress((void**)&U,     g_U);
    cudaGetSymbolAddress((void**)&sa,    g_sa);
    cudaGetSymbolAddress((void**)&sb,    g_sb);
    cudaGetSymbolAddress((void**)&w1,    g_w1);
    cudaGetSymbolAddress((void**)&w2,    g_w2);
    cudaGetSymbolAddress((void**)&bias2, g_bias2);
    cudaGetSymbolAddress((void**)&h1A,   g_h1A);
    cudaGetSymbolAddress((void**)&h2A,   g_h2A);
    cudaGetSymbolAddress((void**)&h1B,   g_h1B);
    cudaGetSymbolAddress((void**)&h2B,   g_h2B);
    cudaGetSymbolAddress((void**)&wpT,   g_wpT);
    cudaGetSymbolAddress((void**)&wwT,   g_wwT);

    cudaFuncSetAttribute(resconv_mma_kernel,
                         cudaFuncAttributeMaxDynamicSharedMemorySize, RC_WORDS*4);
    cudaFuncSetAttribute(mma_gemm_kernel,
                         cudaFuncAttributeMaxDynamicSharedMemorySize, 2*GBUF*4);
    cudaFuncSetAttribute(sru2_kernel<4>,
                         cudaFuncAttributeMaxDynamicSharedMemorySize, 65536);
    cudaFuncSetAttribute(sru2_kernel<3>,
                         cudaFuncAttributeMaxDynamicSharedMemorySize, 65536);

    // ---- weight prep: 2 launches ----
    trT_all_kernel<<<4608, dim3(32, 8)>>>(wproj0, w0, wproj, w, wpT, wwT);
    prep_conv_all_kernel<<<dim3(5, 6), 1024>>>(rc1w, rc1b, rb1g, rb1b, rb1m, rb1v,
                                               rc2w, rc2b, rb2g, rb2b, rb2m, rb2v,
                                               w1, w2, bias2);

    // ---- conv front-end ----
    conv0_kernel<<<dim3(4, 64, 16), 256>>>(x, conv0_w, conv0_b, bufA, h1A, h2A);

    dim3 rcgrid(8, 32, 16);   // 2 f-rows per block, 256 thr
    for (int i = 0; i < 3; i++) {
        resconv_mma_kernel<<<rcgrid, 256, RC_WORDS*4>>>(h1A, h2A,
            w1 + (2*i)*4864, w2 + (2*i)*4864, bias2 + (2*i)*32,
            nullptr, bufB, h1B, h2B);
        resconv_mma_kernel<<<rcgrid, 256, RC_WORDS*4>>>(h1B, h2B,
            w1 + (2*i+1)*4864, w2 + (2*i+1)*4864, bias2 + (2*i+1)*32,
            bufA, bufA, h1A, h2A);
    }

    // ---- transpose+LN(2048) ----
    transpose_ln_kernel<<<dim3(1024, 16), 256>>>(bufA, ln0g, ln0b, xnT);

    // ---- SRU layer 0 (k=4) ----
    mma_gemm_kernel<<<dim3(2, 128), 256, 2*GBUF*4>>>(xnT, wpT, tmp, NROWS, 256, 2048, 1);
    mma_gemm_kernel<<<dim3(32, 128), 256, 2*GBUF*4>>>(tmp, wwT, U, NROWS, 4096, 256, 0);
    sru2_kernel<4><<<64, 256, 65536>>>(U, xn, vc0, bias0, sa);

    // ---- SRU layers 1-3 (k=3) ----
    float* cur = sa;
    float* nxt = sb;
    for (int i = 0; i < 3; i++) {
        ln_kernel<<<NROWS, 256>>>(cur, lng + i*1024, lnb + i*1024, xn, xnT);
        mma_gemm_kernel<<<dim3(2, 128), 256, 2*GBUF*4>>>(xnT, wpT + 524288 + i*262144,
                                                         tmp, NROWS, 256, 1024, 1);
        mma_gemm_kernel<<<dim3(24, 128), 256, 2*GBUF*4>>>(tmp, wwT + 1048576 + i*786432,
                                                          U, NROWS, 3072, 256, 0);
        sru2_kernel<3><<<64, 256, 65536>>>(U, xn, vc + i*2048, bias + i*2048, nxt);
        float* t2 = cur; cur = nxt; nxt = t2;
    }

    // ---- final LN + classifier ----
    final_kernel<<<NROWS, 256>>>(cur, clng, clnb, clsw, (float*)d_out);
}

// round 12
// speedup vs baseline: 1.0105x; 1.0019x over previous
#include <cuda_runtime.h>
#include <cuda_fp16.h>
#include <math.h>
#include <stdint.h>

#define EPSV 1e-5f

// ---- dims ----
#define BB   16
#define CC   32
#define FF   64
#define TT   1024
#define LL   1024
#define HH   512
#define PP   256
#define FEAT2 2048
#define DD   1024
#define NROWS (LL*BB)   // 16384

extern __shared__ char dynsmem[];

// ---- scratch ----
__device__ float g_bufA[BB*CC*FF*TT];
__device__ float g_bufB[BB*CC*FF*TT];
__device__ float g_xn[NROWS*FEAT2];
__device__ float g_xnT[NROWS*FEAT2];       // k-permuted tf32 LN out
__device__ float g_tmp[NROWS*PP];          // k-permuted tf32 GEMM1 out
__device__ float g_U[NROWS*4096];
__device__ float g_sa[NROWS*DD];
__device__ float g_sb[NROWS*DD];
__device__ uint32_t g_w1[6*32*152];        // conv fp16 hi weights [layer][co][kk'] pad152
__device__ uint32_t g_w2[6*32*152];
__device__ float g_bias2[6*32];
__device__ uint32_t g_h1A[BB*FF*TT*16];    // packed fp16-hi, word order ksperm'ed
__device__ uint32_t g_h2A[BB*FF*TT*16];
__device__ uint32_t g_h1B[BB*FF*TT*16];
__device__ uint32_t g_h2B[BB*FF*TT*16];
__device__ float g_wpT[2048*256 + 3*1024*256];
__device__ float g_wwT[4096*256 + 3*3072*256];

__device__ __forceinline__ void cpa16(void* smem, const void* gmem) {
    uint32_t s = (uint32_t)__cvta_generic_to_shared(smem);
    asm volatile("cp.async.cg.shared.global [%0], [%1], 16;\n" :: "r"(s), "l"(gmem));
}
__device__ __forceinline__ void cpa16z(void* smem, const void* gmem, bool ok) {
    uint32_t s = (uint32_t)__cvta_generic_to_shared(smem);
    int sz = ok ? 16 : 0;
    asm volatile("cp.async.cg.shared.global [%0], [%1], 16, %2;\n" :: "r"(s), "l"(gmem), "r"(sz));
}
__device__ __forceinline__ uint32_t f2tf(float x) {
    uint32_t u;
    asm("cvt.rna.tf32.f32 %0, %1;" : "=r"(u) : "f"(x));
    return u;
}
// stored position of logical k within its 8-block: order 0,4,1,5,2,6,3,7
__device__ __forceinline__ int ksperm(int k) {
    return (k & ~7) | (((k & 3) << 1) | ((k >> 2) & 1));
}
__device__ __forceinline__ uint32_t packhi(float a, float b) {
    __half2 h = __halves2half2(__float2half_rn(a), __float2half_rn(b));
    return *(uint32_t*)&h;
}
__device__ __forceinline__ uint32_t packlo(float a, float b) {
    __half ha = __float2half_rn(a), hb = __float2half_rn(b);
    __half2 l = __halves2half2(__float2half_rn(a - __half2float(ha)),
                               __float2half_rn(b - __half2float(hb)));
    return *(uint32_t*)&l;
}

// ============================================================
// ALL weight transposes in one launch (GEMM weights)
// ============================================================
__global__ void trT_all_kernel(const float* __restrict__ wproj0,
                               const float* __restrict__ w0,
                               const float* __restrict__ wproj,
                               const float* __restrict__ w,
                               float* __restrict__ wpT,
                               float* __restrict__ wwT) {
    int bid = blockIdx.x;
    const float* W; float* WT; int K, N, nx, base;
    if (bid < 512)        { W = wproj0; WT = wpT;  K = 2048; N = 256;  nx = 8;   base = 0; }
    else if (bid < 1536)  { W = w0;     WT = wwT;  K = 256;  N = 4096; nx = 128; base = 512; }
    else if (bid < 2304)  {
        int i = (bid - 1536) >> 8;
        W = wproj + (size_t)i*262144; WT = wpT + 524288 + i*262144;
        K = 1024; N = 256; nx = 8; base = 1536 + i*256;
    } else {
        int i = (bid - 2304) / 768;
        W = w + (size_t)i*786432; WT = wwT + 1048576 + i*786432;
        K = 256; N = 3072; nx = 96; base = 2304 + i*768;
    }
    int r = bid - base;
    int n0 = (r % nx) * 32, k0 = (r / nx) * 32;

    __shared__ float tile[32][33];
    int tx = threadIdx.x, ty = threadIdx.y;  // (32,8)
#pragma unroll
    for (int i = 0; i < 4; i++)
        tile[ty + 8*i][tx] = W[(size_t)(k0 + ty + 8*i)*N + n0 + tx];
    __syncthreads();
    int kst = k0 + ksperm(tx);
#pragma unroll
    for (int i = 0; i < 4; i++) {
        int n = n0 + ty + 8*i;
        WT[(size_t)n*K + kst] = __uint_as_float(f2tf(tile[tx][ty + 8*i]));
    }
}

// ============================================================
// conv0 -> NHWC fp32 + packed fp16 hi/lo (word order permuted)
// ============================================================
__global__ void conv0_kernel(const float* __restrict__ x,
                             const float* __restrict__ w,
                             const float* __restrict__ cb,
                             float* __restrict__ out,
                             uint32_t* __restrict__ oh1,
                             uint32_t* __restrict__ oh2) {
    __shared__ float ws[288];
    __shared__ float bs[32];
    int tid = threadIdx.x;
    for (int i = tid; i < 288; i += 256) {
        int co = i / 9, j = i % 9;
        ws[j*32 + co] = w[i];
    }
    if (tid < 32) bs[tid] = cb[tid];
    __syncthreads();

    int to = blockIdx.x * 256 + tid;
    int fo = blockIdx.y;
    int b  = blockIdx.z;

    float acc[32];
#pragma unroll
    for (int q = 0; q < 32; q++) acc[q] = bs[q];

#pragma unroll
    for (int df = 0; df < 3; df++) {
        int xi = 2*fo + df - 1;
        if (xi < 0 || xi >= 128) continue;
#pragma unroll
        for (int dt = 0; dt < 3; dt++) {
            int ti = 2*to + dt - 1;
            if (ti < 0 || ti >= 2048) continue;
            float v = x[((size_t)b*128 + xi)*2048 + ti];
            int j = df*3 + dt;
#pragma unroll
            for (int q = 0; q < 8; q++) {
                float4 w4 = *(const float4*)&ws[j*32 + q*4];
                acc[q*4+0] = fmaf(v, w4.x, acc[q*4+0]);
                acc[q*4+1] = fmaf(v, w4.y, acc[q*4+1]);
                acc[q*4+2] = fmaf(v, w4.z, acc[q*4+2]);
                acc[q*4+3] = fmaf(v, w4.w, acc[q*4+3]);
            }
        }
    }
    size_t pos = ((size_t)b*64 + fo)*1024 + to;
#pragma unroll
    for (int q = 0; q < 8; q++)
        *(float4*)&out[pos*32 + q*4] = make_float4(acc[q*4], acc[q*4+1], acc[q*4+2], acc[q*4+3]);

    uint32_t hw_[16], lw_[16];
#pragma unroll
    for (int p = 0; p < 16; p++) {
        int ps = ksperm(p);
        hw_[ps] = packhi(acc[2*p], acc[2*p+1]);
        lw_[ps] = packlo(acc[2*p], acc[2*p+1]);
    }
#pragma unroll
    for (int q = 0; q < 4; q++) {
        *(uint4*)&oh1[pos*16 + q*4] = *(uint4*)&hw_[q*4];
        *(uint4*)&oh2[pos*16 + q*4] = *(uint4*)&lw_[q*4];
    }
}

// ============================================================
// prep ALL 6 conv layers: [co][kk'] layout, stride 152
// ============================================================
__global__ void prep_conv_all_kernel(const float* __restrict__ rc1w,
                                     const float* __restrict__ rc1b,
                                     const float* __restrict__ rb1g,
                                     const float* __restrict__ rb1b,
                                     const float* __restrict__ rb1m,
                                     const float* __restrict__ rb1v,
                                     const float* __restrict__ rc2w,
                                     const float* __restrict__ rc2b,
                                     const float* __restrict__ rb2g,
                                     const float* __restrict__ rb2b,
                                     const float* __restrict__ rb2m,
                                     const float* __restrict__ rb2v,
                                     uint32_t* __restrict__ w1,
                                     uint32_t* __restrict__ w2,
                                     float* __restrict__ bias2) {
    int layer = blockIdx.y;
    int bi = layer >> 1, sec = layer & 1;
    const float* w   = (sec ? rc2w : rc1w) + bi*9216;
    const float* cb  = (sec ? rc2b : rc1b) + bi*32;
    const float* g   = (sec ? rb2g : rb1g) + bi*32;
    const float* bt  = (sec ? rb2b : rb1b) + bi*32;
    const float* m   = (sec ? rb2m : rb1m) + bi*32;
    const float* v   = (sec ? rb2v : rb1v) + bi*32;
    uint32_t* o1 = w1 + layer*4864;
    uint32_t* o2 = w2 + layer*4864;
    float* ob = bias2 + layer*32;

    int i = blockIdx.x * blockDim.x + threadIdx.x;
    if (i < 4608) {
        int co  = i & 31;
        int kk  = i >> 5;              // logical kk = j*16 + ci2
        int j   = kk >> 4;
        int ci2 = kk & 15;
        float scale = g[co] * rsqrtf(v[co] + EPSV);
        float f0 = w[co*288 + (2*ci2    )*9 + j] * scale;
        float f1 = w[co*288 + (2*ci2 + 1)*9 + j] * scale;
        int kks = ksperm(kk);
        o1[co*152 + kks] = packhi(f0, f1);
        o2[co*152 + kks] = packlo(f0, f1);
    }
    if (i < 32) {
        float scale = g[i] * rsqrtf(v[i] + EPSV);
        ob[i] = bt[i] + (cb[i] - m[i]) * scale;
    }
}

// ============================================================
// residual conv v4: 256 thr (8 warps), warp tile 32x32
// B fragments reused across 2 M-tiles -> 5.3 B smem/mma
// ============================================================
__device__ __forceinline__ void mma_f16(float* c, const uint32_t* a, const uint32_t* b) {
    asm volatile(
        "mma.sync.aligned.m16n8k16.row.col.f32.f16.f16.f32 "
        "{%0,%1,%2,%3}, {%4,%5,%6,%7}, {%8,%9}, {%0,%1,%2,%3};\n"
        : "+f"(c[0]), "+f"(c[1]), "+f"(c[2]), "+f"(c[3])
        : "r"(a[0]), "r"(a[1]), "r"(a[2]), "r"(a[3]),
          "r"(b[0]), "r"(b[1]));
}

#define RC_SLAB  3120          // 130*24 words per slab
#define RC_A1 0                // [4][130][24] = 12480
#define RC_A2 12480
#define RC_W1 24960            // [32][152] = 4864
#define RC_W2 29824
#define RC_WORDS 34688         // *4 = 138752 bytes

__global__ __launch_bounds__(256)
void resconv_mma_kernel(const uint32_t* __restrict__ ih1,
                        const uint32_t* __restrict__ ih2,
                        const uint32_t* __restrict__ w1g,
                        const uint32_t* __restrict__ w2g,
                        const float* __restrict__ bias2,
                        const float* __restrict__ res,
                        float* __restrict__ out,
                        uint32_t* __restrict__ oh1,
                        uint32_t* __restrict__ oh2) {
    uint32_t* sm = (uint32_t*)dynsmem;
    uint32_t* A1 = sm + RC_A1;
    uint32_t* A2 = sm + RC_A2;
    uint32_t* W1 = sm + RC_W1;
    uint32_t* W2 = sm + RC_W2;
    __shared__ float bs[32];

    int tid = threadIdx.x;
    int t0 = blockIdx.x * 128;
    int f0 = blockIdx.y * 2;
    int b  = blockIdx.z;

    if (tid < 32) bs[tid] = bias2[tid];

    // weights: 1216 granules each
    for (int i = tid; i < 1216; i += 256) {
        cpa16(W1 + i*4, w1g + i*4);
        cpa16(W2 + i*4, w2g + i*4);
    }
    // 4 halo slabs; 520 granules per slab
    for (int idx = tid; idx < 2080; idx += 256) {
        int s   = idx / 520;
        int rem = idx - s*520;
        int r = rem >> 2, gq = rem & 3;
        int xi = f0 - 1 + s;
        int t  = t0 - 1 + r;
        bool ok = (xi >= 0) && (xi < 64) && (t >= 0) && (t < 1024);
        size_t off = ok ? ((((size_t)b*64 + xi)*1024 + t)*16 + gq*4) : 0;
        int dst = s*RC_SLAB + r*24 + gq*4;
        cpa16z(A1 + dst, ih1 + off, ok);
        cpa16z(A2 + dst, ih2 + off, ok);
    }
    asm volatile("cp.async.commit_group;\n");
    asm volatile("cp.async.wait_group 0;\n");
    __syncthreads();

    int lane = tid & 31, wid = tid >> 5;
    int fi = wid >> 2;              // plane 0/1 (warps 0-3 / 4-7)
    int w4 = wid & 3;
    int f  = f0 + fi;
    int g = lane >> 2, tg = lane & 3;
    int rowA = w4 * 32;             // warp covers 32 t-rows

    float acc[2][4][4];
#pragma unroll
    for (int mt = 0; mt < 2; mt++)
#pragma unroll
        for (int nt = 0; nt < 4; nt++)
#pragma unroll
            for (int i = 0; i < 4; i++) acc[mt][nt][i] = 0.f;

#pragma unroll
    for (int j = 0; j < 9; j++) {
        const int df = j / 3, dt = j % 3;
        const uint32_t* a1s = A1 + (fi + df)*RC_SLAB + (rowA + dt)*24;
        const uint32_t* a2s = A2 + (fi + df)*RC_SLAB + (rowA + dt)*24;
        const int wcol = j*16;
#pragma unroll
        for (int h = 0; h < 2; h++) {
            int kb = h*8 + 2*tg;
            // B fragments once, reused across both M-tiles
            uint32_t b1f[4][2], b2f[4][2];
#pragma unroll
            for (int nt = 0; nt < 4; nt++) {
                int co = nt*8 + g;
                uint2 b1 = *(const uint2*)&W1[co*152 + wcol + kb];
                uint2 b2 = *(const uint2*)&W2[co*152 + wcol + kb];
                b1f[nt][0] = b1.x; b1f[nt][1] = b1.y;
                b2f[nt][0] = b2.x; b2f[nt][1] = b2.y;
            }
#pragma unroll
            for (int mt = 0; mt < 2; mt++) {
                int rb = mt*16;
                uint32_t a1f[4], a2f[4];
                uint2 lo1 = *(const uint2*)&a1s[(rb + g    )*24 + kb];
                uint2 hi1 = *(const uint2*)&a1s[(rb + g + 8)*24 + kb];
                a1f[0] = lo1.x; a1f[2] = lo1.y;
                a1f[1] = hi1.x; a1f[3] = hi1.y;
                uint2 lo2 = *(const uint2*)&a2s[(rb + g    )*24 + kb];
                uint2 hi2 = *(const uint2*)&a2s[(rb + g + 8)*24 + kb];
                a2f[0] = lo2.x; a2f[2] = lo2.y;
                a2f[1] = hi2.x; a2f[3] = hi2.y;
#pragma unroll
                for (int nt = 0; nt < 4; nt++) {
                    mma_f16(acc[mt][nt], a1f, b1f[nt]);
                    mma_f16(acc[mt][nt], a2f, b1f[nt]);
                    mma_f16(acc[mt][nt], a1f, b2f[nt]);
                }
            }
        }
    }

    bool hasres = (res != nullptr);
    bool hash   = (oh1 != nullptr);
    __syncthreads();   // done reading slabs; reuse A1/A2 for packing

    float vv[2][4][4];
#pragma unroll
    for (int mt = 0; mt < 2; mt++) {
#pragma unroll
        for (int nt = 0; nt < 4; nt++) {
            int co = nt*8 + tg*2;
#pragma unroll
            for (int half = 0; half < 2; half++) {
                int t = t0 + rowA + mt*16 + g + half*8;
                size_t addr = (((size_t)b*64 + f)*1024 + t)*32 + co;
                float v0 = acc[mt][nt][half*2 + 0] + bs[co];
                float v1 = acc[mt][nt][half*2 + 1] + bs[co + 1];
                if (hasres) {
                    float2 rv = *(const float2*)(res + addr);
                    v0 += rv.x; v1 += rv.y;
                }
                v0 = fmaxf(v0, 0.f); v1 = fmaxf(v1, 0.f);
                *(float2*)(out + addr) = make_float2(v0, v1);
                vv[mt][nt][half*2]   = v0;
                vv[mt][nt][half*2+1] = v1;
            }
        }
    }

    if (hash) {
#pragma unroll
        for (int mt = 0; mt < 2; mt++) {
#pragma unroll
            for (int nt = 0; nt < 4; nt++) {
                int wd = ksperm(nt*4 + tg);
#pragma unroll
                for (int half = 0; half < 2; half++) {
                    int tl = rowA + mt*16 + g + half*8;
                    A1[fi*RC_SLAB + tl*24 + wd] = packhi(vv[mt][nt][half*2], vv[mt][nt][half*2+1]);
                    A2[fi*RC_SLAB + tl*24 + wd] = packlo(vv[mt][nt][half*2], vv[mt][nt][half*2+1]);
                }
            }
        }
        __syncthreads();
#pragma unroll
        for (int l = 0; l < 4; l++) {
            int idx = tid + l*256;          // 0..1023
            int pf  = idx >> 9;
            int rr  = (idx >> 2) & 127;
            int q   = idx & 3;
            size_t posb = ((size_t)b*64 + f0 + pf)*1024 + t0;
            *(uint4*)&oh1[(posb + rr)*16 + q*4] = *(uint4*)&A1[pf*RC_SLAB + rr*24 + q*4];
            *(uint4*)&oh2[(posb + rr)*16 + q*4] = *(uint4*)&A2[pf*RC_SLAB + rr*24 + q*4];
        }
    }
}

// ============================================================
// fused transpose + LN(2048) -> xnT (tf32, k-permuted)
// ============================================================
__global__ void transpose_ln_kernel(const float* __restrict__ in,
                                    const float* __restrict__ g,
                                    const float* __restrict__ bb,
                                    float* __restrict__ outT) {
    __shared__ float tile[64][33];
    __shared__ float rs[256], rs2[256];
    int t = blockIdx.x, b = blockIdx.y;
    int tid = threadIdx.x;
    float s = 0.f, s2 = 0.f;
    for (int i = tid; i < 512; i += 256) {
        int fq = i >> 3, c4 = (i & 7)*4;
        float4 v = *(const float4*)(in + (((size_t)b*64 + fq)*1024 + t)*32 + c4);
        tile[fq][c4]   = v.x; tile[fq][c4+1] = v.y;
        tile[fq][c4+2] = v.z; tile[fq][c4+3] = v.w;
        s  += v.x + v.y + v.z + v.w;
        s2 += v.x*v.x + v.y*v.y + v.z*v.z + v.w*v.w;
    }
    rs[tid] = s; rs2[tid] = s2;
    __syncthreads();
    for (int o = 128; o > 0; o >>= 1) {
        if (tid < o) { rs[tid] += rs[tid+o]; rs2[tid] += rs2[tid+o]; }
        __syncthreads();
    }
    float mean = rs[0] * (1.f/2048.f);
    float var  = rs2[0] * (1.f/2048.f) - mean*mean;
    float inv  = rsqrtf(var + EPSV);

    size_t ob = ((size_t)t*16 + b)*2048;
    for (int i = tid; i < 2048; i += 256) {
        int c = i >> 6, ff = i & 63;
        float vv = (tile[ff][c] - mean)*inv*g[i] + bb[i];
        outT[ob + ksperm(i)] = __uint_as_float(f2tf(vv));
    }
}

// ============================================================
// LN(1024): fp32 (rx path) + tf32 k-permuted (GEMM A)
// ============================================================
__global__ void ln_kernel(const float* __restrict__ in,
                          const float* __restrict__ g,
                          const float* __restrict__ bb,
                          float* __restrict__ out,
                          float* __restrict__ outT) {
    const int W = 1024;
    int row = blockIdx.x;
    int tid = threadIdx.x;
    const float* x = in + (size_t)row * W;

    float4 v4 = *(const float4*)(x + tid*4);
    float s  = v4.x + v4.y + v4.z + v4.w;
    float s2 = v4.x*v4.x + v4.y*v4.y + v4.z*v4.z + v4.w*v4.w;

    __shared__ float rs[256], rs2[256];
    rs[tid] = s; rs2[tid] = s2;
    __syncthreads();
    for (int o = 128; o > 0; o >>= 1) {
        if (tid < o) { rs[tid] += rs[tid+o]; rs2[tid] += rs2[tid+o]; }
        __syncthreads();
    }
    float mean = rs[0] * (1.f/1024.f);
    float var  = rs2[0] * (1.f/1024.f) - mean * mean;
    float inv  = rsqrtf(var + EPSV);

    int i = tid*4;
    float4 gg = *(const float4*)(g + i);
    float4 bv = *(const float4*)(bb + i);
    float r0 = (v4.x - mean)*inv*gg.x + bv.x;
    float r1 = (v4.y - mean)*inv*gg.y + bv.y;
    float r2 = (v4.z - mean)*inv*gg.z + bv.z;
    float r3 = (v4.w - mean)*inv*gg.w + bv.w;
    *(float4*)(out + (size_t)row*W + i) = make_float4(r0, r1, r2, r3);
    float* oT = outT + (size_t)row*W;
    oT[ksperm(i  )] = __uint_as_float(f2tf(r0));
    oT[ksperm(i+1)] = __uint_as_float(f2tf(r1));
    oT[ksperm(i+2)] = __uint_as_float(f2tf(r2));
    oT[ksperm(i+3)] = __uint_as_float(f2tf(r3));
}

// ============================================================
// TF32 GEMM (R7 config: 2-stage, k-interleaved LDS.64)
// ============================================================
__device__ __forceinline__ void mma_tf32(float* c, const uint32_t* a, const uint32_t* b) {
    asm volatile(
        "mma.sync.aligned.m16n8k8.row.col.f32.tf32.tf32.f32 "
        "{%0,%1,%2,%3}, {%4,%5,%6,%7}, {%8,%9}, {%0,%1,%2,%3};\n"
        : "+f"(c[0]), "+f"(c[1]), "+f"(c[2]), "+f"(c[3])
        : "r"(a[0]), "r"(a[1]), "r"(a[2]), "r"(a[3]),
          "r"(b[0]), "r"(b[1]));
}

#define GA_WORDS (128*40)
#define GB_WORDS (128*40)
#define GBUF (GA_WORDS + GB_WORDS)   // 10240 words; 2 stages = 81920 B

__global__ __launch_bounds__(256)
void mma_gemm_kernel(const float* __restrict__ A,
                     const float* __restrict__ BT,
                     float* __restrict__ Cm,
                     int M, int N, int K, int round_out) {
    uint32_t* gsm = (uint32_t*)dynsmem;

    int tid  = threadIdx.x;
    int lane = tid & 31, warp = tid >> 5;
    int m0 = blockIdx.y * 128, n0 = blockIdx.x * 128;
    int wm = (warp >> 1) * 32;
    int wn = (warp & 1) * 64;
    int g  = lane >> 2, tg = lane & 3;

    float acc[2][8][4];
#pragma unroll
    for (int mt = 0; mt < 2; mt++)
#pragma unroll
        for (int nt = 0; nt < 8; nt++)
#pragma unroll
            for (int i = 0; i < 4; i++) acc[mt][nt][i] = 0.f;

#define GEMM_STAGE(k0_, buf_) do {                                            \
    uint32_t* as_ = gsm + (buf_)*GBUF;                                        \
    uint32_t* bs_ = as_ + GA_WORDS;                                           \
    _Pragma("unroll")                                                         \
    for (int l = 0; l < 4; l++) {                                             \
        int idx = tid + l*256;                                                \
        int r = idx >> 3, gq = idx & 7;                                       \
        cpa16(as_ + r*40 + gq*4, A + (size_t)(m0 + r)*K + (k0_) + gq*4);      \
    }                                                                         \
    _Pragma("unroll")                                                         \
    for (int l = 0; l < 4; l++) {                                             \
        int idx = tid + l*256;                                                \
        int c = idx >> 3, gq = idx & 7;                                       \
        cpa16(bs_ + c*40 + gq*4, BT + (size_t)(n0 + c)*K + (k0_) + gq*4);     \
    }                                                                         \
    asm volatile("cp.async.commit_group;\n");                                 \
} while (0)

    GEMM_STAGE(0, 0);

    int cur = 0;
    for (int k0 = 0; k0 < K; k0 += 32) {
        bool hn = (k0 + 32) < K;
        if (hn) {
            GEMM_STAGE(k0 + 32, cur ^ 1);
            asm volatile("cp.async.wait_group 1;\n");
        } else {
            asm volatile("cp.async.wait_group 0;\n");
        }
        __syncthreads();

        const uint32_t* asc = gsm + cur*GBUF;
        const uint32_t* bsc = asc + GA_WORDS;

#pragma unroll
        for (int kc = 0; kc < 4; kc++) {
            int kb = kc * 8;
            uint32_t af[2][4];
#pragma unroll
            for (int mt = 0; mt < 2; mt++) {
                int row = wm + mt*16 + g;
                uint2 aA = *(const uint2*)&asc[(row    )*40 + kb + 2*tg];
                uint2 aB = *(const uint2*)&asc[(row + 8)*40 + kb + 2*tg];
                af[mt][0] = aA.x; af[mt][2] = aA.y;
                af[mt][1] = aB.x; af[mt][3] = aB.y;
            }
            uint32_t bf[8][2];
#pragma unroll
            for (int nt = 0; nt < 8; nt++) {
                int col = wn + nt*8 + g;
                uint2 bb = *(const uint2*)&bsc[col*40 + kb + 2*tg];
                bf[nt][0] = bb.x; bf[nt][1] = bb.y;
            }
#pragma unroll
            for (int mt = 0; mt < 2; mt++)
#pragma unroll
                for (int nt = 0; nt < 8; nt++)
                    mma_tf32(acc[mt][nt], af[mt], bf[nt]);
        }
        __syncthreads();
        cur ^= 1;
    }
#undef GEMM_STAGE

#pragma unroll
    for (int mt = 0; mt < 2; mt++) {
        int row = m0 + wm + mt*16 + g;
#pragma unroll
        for (int nt = 0; nt < 8; nt++) {
            int base = n0 + wn + nt*8;
            float o0 = acc[mt][nt][0], o1 = acc[mt][nt][1];
            float o2 = acc[mt][nt][2], o3 = acc[mt][nt][3];
            if (round_out) {
                int p0 = ksperm(2*tg), p1 = ksperm(2*tg + 1);
                Cm[(size_t)row * N + base + p0]       = __uint_as_float(f2tf(o0));
                Cm[(size_t)row * N + base + p1]       = __uint_as_float(f2tf(o1));
                Cm[(size_t)(row + 8) * N + base + p0] = __uint_as_float(f2tf(o2));
                Cm[(size_t)(row + 8) * N + base + p1] = __uint_as_float(f2tf(o3));
            } else {
                int col = base + tg*2;
                *(float2*)&Cm[(size_t)row * N + col]       = make_float2(o0, o1);
                *(float2*)&Cm[(size_t)(row + 8) * N + col] = make_float2(o2, o3);
            }
        }
    }
}

// ============================================================
// SRU (R7 config): block per (d,b,jhalf) = 64 blocks x 256 thr
// ============================================================
__device__ __forceinline__ float sigmf(float x) {
    return __fdividef(1.f, 1.f + __expf(-x));
}

template <int KK>
__global__ __launch_bounds__(256)
void sru2_kernel(const float* __restrict__ U,
                 const float* __restrict__ xn,
                 const float* __restrict__ vc,
                 const float* __restrict__ bias,
                 float* __restrict__ out) {
    float* sm = (float*)dynsmem;
    float* ub = sm;                       // [2][8][KK*256]
    float* xb = sm + 2*8*KK*256;          // [2][8][256] (KK==3)

    const int tj = threadIdx.x;
    const int bx = blockIdx.x;
    const int d  = bx >> 5;
    const int b  = (bx >> 1) & 15;
    const int jh = bx & 1;
    const int j  = jh*256 + tj;
    const int RW = 2*KK*512;

    float vf = vc[d*1024 + j],   vr = vc[d*1024 + 512 + j];
    float bf = bias[d*1024 + j], br = bias[d*1024 + 512 + j];

#define SRU_LOAD_CHUNK(cc, buf) do {                                          \
    int s0 = (cc)*8;                                                          \
    for (int idx = tj; idx < 8*KK*64; idx += 256) {                           \
        int i = idx / (KK*64);                                                \
        int o = idx - i*(KK*64);                                              \
        int gi = o >> 6, gw = o & 63;                                         \
        int t = d ? (1023 - (s0+i)) : (s0+i);                                 \
        const float* src = U + ((size_t)t*16 + b)*RW + d*KK*512               \
                             + gi*512 + jh*256 + gw*4;                        \
        cpa16(ub + ((size_t)((buf)*8 + i)*KK + gi)*256 + gw*4, src);          \
    }                                                                         \
    if (KK == 3) {                                                            \
        for (int idx = tj; idx < 512; idx += 256) {                           \
            int i = idx >> 6, gw = idx & 63;                                  \
            int t = d ? (1023 - (s0+i)) : (s0+i);                             \
            const float* src = xn + ((size_t)t*16 + b)*1024 + d*512           \
                                  + jh*256 + gw*4;                            \
            cpa16(xb + ((buf)*8 + i)*256 + gw*4, src);                        \
        }                                                                     \
    }                                                                         \
    asm volatile("cp.async.commit_group;\n");                                 \
} while (0)

    SRU_LOAD_CHUNK(0, 0);

    float c = 0.f;
    for (int ch = 0; ch < 128; ch++) {
        int buf = ch & 1;
        if (ch < 127) {
            SRU_LOAD_CHUNK(ch + 1, buf ^ 1);
            asm volatile("cp.async.wait_group 1;\n");
        } else {
            asm volatile("cp.async.wait_group 0;\n");
        }
        __syncthreads();
#pragma unroll
        for (int i = 0; i < 8; i++) {
            int s = ch*8 + i;
            int t = d ? (1023 - s) : s;
            const float* us = ub + (size_t)(buf*8 + i)*KK*256;
            float a0 = us[tj], a1 = us[256 + tj], a2 = us[512 + tj];
            float rx = (KK == 4) ? us[768 + tj] : xb[(buf*8 + i)*256 + tj];
            float f = sigmf(fmaf(vf, c, a1) + bf);
            c = fmaf(f, c - a0, a0);
            float r = sigmf(fmaf(vr, c, a2) + br);
            out[((size_t)t*16 + b)*1024 + d*512 + j] = fmaf(r, c - rx, rx);
        }
        __syncthreads();
    }
#undef SRU_LOAD_CHUNK
}

// ============================================================
// final: per row LN(1024) + @cls_w(1024,30)
// ============================================================
__global__ void final_kernel(const float* __restrict__ s,
                             const float* __restrict__ g,
                             const float* __restrict__ bb,
                             const float* __restrict__ cw,
                             float* __restrict__ out) {
    int row = blockIdx.x;
    int t = row >> 4, b = row & 15;
    int tid = threadIdx.x;
    const float* x = s + (size_t)row * 1024;

    float4 v4 = *(const float4*)(x + tid*4);
    float sm = v4.x + v4.y + v4.z + v4.w;
    float s2 = v4.x*v4.x + v4.y*v4.y + v4.z*v4.z + v4.w*v4.w;

    __shared__ float rs[256], rs2[256];
    rs[tid] = sm; rs2[tid] = s2;
    __syncthreads();
    for (int o = 128; o > 0; o >>= 1) {
        if (tid < o) { rs[tid] += rs[tid+o]; rs2[tid] += rs2[tid+o]; }
        __syncthreads();
    }
    float mean = rs[0] * (1.f/1024.f);
    float var  = rs2[0] * (1.f/1024.f) - mean*mean;
    float inv  = rsqrtf(var + EPSV);

    float acc[30];
#pragma unroll
    for (int k = 0; k < 30; k++) acc[k] = 0.f;

    for (int dd = tid; dd < 1024; dd += 256) {
        float v = (x[dd] - mean)*inv*g[dd] + bb[dd];
        const float* cwr = cw + dd*30;
#pragma unroll
        for (int k = 0; k < 30; k++)
            acc[k] = fmaf(v, cwr[k], acc[k]);
    }

    __shared__ float sacc[30];
    if (tid < 30) sacc[tid] = 0.f;
    __syncthreads();
#pragma unroll
    for (int k = 0; k < 30; k++) {
        float v = acc[k];
#pragma unroll
        for (int o = 16; o > 0; o >>= 1)
            v += __shfl_down_sync(0xffffffffu, v, o);
        if ((tid & 31) == 0) atomicAdd(&sacc[k], v);
    }
    __syncthreads();
    if (tid < 30)
        out[((size_t)b*1024 + t)*30 + tid] = sacc[tid];
}

// ============================================================
// host orchestration
// ============================================================
extern "C" void kernel_launch(void* const* d_in, const int* in_sizes, int n_in,
                              void* d_out, int out_size) {
    const float* x       = (const float*)d_in[0];
    const float* conv0_w = (const float*)d_in[1];
    const float* conv0_b = (const float*)d_in[2];
    const float* rc1w = (const float*)d_in[3];
    const float* rc1b = (const float*)d_in[4];
    const float* rb1g = (const float*)d_in[5];
    const float* rb1b = (const float*)d_in[6];
    const float* rb1m = (const float*)d_in[7];
    const float* rb1v = (const float*)d_in[8];
    const float* rc2w = (const float*)d_in[9];
    const float* rc2b = (const float*)d_in[10];
    const float* rb2g = (const float*)d_in[11];
    const float* rb2b = (const float*)d_in[12];
    const float* rb2m = (const float*)d_in[13];
    const float* rb2v = (const float*)d_in[14];
    const float* ln0g = (const float*)d_in[15];
    const float* ln0b = (const float*)d_in[16];
    const float* wproj0 = (const float*)d_in[17];
    const float* w0   = (const float*)d_in[18];
    const float* vc0  = (const float*)d_in[19];
    const float* bias0= (const float*)d_in[20];
    const float* lng  = (const float*)d_in[21];
    const float* lnb  = (const float*)d_in[22];
    const float* wproj= (const float*)d_in[23];
    const float* w    = (const float*)d_in[24];
    const float* vc   = (const float*)d_in[25];
    const float* bias = (const float*)d_in[26];
    const float* clng = (const float*)d_in[27];
    const float* clnb = (const float*)d_in[28];
    const float* clsw = (const float*)d_in[29];

    float *bufA, *bufB, *xn, *xnT, *tmp, *U, *sa, *sb, *bias2, *wpT, *wwT;
    uint32_t *w1, *w2, *h1A, *h2A, *h1B, *h2B;
    cudaGetSymbolAddress((void**)&bufA,  g_bufA);
    cudaGetSymbolAddress((void**)&bufB,  g_bufB);
    cudaGetSymbolAddress((void**)&xn,    g_xn);
    cudaGetSymbolAddress((void**)&xnT,   g_xnT);
    cudaGetSymbolAddress((void**)&tmp,   g_tmp);
    cudaGetSymbolAddress((void**)&U,     g_U);
    cudaGetSymbolAddress((void**)&sa,    g_sa);
    cudaGetSymbolAddress((void**)&sb,    g_sb);
    cudaGetSymbolAddress((void**)&w1,    g_w1);
    cudaGetSymbolAddress((void**)&w2,    g_w2);
    cudaGetSymbolAddress((void**)&bias2, g_bias2);
    cudaGetSymbolAddress((void**)&h1A,   g_h1A);
    cudaGetSymbolAddress((void**)&h2A,   g_h2A);
    cudaGetSymbolAddress((void**)&h1B,   g_h1B);
    cudaGetSymbolAddress((void**)&h2B,   g_h2B);
    cudaGetSymbolAddress((void**)&wpT,   g_wpT);
    cudaGetSymbolAddress((void**)&wwT,   g_wwT);

    cudaFuncSetAttribute(resconv_mma_kernel,
                         cudaFuncAttributeMaxDynamicSharedMemorySize, RC_WORDS*4);
    cudaFuncSetAttribute(mma_gemm_kernel,
                         cudaFuncAttributeMaxDynamicSharedMemorySize, 2*GBUF*4);
    cudaFuncSetAttribute(sru2_kernel<4>,
                         cudaFuncAttributeMaxDynamicSharedMemorySize, 65536);
    cudaFuncSetAttribute(sru2_kernel<3>,
                         cudaFuncAttributeMaxDynamicSharedMemorySize, 65536);

    // ---- weight prep: 2 launches ----
    trT_all_kernel<<<4608, dim3(32, 8)>>>(wproj0, w0, wproj, w, wpT, wwT);
    prep_conv_all_kernel<<<dim3(5, 6), 1024>>>(rc1w, rc1b, rb1g, rb1b, rb1m, rb1v,
                                               rc2w, rc2b, rb2g, rb2b, rb2m, rb2v,
                                               w1, w2, bias2);

    // ---- conv front-end ----
    conv0_kernel<<<dim3(4, 64, 16), 256>>>(x, conv0_w, conv0_b, bufA, h1A, h2A);

    dim3 rcgrid(8, 32, 16);   // 2 f-rows per block, 256 thr
    for (int i = 0; i < 3; i++) {
        resconv_mma_kernel<<<rcgrid, 256, RC_WORDS*4>>>(h1A, h2A,
            w1 + (2*i)*4864, w2 + (2*i)*4864, bias2 + (2*i)*32,
            nullptr, bufB, h1B, h2B);
        resconv_mma_kernel<<<rcgrid, 256, RC_WORDS*4>>>(h1B, h2B,
            w1 + (2*i+1)*4864, w2 + (2*i+1)*4864, bias2 + (2*i+1)*32,
            bufA, bufA, h1A, h2A);
    }

    // ---- transpose+LN(2048) ----
    transpose_ln_kernel<<<dim3(1024, 16), 256>>>(bufA, ln0g, ln0b, xnT);

    // ---- SRU layer 0 (k=4) ----
    mma_gemm_kernel<<<dim3(2, 128), 256, 2*GBUF*4>>>(xnT, wpT, tmp, NROWS, 256, 2048, 1);
    mma_gemm_kernel<<<dim3(32, 128), 256, 2*GBUF*4>>>(tmp, wwT, U, NROWS, 4096, 256, 0);
    sru2_kernel<4><<<64, 256, 65536>>>(U, xn, vc0, bias0, sa);

    // ---- SRU layers 1-3 (k=3) ----
    float* cur = sa;
    float* nxt = sb;
    for (int i = 0; i < 3; i++) {
        ln_kernel<<<NROWS, 256>>>(cur, lng + i*1024, lnb + i*1024, xn, xnT);
        mma_gemm_kernel<<<dim3(2, 128), 256, 2*GBUF*4>>>(xnT, wpT + 524288 + i*262144,
                                                         tmp, NROWS, 256, 1024, 1);
        mma_gemm_kernel<<<dim3(24, 128), 256, 2*GBUF*4>>>(tmp, wwT + 1048576 + i*786432,
                                                          U, NROWS, 3072, 256, 0);
        sru2_kernel<3><<<64, 256, 65536>>>(U, xn, vc + i*2048, bias + i*2048, nxt);
        float* t2 = cur; cur = nxt; nxt = t2;
    }

    // ---- final LN + classifier ----
    final_kernel<<<NROWS, 256>>>(cur, clng, clnb, clsw, (float*)d_out);
}

// round 14
// speedup vs baseline: 1.0238x; 1.0131x over previous
#include <cuda_runtime.h>
#include <cuda_fp16.h>
#include <math.h>
#include <stdint.h>

#define EPSV 1e-5f
#define PP 256
#define NROWS 16384

extern __shared__ char dynsmem[];

// ---- scratch ----
__device__ float g_bufA[16*32*64*1024];
__device__ float g_bufB[16*32*64*1024];
__device__ float g_xn[NROWS*2048];
__device__ float g_xnT[NROWS*2048];
__device__ float g_tmp[NROWS*PP];
__device__ float g_U[NROWS*4096];
__device__ float g_sa[NROWS*1024];
__device__ float g_sb[NROWS*1024];
__device__ uint32_t g_w1[6*32*152];
__device__ uint32_t g_w2[6*32*152];
__device__ float g_bias2[6*32];
__device__ uint32_t g_h1A[16*64*1024*16];
__device__ uint32_t g_h2A[16*64*1024*16];
__device__ uint32_t g_h1B[16*64*1024*16];
__device__ uint32_t g_h2B[16*64*1024*16];
__device__ float g_wpT[2048*256 + 3*1024*256];
__device__ float g_wwT[4096*256 + 3*3072*256];

__device__ __forceinline__ void cpa16(void* smem, const void* gmem) {
    uint32_t s = (uint32_t)__cvta_generic_to_shared(smem);
    asm volatile("cp.async.cg.shared.global [%0], [%1], 16;\n" :: "r"(s), "l"(gmem));
}
__device__ __forceinline__ void cpa16z(void* smem, const void* gmem, bool ok) {
    uint32_t s = (uint32_t)__cvta_generic_to_shared(smem);
    int sz = ok ? 16 : 0;
    asm volatile("cp.async.cg.shared.global [%0], [%1], 16, %2;\n" :: "r"(s), "l"(gmem), "r"(sz));
}
__device__ __forceinline__ uint32_t f2tf(float x) {
    uint32_t u; asm("cvt.rna.tf32.f32 %0, %1;" : "=r"(u) : "f"(x)); return u;
}
__device__ __forceinline__ int ksperm(int k) {
    return (k & ~7) | (((k & 3) << 1) | ((k >> 2) & 1));
}
__device__ __forceinline__ uint32_t packhi(float a, float b) {
    __half2 h = __halves2half2(__float2half_rn(a), __float2half_rn(b));
    return *(uint32_t*)&h;
}
__device__ __forceinline__ uint32_t packlo(float a, float b) {
    __half ha = __float2half_rn(a), hb = __float2half_rn(b);
    __half2 l = __halves2half2(__float2half_rn(a - __half2float(ha)),
                               __float2half_rn(b - __half2float(hb)));
    return *(uint32_t*)&l;
}

// ============================================================
// ALL GEMM weight transposes in one launch
// ============================================================
__global__ void trT_all_kernel(const float* __restrict__ wproj0,
                               const float* __restrict__ w0,
                               const float* __restrict__ wproj,
                               const float* __restrict__ w,
                               float* __restrict__ wpT,
                               float* __restrict__ wwT) {
    int bid = blockIdx.x;
    const float* W; float* WT; int K, N, nx, base;
    if (bid < 512)        { W = wproj0; WT = wpT;  K = 2048; N = 256;  nx = 8;   base = 0; }
    else if (bid < 1536)  { W = w0;     WT = wwT;  K = 256;  N = 4096; nx = 128; base = 512; }
    else if (bid < 2304)  {
        int i = (bid - 1536) >> 8;
        W = wproj + (size_t)i*262144; WT = wpT + 524288 + i*262144;
        K = 1024; N = 256; nx = 8; base = 1536 + i*256;
    } else {
        int i = (bid - 2304) / 768;
        W = w + (size_t)i*786432; WT = wwT + 1048576 + i*786432;
        K = 256; N = 3072; nx = 96; base = 2304 + i*768;
    }
    int r = bid - base;
    int n0 = (r % nx) * 32, k0 = (r / nx) * 32;

    __shared__ float tile[32][33];
    int tx = threadIdx.x, ty = threadIdx.y;  // (32,8)
#pragma unroll
    for (int i = 0; i < 4; i++)
        tile[ty + 8*i][tx] = W[(size_t)(k0 + ty + 8*i)*N + n0 + tx];
    __syncthreads();
    int kst = k0 + ksperm(tx);
#pragma unroll
    for (int i = 0; i < 4; i++) {
        int n = n0 + ty + 8*i;
        WT[(size_t)n*K + kst] = __uint_as_float(f2tf(tile[tx][ty + 8*i]));
    }
}

// ============================================================
// conv0 -> NHWC fp32 + packed fp16 hi/lo (word order permuted)
// ============================================================
__global__ void conv0_kernel(const float* __restrict__ x,
                             const float* __restrict__ w,
                             const float* __restrict__ cb,
                             float* __restrict__ out,
                             uint32_t* __restrict__ oh1,
                             uint32_t* __restrict__ oh2) {
    __shared__ float ws[288];
    __shared__ float bs[32];
    int tid = threadIdx.x;
    for (int i = tid; i < 288; i += 256) ws[(i % 9)*32 + i/9] = w[i];
    if (tid < 32) bs[tid] = cb[tid];
    __syncthreads();

    int to = blockIdx.x * 256 + tid;
    int fo = blockIdx.y;
    int b  = blockIdx.z;

    float acc[32];
#pragma unroll
    for (int q = 0; q < 32; q++) acc[q] = bs[q];

#pragma unroll
    for (int df = 0; df < 3; df++) {
        int xi = 2*fo + df - 1;
        if (xi < 0 || xi >= 128) continue;
#pragma unroll
        for (int dt = 0; dt < 3; dt++) {
            int ti = 2*to + dt - 1;
            if (ti < 0 || ti >= 2048) continue;
            float v = x[((size_t)b*128 + xi)*2048 + ti];
            int j = df*3 + dt;
#pragma unroll
            for (int q = 0; q < 8; q++) {
                float4 w4 = *(const float4*)&ws[j*32 + q*4];
                acc[q*4+0] = fmaf(v, w4.x, acc[q*4+0]);
                acc[q*4+1] = fmaf(v, w4.y, acc[q*4+1]);
                acc[q*4+2] = fmaf(v, w4.z, acc[q*4+2]);
                acc[q*4+3] = fmaf(v, w4.w, acc[q*4+3]);
            }
        }
    }
    size_t pos = ((size_t)b*64 + fo)*1024 + to;
#pragma unroll
    for (int q = 0; q < 8; q++)
        *(float4*)&out[pos*32 + q*4] = make_float4(acc[q*4], acc[q*4+1], acc[q*4+2], acc[q*4+3]);

    uint32_t hw_[16], lw_[16];
#pragma unroll
    for (int p = 0; p < 16; p++) {
        int ps = ksperm(p);
        hw_[ps] = packhi(acc[2*p], acc[2*p+1]);
        lw_[ps] = packlo(acc[2*p], acc[2*p+1]);
    }
#pragma unroll
    for (int q = 0; q < 4; q++) {
        *(uint4*)&oh1[pos*16 + q*4] = *(uint4*)&hw_[q*4];
        *(uint4*)&oh2[pos*16 + q*4] = *(uint4*)&lw_[q*4];
    }
}

// ============================================================
// prep ALL 6 conv layers: [co][kk'] layout, stride 152
// ============================================================
__global__ void prep_conv_all_kernel(const float* __restrict__ rc1w,
                                     const float* __restrict__ rc1b,
                                     const float* __restrict__ rb1g,
                                     const float* __restrict__ rb1b,
                                     const float* __restrict__ rb1m,
                                     const float* __restrict__ rb1v,
                                     const float* __restrict__ rc2w,
                                     const float* __restrict__ rc2b,
                                     const float* __restrict__ rb2g,
                                     const float* __restrict__ rb2b,
                                     const float* __restrict__ rb2m,
                                     const float* __restrict__ rb2v,
                                     uint32_t* __restrict__ w1,
                                     uint32_t* __restrict__ w2,
                                     float* __restrict__ bias2) {
    int layer = blockIdx.y;
    int bi = layer >> 1, sec = layer & 1;
    const float* w   = (sec ? rc2w : rc1w) + bi*9216;
    const float* cb  = (sec ? rc2b : rc1b) + bi*32;
    const float* g   = (sec ? rb2g : rb1g) + bi*32;
    const float* bt  = (sec ? rb2b : rb1b) + bi*32;
    const float* m   = (sec ? rb2m : rb1m) + bi*32;
    const float* v   = (sec ? rb2v : rb1v) + bi*32;
    uint32_t* o1 = w1 + layer*4864;
    uint32_t* o2 = w2 + layer*4864;
    float* ob = bias2 + layer*32;

    int i = blockIdx.x * blockDim.x + threadIdx.x;
    if (i < 4608) {
        int co = i & 31, kk = i >> 5, j = kk >> 4, ci2 = kk & 15;
        float scale = g[co] * rsqrtf(v[co] + EPSV);
        float f0 = w[co*288 + (2*ci2    )*9 + j] * scale;
        float f1 = w[co*288 + (2*ci2 + 1)*9 + j] * scale;
        int kks = ksperm(kk);
        o1[co*152 + kks] = packhi(f0, f1);
        o2[co*152 + kks] = packlo(f0, f1);
    }
    if (i < 32) {
        float scale = g[i] * rsqrtf(v[i] + EPSV);
        ob[i] = bt[i] + (cb[i] - m[i]) * scale;
    }
}

// ============================================================
// residual conv (R11 config): 256 thr, warp tile 32x32
// ============================================================
__device__ __forceinline__ void mma_f16(float* c, const uint32_t* a, const uint32_t* b) {
    asm volatile(
        "mma.sync.aligned.m16n8k16.row.col.f32.f16.f16.f32 "
        "{%0,%1,%2,%3}, {%4,%5,%6,%7}, {%8,%9}, {%0,%1,%2,%3};\n"
        : "+f"(c[0]), "+f"(c[1]), "+f"(c[2]), "+f"(c[3])
        : "r"(a[0]), "r"(a[1]), "r"(a[2]), "r"(a[3]), "r"(b[0]), "r"(b[1]));
}

#define RC_SLAB  3120
#define RC_A1 0
#define RC_A2 12480
#define RC_W1 24960
#define RC_W2 29824
#define RC_WORDS 34688

__global__ __launch_bounds__(256)
void resconv_mma_kernel(const uint32_t* __restrict__ ih1,
                        const uint32_t* __restrict__ ih2,
                        const uint32_t* __restrict__ w1g,
                        const uint32_t* __restrict__ w2g,
                        const float* __restrict__ bias2,
                        const float* __restrict__ res,
                        float* __restrict__ out,
                        uint32_t* __restrict__ oh1,
                        uint32_t* __restrict__ oh2) {
    uint32_t* sm = (uint32_t*)dynsmem;
    uint32_t* A1 = sm + RC_A1;
    uint32_t* A2 = sm + RC_A2;
    uint32_t* W1 = sm + RC_W1;
    uint32_t* W2 = sm + RC_W2;
    __shared__ float bs[32];

    int tid = threadIdx.x;
    int t0 = blockIdx.x * 128;
    int f0 = blockIdx.y * 2;
    int b  = blockIdx.z;
    if (tid < 32) bs[tid] = bias2[tid];

    for (int i = tid; i < 1216; i += 256) {
        cpa16(W1 + i*4, w1g + i*4);
        cpa16(W2 + i*4, w2g + i*4);
    }
    for (int idx = tid; idx < 2080; idx += 256) {
        int s = idx / 520, rem = idx - s*520;
        int r = rem >> 2, gq = rem & 3;
        int xi = f0 - 1 + s;
        int t  = t0 - 1 + r;
        bool ok = (xi >= 0) && (xi < 64) && (t >= 0) && (t < 1024);
        size_t off = ok ? ((((size_t)b*64 + xi)*1024 + t)*16 + gq*4) : 0;
        int dst = s*RC_SLAB + r*24 + gq*4;
        cpa16z(A1 + dst, ih1 + off, ok);
        cpa16z(A2 + dst, ih2 + off, ok);
    }
    asm volatile("cp.async.commit_group;\n");
    asm volatile("cp.async.wait_group 0;\n");
    __syncthreads();

    int lane = tid & 31, wid = tid >> 5;
    int fi = wid >> 2, w4 = wid & 3;
    int f  = f0 + fi;
    int g = lane >> 2, tg = lane & 3;
    int rowA = w4 * 32;

    float acc[2][4][4];
#pragma unroll
    for (int mt = 0; mt < 2; mt++)
#pragma unroll
        for (int nt = 0; nt < 4; nt++)
#pragma unroll
            for (int i = 0; i < 4; i++) acc[mt][nt][i] = 0.f;

#pragma unroll
    for (int j = 0; j < 9; j++) {
        const int df = j / 3, dt = j % 3;
        const uint32_t* a1s = A1 + (fi + df)*RC_SLAB + (rowA + dt)*24;
        const uint32_t* a2s = A2 + (fi + df)*RC_SLAB + (rowA + dt)*24;
        const int wcol = j*16;
#pragma unroll
        for (int h = 0; h < 2; h++) {
            int kb = h*8 + 2*tg;
            uint32_t b1f[4][2], b2f[4][2];
#pragma unroll
            for (int nt = 0; nt < 4; nt++) {
                int co = nt*8 + g;
                uint2 b1 = *(const uint2*)&W1[co*152 + wcol + kb];
                uint2 b2 = *(const uint2*)&W2[co*152 + wcol + kb];
                b1f[nt][0] = b1.x; b1f[nt][1] = b1.y;
                b2f[nt][0] = b2.x; b2f[nt][1] = b2.y;
            }
#pragma unroll
            for (int mt = 0; mt < 2; mt++) {
                int rb = mt*16;
                uint32_t a1f[4], a2f[4];
                uint2 lo1 = *(const uint2*)&a1s[(rb + g    )*24 + kb];
                uint2 hi1 = *(const uint2*)&a1s[(rb + g + 8)*24 + kb];
                a1f[0] = lo1.x; a1f[2] = lo1.y; a1f[1] = hi1.x; a1f[3] = hi1.y;
                uint2 lo2 = *(const uint2*)&a2s[(rb + g    )*24 + kb];
                uint2 hi2 = *(const uint2*)&a2s[(rb + g + 8)*24 + kb];
                a2f[0] = lo2.x; a2f[2] = lo2.y; a2f[1] = hi2.x; a2f[3] = hi2.y;
#pragma unroll
                for (int nt = 0; nt < 4; nt++) {
                    mma_f16(acc[mt][nt], a1f, b1f[nt]);
                    mma_f16(acc[mt][nt], a2f, b1f[nt]);
                    mma_f16(acc[mt][nt], a1f, b2f[nt]);
                }
            }
        }
    }

    bool hasres = (res != nullptr);
    bool hash   = (oh1 != nullptr);
    __syncthreads();

    float vv[2][4][4];
#pragma unroll
    for (int mt = 0; mt < 2; mt++) {
#pragma unroll
        for (int nt = 0; nt < 4; nt++) {
            int co = nt*8 + tg*2;
#pragma unroll
            for (int half = 0; half < 2; half++) {
                int t = t0 + rowA + mt*16 + g + half*8;
                size_t addr = (((size_t)b*64 + f)*1024 + t)*32 + co;
                float v0 = acc[mt][nt][half*2 + 0] + bs[co];
                float v1 = acc[mt][nt][half*2 + 1] + bs[co + 1];
                if (hasres) {
                    float2 rv = *(const float2*)(res + addr);
                    v0 += rv.x; v1 += rv.y;
                }
                v0 = fmaxf(v0, 0.f); v1 = fmaxf(v1, 0.f);
                *(float2*)(out + addr) = make_float2(v0, v1);
                vv[mt][nt][half*2]   = v0;
                vv[mt][nt][half*2+1] = v1;
            }
        }
    }

    if (hash) {
#pragma unroll
        for (int mt = 0; mt < 2; mt++) {
#pragma unroll
            for (int nt = 0; nt < 4; nt++) {
                int wd = ksperm(nt*4 + tg);
#pragma unroll
                for (int half = 0; half < 2; half++) {
                    int tl = rowA + mt*16 + g + half*8;
                    A1[fi*RC_SLAB + tl*24 + wd] = packhi(vv[mt][nt][half*2], vv[mt][nt][half*2+1]);
                    A2[fi*RC_SLAB + tl*24 + wd] = packlo(vv[mt][nt][half*2], vv[mt][nt][half*2+1]);
                }
            }
        }
        __syncthreads();
#pragma unroll
        for (int l = 0; l < 4; l++) {
            int idx = tid + l*256;
            int pf  = idx >> 9;
            int rr  = (idx >> 2) & 127;
            int q   = idx & 3;
            size_t posb = ((size_t)b*64 + f0 + pf)*1024 + t0;
            *(uint4*)&oh1[(posb + rr)*16 + q*4] = *(uint4*)&A1[pf*RC_SLAB + rr*24 + q*4];
            *(uint4*)&oh2[(posb + rr)*16 + q*4] = *(uint4*)&A2[pf*RC_SLAB + rr*24 + q*4];
        }
    }
}

// ============================================================
// fused transpose + LN(2048) -> xnT (tf32, k-permuted)
// ============================================================
__global__ void transpose_ln_kernel(const float* __restrict__ in,
                                    const float* __restrict__ g,
                                    const float* __restrict__ bb,
                                    float* __restrict__ outT) {
    __shared__ float tile[64][33];
    __shared__ float rs[256], rs2[256];
    int t = blockIdx.x, b = blockIdx.y;
    int tid = threadIdx.x;
    float s = 0.f, s2 = 0.f;
    for (int i = tid; i < 512; i += 256) {
        int fq = i >> 3, c4 = (i & 7)*4;
        float4 v = *(const float4*)(in + (((size_t)b*64 + fq)*1024 + t)*32 + c4);
        tile[fq][c4]   = v.x; tile[fq][c4+1] = v.y;
        tile[fq][c4+2] = v.z; tile[fq][c4+3] = v.w;
        s  += v.x + v.y + v.z + v.w;
        s2 += v.x*v.x + v.y*v.y + v.z*v.z + v.w*v.w;
    }
    rs[tid] = s; rs2[tid] = s2;
    __syncthreads();
    for (int o = 128; o > 0; o >>= 1) {
        if (tid < o) { rs[tid] += rs[tid+o]; rs2[tid] += rs2[tid+o]; }
        __syncthreads();
    }
    float mean = rs[0] * (1.f/2048.f);
    float var  = rs2[0] * (1.f/2048.f) - mean*mean;
    float inv  = rsqrtf(var + EPSV);
    size_t ob = ((size_t)t*16 + b)*2048;
    for (int i = tid; i < 2048; i += 256) {
        int c = i >> 6, ff = i & 63;
        float vv = (tile[ff][c] - mean)*inv*g[i] + bb[i];
        outT[ob + ksperm(i)] = __uint_as_float(f2tf(vv));
    }
}

// ============================================================
// LN(1024): fp32 (rx path) + tf32 k-permuted (GEMM A)
// ============================================================
__global__ void ln_kernel(const float* __restrict__ in,
                          const float* __restrict__ g,
                          const float* __restrict__ bb,
                          float* __restrict__ out,
                          float* __restrict__ outT) {
    const int W = 1024;
    int row = blockIdx.x;
    int tid = threadIdx.x;
    const float* x = in + (size_t)row * W;
    float4 v4 = *(const float4*)(x + tid*4);
    float s  = v4.x + v4.y + v4.z + v4.w;
    float s2 = v4.x*v4.x + v4.y*v4.y + v4.z*v4.z + v4.w*v4.w;
    __shared__ float rs[256], rs2[256];
    rs[tid] = s; rs2[tid] = s2;
    __syncthreads();
    for (int o = 128; o > 0; o >>= 1) {
        if (tid < o) { rs[tid] += rs[tid+o]; rs2[tid] += rs2[tid+o]; }
        __syncthreads();
    }
    float mean = rs[0] * (1.f/1024.f);
    float var  = rs2[0] * (1.f/1024.f) - mean * mean;
    float inv  = rsqrtf(var + EPSV);
    int i = tid*4;
    float4 gg = *(const float4*)(g + i);
    float4 bv = *(const float4*)(bb + i);
    float r0 = (v4.x - mean)*inv*gg.x + bv.x;
    float r1 = (v4.y - mean)*inv*gg.y + bv.y;
    float r2 = (v4.z - mean)*inv*gg.z + bv.z;
    float r3 = (v4.w - mean)*inv*gg.w + bv.w;
    *(float4*)(out + (size_t)row*W + i) = make_float4(r0, r1, r2, r3);
    float* oT = outT + (size_t)row*W;
    oT[ksperm(i  )] = __uint_as_float(f2tf(r0));
    oT[ksperm(i+1)] = __uint_as_float(f2tf(r1));
    oT[ksperm(i+2)] = __uint_as_float(f2tf(r2));
    oT[ksperm(i+3)] = __uint_as_float(f2tf(r3));
}

// ============================================================
// TF32 GEMM (R7 config: 2-stage, k-interleaved LDS.64)
// ============================================================
__device__ __forceinline__ void mma_tf32(float* c, const uint32_t* a, const uint32_t* b) {
    asm volatile(
        "mma.sync.aligned.m16n8k8.row.col.f32.tf32.tf32.f32 "
        "{%0,%1,%2,%3}, {%4,%5,%6,%7}, {%8,%9}, {%0,%1,%2,%3};\n"
        : "+f"(c[0]), "+f"(c[1]), "+f"(c[2]), "+f"(c[3])
        : "r"(a[0]), "r"(a[1]), "r"(a[2]), "r"(a[3]), "r"(b[0]), "r"(b[1]));
}

#define GA_WORDS (128*40)
#define GBUF (2*GA_WORDS)

__global__ __launch_bounds__(256)
void mma_gemm_kernel(const float* __restrict__ A,
                     const float* __restrict__ BT,
                     float* __restrict__ Cm,
                     int M, int N, int K, int round_out) {
    uint32_t* gsm = (uint32_t*)dynsmem;
    int tid  = threadIdx.x;
    int lane = tid & 31, warp = tid >> 5;
    int m0 = blockIdx.y * 128, n0 = blockIdx.x * 128;
    int wm = (warp >> 1) * 32;
    int wn = (warp & 1) * 64;
    int g  = lane >> 2, tg = lane & 3;

    float acc[2][8][4];
#pragma unroll
    for (int mt = 0; mt < 2; mt++)
#pragma unroll
        for (int nt = 0; nt < 8; nt++)
#pragma unroll
            for (int i = 0; i < 4; i++) acc[mt][nt][i] = 0.f;

#define GEMM_STAGE(k0_, buf_) do {                                            \
    uint32_t* as_ = gsm + (buf_)*GBUF;                                        \
    uint32_t* bs_ = as_ + GA_WORDS;                                           \
    _Pragma("unroll")                                                         \
    for (int l = 0; l < 4; l++) {                                             \
        int idx = tid + l*256;                                                \
        int r = idx >> 3, gq = idx & 7;                                       \
        cpa16(as_ + r*40 + gq*4, A + (size_t)(m0 + r)*K + (k0_) + gq*4);      \
        cpa16(bs_ + r*40 + gq*4, BT + (size_t)(n0 + r)*K + (k0_) + gq*4);     \
    }                                                                         \
    asm volatile("cp.async.commit_group;\n");                                 \
} while (0)

    GEMM_STAGE(0, 0);
    int cur = 0;
    for (int k0 = 0; k0 < K; k0 += 32) {
        bool hn = (k0 + 32) < K;
        if (hn) {
            GEMM_STAGE(k0 + 32, cur ^ 1);
            asm volatile("cp.async.wait_group 1;\n");
        } else {
            asm volatile("cp.async.wait_group 0;\n");
        }
        __syncthreads();
        const uint32_t* asc = gsm + cur*GBUF;
        const uint32_t* bsc = asc + GA_WORDS;
#pragma unroll
        for (int kc = 0; kc < 4; kc++) {
            int kb = kc * 8;
            uint32_t af[2][4];
#pragma unroll
            for (int mt = 0; mt < 2; mt++) {
                int row = wm + mt*16 + g;
                uint2 aA = *(const uint2*)&asc[(row    )*40 + kb + 2*tg];
                uint2 aB = *(const uint2*)&asc[(row + 8)*40 + kb + 2*tg];
                af[mt][0] = aA.x; af[mt][2] = aA.y;
                af[mt][1] = aB.x; af[mt][3] = aB.y;
            }
            uint32_t bf[8][2];
#pragma unroll
            for (int nt = 0; nt < 8; nt++) {
                int col = wn + nt*8 + g;
                uint2 bb = *(const uint2*)&bsc[col*40 + kb + 2*tg];
                bf[nt][0] = bb.x; bf[nt][1] = bb.y;
            }
#pragma unroll
            for (int mt = 0; mt < 2; mt++)
#pragma unroll
                for (int nt = 0; nt < 8; nt++)
                    mma_tf32(acc[mt][nt], af[mt], bf[nt]);
        }
        __syncthreads();
        cur ^= 1;
    }
#undef GEMM_STAGE

#pragma unroll
    for (int mt = 0; mt < 2; mt++) {
        int row = m0 + wm + mt*16 + g;
#pragma unroll
        for (int nt = 0; nt < 8; nt++) {
            int base = n0 + wn + nt*8;
            float o0 = acc[mt][nt][0], o1 = acc[mt][nt][1];
            float o2 = acc[mt][nt][2], o3 = acc[mt][nt][3];
            if (round_out) {
                int p0 = ksperm(2*tg), p1 = ksperm(2*tg + 1);
                Cm[(size_t)row * N + base + p0]       = __uint_as_float(f2tf(o0));
                Cm[(size_t)row * N + base + p1]       = __uint_as_float(f2tf(o1));
                Cm[(size_t)(row + 8) * N + base + p0] = __uint_as_float(f2tf(o2));
                Cm[(size_t)(row + 8) * N + base + p1] = __uint_as_float(f2tf(o3));
            } else {
                int col = base + tg*2;
                *(float2*)&Cm[(size_t)row * N + col]       = make_float2(o0, o1);
                *(float2*)&Cm[(size_t)(row + 8) * N + col] = make_float2(o2, o3);
            }
        }
    }
}

// ============================================================
// SRU v4: block per (d,b,jquarter) = 128 blocks x 128 thr
// ============================================================
__device__ __forceinline__ float sigmf(float x) {
    return __fdividef(1.f, 1.f + __expf(-x));
}

template <int KK>
__global__ __launch_bounds__(128)
void sru2_kernel(const float* __restrict__ U,
                 const float* __restrict__ xn,
                 const float* __restrict__ vc,
                 const float* __restrict__ bias,
                 float* __restrict__ out) {
    float* sm = (float*)dynsmem;
    float* ub = sm;                       // [2][8][KK*128]
    float* xb = sm + 2*8*KK*128;          // [2][8][128] (KK==3)

    const int tj = threadIdx.x;
    const int bx = blockIdx.x;
    const int d  = bx >> 6;
    const int b  = (bx >> 2) & 15;
    const int jq = bx & 3;
    const int j  = jq*128 + tj;
    const int RW = 2*KK*512;

    float vf = vc[d*1024 + j],   vr = vc[d*1024 + 512 + j];
    float bf = bias[d*1024 + j], br = bias[d*1024 + 512 + j];

#define SRU_LOAD_CHUNK(cc, buf) do {                                          \
    int s0 = (cc)*8;                                                          \
    for (int idx = tj; idx < 8*KK*32; idx += 128) {                           \
        int i = idx / (KK*32);                                                \
        int o = idx - i*(KK*32);                                              \
        int gi = o >> 5, gw = o & 31;                                         \
        int t = d ? (1023 - (s0+i)) : (s0+i);                                 \
        const float* src = U + ((size_t)t*16 + b)*RW + d*KK*512               \
                             + gi*512 + jq*128 + gw*4;                        \
        cpa16(ub + ((size_t)((buf)*8 + i)*KK + gi)*128 + gw*4, src);          \
    }                                                                         \
    if (KK == 3) {                                                            \
        for (int idx = tj; idx < 256; idx += 128) {                           \
            int i = idx >> 5, gw = idx & 31;                                  \
            int t = d ? (1023 - (s0+i)) : (s0+i);                             \
            const float* src = xn + ((size_t)t*16 + b)*1024 + d*512           \
                                  + jq*128 + gw*4;                            \
            cpa16(xb + ((buf)*8 + i)*128 + gw*4, src);                        \
        }                                                                     \
    }                                                                         \
    asm volatile("cp.async.commit_group;\n");                                 \
} while (0)

    SRU_LOAD_CHUNK(0, 0);
    float c = 0.f;
    for (int ch = 0; ch < 128; ch++) {
        int buf = ch & 1;
        if (ch < 127) {
            SRU_LOAD_CHUNK(ch + 1, buf ^ 1);
            asm volatile("cp.async.wait_group 1;\n");
        } else {
            asm volatile("cp.async.wait_group 0;\n");
        }
        __syncthreads();
#pragma unroll
        for (int i = 0; i < 8; i++) {
            int s = ch*8 + i;
            int t = d ? (1023 - s) : s;
            const float* us = ub + (size_t)(buf*8 + i)*KK*128;
            float a0 = us[tj], a1 = us[128 + tj], a2 = us[256 + tj];
            float rx = (KK == 4) ? us[384 + tj] : xb[(buf*8 + i)*128 + tj];
            float f = sigmf(fmaf(vf, c, a1) + bf);
            c = fmaf(f, c - a0, a0);
            float r = sigmf(fmaf(vr, c, a2) + br);
            out[((size_t)t*16 + b)*1024 + d*512 + j] = fmaf(r, c - rx, rx);
        }
        __syncthreads();
    }
#undef SRU_LOAD_CHUNK
}

// ============================================================
// final v2: 4 rows per block (cw L1 reuse); per-row math identical
// ============================================================
__global__ void final_kernel(const float* __restrict__ s,
                             const float* __restrict__ g,
                             const float* __restrict__ bb,
                             const float* __restrict__ cw,
                             float* __restrict__ out) {
    int tid = threadIdx.x;
    __shared__ float rs[256], rs2[256];
    __shared__ float sacc[30];

    for (int rr = 0; rr < 4; rr++) {
        int row = blockIdx.x*4 + rr;
        int t = row >> 4, b = row & 15;
        const float* x = s + (size_t)row * 1024;

        float4 v4 = *(const float4*)(x + tid*4);
        float sm = v4.x + v4.y + v4.z + v4.w;
        float s2 = v4.x*v4.x + v4.y*v4.y + v4.z*v4.z + v4.w*v4.w;
        rs[tid] = sm; rs2[tid] = s2;
        __syncthreads();
        for (int o = 128; o > 0; o >>= 1) {
            if (tid < o) { rs[tid] += rs[tid+o]; rs2[tid] += rs2[tid+o]; }
            __syncthreads();
        }
        float mean = rs[0] * (1.f/1024.f);
        float var  = rs2[0] * (1.f/1024.f) - mean*mean;
        float inv  = rsqrtf(var + EPSV);

        float acc[30];
#pragma unroll
        for (int k = 0; k < 30; k++) acc[k] = 0.f;
        for (int dd = tid; dd < 1024; dd += 256) {
            float v = (x[dd] - mean)*inv*g[dd] + bb[dd];
            const float* cwr = cw + dd*30;
#pragma unroll
            for (int k = 0; k < 30; k++)
                acc[k] = fmaf(v, cwr[k], acc[k]);
        }

        if (tid < 30) sacc[tid] = 0.f;
        __syncthreads();
#pragma unroll
        for (int k = 0; k < 30; k++) {
            float v = acc[k];
#pragma unroll
            for (int o = 16; o > 0; o >>= 1)
                v += __shfl_down_sync(0xffffffffu, v, o);
            if ((tid & 31) == 0) atomicAdd(&sacc[k], v);
        }
        __syncthreads();
        if (tid < 30)
            out[((size_t)b*1024 + t)*30 + tid] = sacc[tid];
        __syncthreads();
    }
}

// ============================================================
// host orchestration
// ============================================================
extern "C" void kernel_launch(void* const* d_in, const int* in_sizes, int n_in,
                              void* d_out, int out_size) {
    const float* x       = (const float*)d_in[0];
    const float* conv0_w = (const float*)d_in[1];
    const float* conv0_b = (const float*)d_in[2];
    const float* rc1w = (const float*)d_in[3];
    const float* rc1b = (const float*)d_in[4];
    const float* rb1g = (const float*)d_in[5];
    const float* rb1b = (const float*)d_in[6];
    const float* rb1m = (const float*)d_in[7];
    const float* rb1v = (const float*)d_in[8];
    const float* rc2w = (const float*)d_in[9];
    const float* rc2b = (const float*)d_in[10];
    const float* rb2g = (const float*)d_in[11];
    const float* rb2b = (const float*)d_in[12];
    const float* rb2m = (const float*)d_in[13];
    const float* rb2v = (const float*)d_in[14];
    const float* ln0g = (const float*)d_in[15];
    const float* ln0b = (const float*)d_in[16];
    const float* wproj0 = (const float*)d_in[17];
    const float* w0   = (const float*)d_in[18];
    const float* vc0  = (const float*)d_in[19];
    const float* bias0= (const float*)d_in[20];
    const float* lng  = (const float*)d_in[21];
    const float* lnb  = (const float*)d_in[22];
    const float* wproj= (const float*)d_in[23];
    const float* w    = (const float*)d_in[24];
    const float* vc   = (const float*)d_in[25];
    const float* bias = (const float*)d_in[26];
    const float* clng = (const float*)d_in[27];
    const float* clnb = (const float*)d_in[28];
    const float* clsw = (const float*)d_in[29];

    float *bufA, *bufB, *xn, *xnT, *tmp, *U, *sa, *sb, *bias2, *wpT, *wwT;
    uint32_t *w1, *w2, *h1A, *h2A, *h1B, *h2B;
    cudaGetSymbolAddress((void**)&bufA,  g_bufA);
    cudaGetSymbolAddress((void**)&bufB,  g_bufB);
    cudaGetSymbolAddress((void**)&xn,    g_xn);
    cudaGetSymbolAddress((void**)&xnT,   g_xnT);
    cudaGetSymbolAddress((void**)&tmp,   g_tmp);
    cudaGetSymbolAddress((void**)&U,     g_U);
    cudaGetSymbolAddress((void**)&sa,    g_sa);
    cudaGetSymbolAddress((void**)&sb,    g_sb);
    cudaGetSymbolAddress((void**)&w1,    g_w1);
    cudaGetSymbolAddress((void**)&w2,    g_w2);
    cudaGetSymbolAddress((void**)&bias2, g_bias2);
    cudaGetSymbolAddress((void**)&h1A,   g_h1A);
    cudaGetSymbolAddress((void**)&h2A,   g_h2A);
    cudaGetSymbolAddress((void**)&h1B,   g_h1B);
    cudaGetSymbolAddress((void**)&h2B,   g_h2B);
    cudaGetSymbolAddress((void**)&wpT,   g_wpT);
    cudaGetSymbolAddress((void**)&wwT,   g_wwT);

    cudaFuncSetAttribute(resconv_mma_kernel,
                         cudaFuncAttributeMaxDynamicSharedMemorySize, RC_WORDS*4);
    cudaFuncSetAttribute(mma_gemm_kernel,
                         cudaFuncAttributeMaxDynamicSharedMemorySize, 2*GBUF*4);
    cudaFuncSetAttribute(sru2_kernel<4>,
                         cudaFuncAttributeMaxDynamicSharedMemorySize, 32768);
    cudaFuncSetAttribute(sru2_kernel<3>,
                         cudaFuncAttributeMaxDynamicSharedMemorySize, 32768);

    // ---- weight prep: 2 launches ----
    trT_all_kernel<<<4608, dim3(32, 8)>>>(wproj0, w0, wproj, w, wpT, wwT);
    prep_conv_all_kernel<<<dim3(5, 6), 1024>>>(rc1w, rc1b, rb1g, rb1b, rb1m, rb1v,
                                               rc2w, rc2b, rb2g, rb2b, rb2m, rb2v,
                                               w1, w2, bias2);

    // ---- conv front-end ----
    conv0_kernel<<<dim3(4, 64, 16), 256>>>(x, conv0_w, conv0_b, bufA, h1A, h2A);

    dim3 rcgrid(8, 32, 16);
    for (int i = 0; i < 3; i++) {
        resconv_mma_kernel<<<rcgrid, 256, RC_WORDS*4>>>(h1A, h2A,
            w1 + (2*i)*4864, w2 + (2*i)*4864, bias2 + (2*i)*32,
            nullptr, bufB, h1B, h2B);
        resconv_mma_kernel<<<rcgrid, 256, RC_WORDS*4>>>(h1B, h2B,
            w1 + (2*i+1)*4864, w2 + (2*i+1)*4864, bias2 + (2*i+1)*32,
            bufA, bufA, h1A, h2A);
    }

    // ---- transpose+LN(2048) ----
    transpose_ln_kernel<<<dim3(1024, 16), 256>>>(bufA, ln0g, ln0b, xnT);

    // ---- SRU layer 0 (k=4) ----
    mma_gemm_kernel<<<dim3(2, 128), 256, 2*GBUF*4>>>(xnT, wpT, tmp, NROWS, 256, 2048, 1);
    mma_gemm_kernel<<<dim3(32, 128), 256, 2*GBUF*4>>>(tmp, wwT, U, NROWS, 4096, 256, 0);
    sru2_kernel<4><<<128, 128, 32768>>>(U, xn, vc0, bias0, sa);

    // ---- SRU layers 1-3 (k=3) ----
    float* cur = sa;
    float* nxt = sb;
    for (int i = 0; i < 3; i++) {
        ln_kernel<<<NROWS, 256>>>(cur, lng + i*1024, lnb + i*1024, xn, xnT);
        mma_gemm_kernel<<<dim3(2, 128), 256, 2*GBUF*4>>>(xnT, wpT + 524288 + i*262144,
                                                         tmp, NROWS, 256, 1024, 1);
        mma_gemm_kernel<<<dim3(24, 128), 256, 2*GBUF*4>>>(tmp, wwT + 1048576 + i*786432,
                                                          U, NROWS, 3072, 256, 0);
        sru2_kernel<3><<<128, 128, 32768>>>(U, xn, vc + i*2048, bias + i*2048, nxt);
        float* t2 = cur; cur = nxt; nxt = t2;
    }

    // ---- final LN + classifier ----
    final_kernel<<<NROWS/4, 256>>>(cur, clng, clnb, clsw, (float*)d_out);
}

// round 15
// speedup vs baseline: 1.1412x; 1.1147x over previous
#include <cuda_runtime.h>
#include <cuda_fp16.h>
#include <math.h>
#include <stdint.h>

#define EPSV 1e-5f
#define PP 256
#define NROWS 16384

extern __shared__ char dynsmem[];

// ---- scratch ----
__device__ float g_bufA[16*32*64*1024];
__device__ float g_bufB[16*32*64*1024];
__device__ float g_xn[NROWS*2048];
__device__ uint32_t g_xnT[NROWS*1024];     // fp16-pair LN out (GEMM1 A)
__device__ uint32_t g_tmp[NROWS*128];      // fp16-pair GEMM1 out (GEMM2 A)
__device__ float g_U[NROWS*4096];
__device__ float g_sa[NROWS*1024];
__device__ float g_sb[NROWS*1024];
__device__ uint32_t g_w1[6*32*152];
__device__ uint32_t g_w2[6*32*152];
__device__ float g_bias2[6*32];
__device__ uint32_t g_h1A[16*64*1024*16];
__device__ uint32_t g_h2A[16*64*1024*16];
__device__ uint32_t g_h1B[16*64*1024*16];
__device__ uint32_t g_h2B[16*64*1024*16];
__device__ uint32_t g_wpT[262144 + 3*131072];   // fp16-pair proj weights [n][K/2]
__device__ uint32_t g_wwT[524288 + 3*393216];   // fp16-pair main weights [n][128]

__device__ __forceinline__ void cpa16(void* smem, const void* gmem) {
    uint32_t s = (uint32_t)__cvta_generic_to_shared(smem);
    asm volatile("cp.async.cg.shared.global [%0], [%1], 16;\n" :: "r"(s), "l"(gmem));
}
__device__ __forceinline__ void cpa16z(void* smem, const void* gmem, bool ok) {
    uint32_t s = (uint32_t)__cvta_generic_to_shared(smem);
    int sz = ok ? 16 : 0;
    asm volatile("cp.async.cg.shared.global [%0], [%1], 16, %2;\n" :: "r"(s), "l"(gmem), "r"(sz));
}
__device__ __forceinline__ int ksperm(int k) {
    return (k & ~7) | (((k & 3) << 1) | ((k >> 2) & 1));
}
__device__ __forceinline__ uint32_t packhi(float a, float b) {
    __half2 h = __halves2half2(__float2half_rn(a), __float2half_rn(b));
    return *(uint32_t*)&h;
}
__device__ __forceinline__ uint32_t packlo(float a, float b) {
    __half ha = __float2half_rn(a), hb = __float2half_rn(b);
    __half2 l = __halves2half2(__float2half_rn(a - __half2float(ha)),
                               __float2half_rn(b - __half2float(hb)));
    return *(uint32_t*)&l;
}

// ============================================================
// ALL GEMM weight transposes -> fp16 pairs [n][K/2]
// ============================================================
__global__ void trT_all_kernel(const float* __restrict__ wproj0,
                               const float* __restrict__ w0,
                               const float* __restrict__ wproj,
                               const float* __restrict__ w,
                               uint32_t* __restrict__ wpT,
                               uint32_t* __restrict__ wwT) {
    int bid = blockIdx.x;
    const float* W; uint32_t* WT; int K, N, nx, base;
    if (bid < 512)        { W = wproj0; WT = wpT;  K = 2048; N = 256;  nx = 8;   base = 0; }
    else if (bid < 1536)  { W = w0;     WT = wwT;  K = 256;  N = 4096; nx = 128; base = 512; }
    else if (bid < 2304)  {
        int i = (bid - 1536) >> 8;
        W = wproj + (size_t)i*262144; WT = wpT + 262144 + i*131072;
        K = 1024; N = 256; nx = 8; base = 1536 + i*256;
    } else {
        int i = (bid - 2304) / 768;
        W = w + (size_t)i*786432; WT = wwT + 524288 + i*393216;
        K = 256; N = 3072; nx = 96; base = 2304 + i*768;
    }
    int r = bid - base;
    int n0 = (r % nx) * 32, k0 = (r / nx) * 32;
    int Kw = K >> 1;

    __shared__ float tile[32][33];
    int tx = threadIdx.x, ty = threadIdx.y;  // (32,8)
#pragma unroll
    for (int i = 0; i < 4; i++)
        tile[ty + 8*i][tx] = W[(size_t)(k0 + ty + 8*i)*N + n0 + tx];
    __syncthreads();
#pragma unroll
    for (int i = 0; i < 2; i++) {
        int kp = ty + 8*i;     // 0..15
        WT[(size_t)(n0 + tx)*Kw + (k0 >> 1) + kp] =
            packhi(tile[2*kp][tx], tile[2*kp + 1][tx]);
    }
}

// ============================================================
// conv0 -> NHWC fp32 + packed fp16 hi/lo (word order permuted)
// ============================================================
__global__ void conv0_kernel(const float* __restrict__ x,
                             const float* __restrict__ w,
                             const float* __restrict__ cb,
                             float* __restrict__ out,
                             uint32_t* __restrict__ oh1,
                             uint32_t* __restrict__ oh2) {
    __shared__ float ws[288];
    __shared__ float bs[32];
    int tid = threadIdx.x;
    for (int i = tid; i < 288; i += 256) ws[(i % 9)*32 + i/9] = w[i];
    if (tid < 32) bs[tid] = cb[tid];
    __syncthreads();

    int to = blockIdx.x * 256 + tid;
    int fo = blockIdx.y;
    int b  = blockIdx.z;

    float acc[32];
#pragma unroll
    for (int q = 0; q < 32; q++) acc[q] = bs[q];

#pragma unroll
    for (int df = 0; df < 3; df++) {
        int xi = 2*fo + df - 1;
        if (xi < 0 || xi >= 128) continue;
#pragma unroll
        for (int dt = 0; dt < 3; dt++) {
            int ti = 2*to + dt - 1;
            if (ti < 0 || ti >= 2048) continue;
            float v = x[((size_t)b*128 + xi)*2048 + ti];
            int j = df*3 + dt;
#pragma unroll
            for (int q = 0; q < 8; q++) {
                float4 w4 = *(const float4*)&ws[j*32 + q*4];
                acc[q*4+0] = fmaf(v, w4.x, acc[q*4+0]);
                acc[q*4+1] = fmaf(v, w4.y, acc[q*4+1]);
                acc[q*4+2] = fmaf(v, w4.z, acc[q*4+2]);
                acc[q*4+3] = fmaf(v, w4.w, acc[q*4+3]);
            }
        }
    }
    size_t pos = ((size_t)b*64 + fo)*1024 + to;
#pragma unroll
    for (int q = 0; q < 8; q++)
        *(float4*)&out[pos*32 + q*4] = make_float4(acc[q*4], acc[q*4+1], acc[q*4+2], acc[q*4+3]);

    uint32_t hw_[16], lw_[16];
#pragma unroll
    for (int p = 0; p < 16; p++) {
        int ps = ksperm(p);
        hw_[ps] = packhi(acc[2*p], acc[2*p+1]);
        lw_[ps] = packlo(acc[2*p], acc[2*p+1]);
    }
#pragma unroll
    for (int q = 0; q < 4; q++) {
        *(uint4*)&oh1[pos*16 + q*4] = *(uint4*)&hw_[q*4];
        *(uint4*)&oh2[pos*16 + q*4] = *(uint4*)&lw_[q*4];
    }
}

// ============================================================
// prep ALL 6 conv layers: [co][kk'] layout, stride 152
// ============================================================
__global__ void prep_conv_all_kernel(const float* __restrict__ rc1w,
                                     const float* __restrict__ rc1b,
                                     const float* __restrict__ rb1g,
                                     const float* __restrict__ rb1b,
                                     const float* __restrict__ rb1m,
                                     const float* __restrict__ rb1v,
                                     const float* __restrict__ rc2w,
                                     const float* __restrict__ rc2b,
                                     const float* __restrict__ rb2g,
                                     const float* __restrict__ rb2b,
                                     const float* __restrict__ rb2m,
                                     const float* __restrict__ rb2v,
                                     uint32_t* __restrict__ w1,
                                     uint32_t* __restrict__ w2,
                                     float* __restrict__ bias2) {
    int layer = blockIdx.y;
    int bi = layer >> 1, sec = layer & 1;
    const float* w   = (sec ? rc2w : rc1w) + bi*9216;
    const float* cb  = (sec ? rc2b : rc1b) + bi*32;
    const float* g   = (sec ? rb2g : rb1g) + bi*32;
    const float* bt  = (sec ? rb2b : rb1b) + bi*32;
    const float* m   = (sec ? rb2m : rb1m) + bi*32;
    const float* v   = (sec ? rb2v : rb1v) + bi*32;
    uint32_t* o1 = w1 + layer*4864;
    uint32_t* o2 = w2 + layer*4864;
    float* ob = bias2 + layer*32;

    int i = blockIdx.x * blockDim.x + threadIdx.x;
    if (i < 4608) {
        int co = i & 31, kk = i >> 5, j = kk >> 4, ci2 = kk & 15;
        float scale = g[co] * rsqrtf(v[co] + EPSV);
        float f0 = w[co*288 + (2*ci2    )*9 + j] * scale;
        float f1 = w[co*288 + (2*ci2 + 1)*9 + j] * scale;
        int kks = ksperm(kk);
        o1[co*152 + kks] = packhi(f0, f1);
        o2[co*152 + kks] = packlo(f0, f1);
    }
    if (i < 32) {
        float scale = g[i] * rsqrtf(v[i] + EPSV);
        ob[i] = bt[i] + (cb[i] - m[i]) * scale;
    }
}

// ============================================================
// residual conv (R11 config, unchanged)
// ============================================================
__device__ __forceinline__ void mma_f16(float* c, const uint32_t* a, const uint32_t* b) {
    asm volatile(
        "mma.sync.aligned.m16n8k16.row.col.f32.f16.f16.f32 "
        "{%0,%1,%2,%3}, {%4,%5,%6,%7}, {%8,%9}, {%0,%1,%2,%3};\n"
        : "+f"(c[0]), "+f"(c[1]), "+f"(c[2]), "+f"(c[3])
        : "r"(a[0]), "r"(a[1]), "r"(a[2]), "r"(a[3]), "r"(b[0]), "r"(b[1]));
}

#define RC_SLAB  3120
#define RC_A1 0
#define RC_A2 12480
#define RC_W1 24960
#define RC_W2 29824
#define RC_WORDS 34688

__global__ __launch_bounds__(256)
void resconv_mma_kernel(const uint32_t* __restrict__ ih1,
                        const uint32_t* __restrict__ ih2,
                        const uint32_t* __restrict__ w1g,
                        const uint32_t* __restrict__ w2g,
                        const float* __restrict__ bias2,
                        const float* __restrict__ res,
                        float* __restrict__ out,
                        uint32_t* __restrict__ oh1,
                        uint32_t* __restrict__ oh2) {
    uint32_t* sm = (uint32_t*)dynsmem;
    uint32_t* A1 = sm + RC_A1;
    uint32_t* A2 = sm + RC_A2;
    uint32_t* W1 = sm + RC_W1;
    uint32_t* W2 = sm + RC_W2;
    __shared__ float bs[32];

    int tid = threadIdx.x;
    int t0 = blockIdx.x * 128;
    int f0 = blockIdx.y * 2;
    int b  = blockIdx.z;
    if (tid < 32) bs[tid] = bias2[tid];

    for (int i = tid; i < 1216; i += 256) {
        cpa16(W1 + i*4, w1g + i*4);
        cpa16(W2 + i*4, w2g + i*4);
    }
    for (int idx = tid; idx < 2080; idx += 256) {
        int s = idx / 520, rem = idx - s*520;
        int r = rem >> 2, gq = rem & 3;
        int xi = f0 - 1 + s;
        int t  = t0 - 1 + r;
        bool ok = (xi >= 0) && (xi < 64) && (t >= 0) && (t < 1024);
        size_t off = ok ? ((((size_t)b*64 + xi)*1024 + t)*16 + gq*4) : 0;
        int dst = s*RC_SLAB + r*24 + gq*4;
        cpa16z(A1 + dst, ih1 + off, ok);
        cpa16z(A2 + dst, ih2 + off, ok);
    }
    asm volatile("cp.async.commit_group;\n");
    asm volatile("cp.async.wait_group 0;\n");
    __syncthreads();

    int lane = tid & 31, wid = tid >> 5;
    int fi = wid >> 2, w4 = wid & 3;
    int f  = f0 + fi;
    int g = lane >> 2, tg = lane & 3;
    int rowA = w4 * 32;

    float acc[2][4][4];
#pragma unroll
    for (int mt = 0; mt < 2; mt++)
#pragma unroll
        for (int nt = 0; nt < 4; nt++)
#pragma unroll
            for (int i = 0; i < 4; i++) acc[mt][nt][i] = 0.f;

#pragma unroll
    for (int j = 0; j < 9; j++) {
        const int df = j / 3, dt = j % 3;
        const uint32_t* a1s = A1 + (fi + df)*RC_SLAB + (rowA + dt)*24;
        const uint32_t* a2s = A2 + (fi + df)*RC_SLAB + (rowA + dt)*24;
        const int wcol = j*16;
#pragma unroll
        for (int h = 0; h < 2; h++) {
            int kb = h*8 + 2*tg;
            uint32_t b1f[4][2], b2f[4][2];
#pragma unroll
            for (int nt = 0; nt < 4; nt++) {
                int co = nt*8 + g;
                uint2 b1 = *(const uint2*)&W1[co*152 + wcol + kb];
                uint2 b2 = *(const uint2*)&W2[co*152 + wcol + kb];
                b1f[nt][0] = b1.x; b1f[nt][1] = b1.y;
                b2f[nt][0] = b2.x; b2f[nt][1] = b2.y;
            }
#pragma unroll
            for (int mt = 0; mt < 2; mt++) {
                int rb = mt*16;
                uint32_t a1f[4], a2f[4];
                uint2 lo1 = *(const uint2*)&a1s[(rb + g    )*24 + kb];
                uint2 hi1 = *(const uint2*)&a1s[(rb + g + 8)*24 + kb];
                a1f[0] = lo1.x; a1f[2] = lo1.y; a1f[1] = hi1.x; a1f[3] = hi1.y;
                uint2 lo2 = *(const uint2*)&a2s[(rb + g    )*24 + kb];
                uint2 hi2 = *(const uint2*)&a2s[(rb + g + 8)*24 + kb];
                a2f[0] = lo2.x; a2f[2] = lo2.y; a2f[1] = hi2.x; a2f[3] = hi2.y;
#pragma unroll
                for (int nt = 0; nt < 4; nt++) {
                    mma_f16(acc[mt][nt], a1f, b1f[nt]);
                    mma_f16(acc[mt][nt], a2f, b1f[nt]);
                    mma_f16(acc[mt][nt], a1f, b2f[nt]);
                }
            }
        }
    }

    bool hasres = (res != nullptr);
    bool hash   = (oh1 != nullptr);
    __syncthreads();

    float vv[2][4][4];
#pragma unroll
    for (int mt = 0; mt < 2; mt++) {
#pragma unroll
        for (int nt = 0; nt < 4; nt++) {
            int co = nt*8 + tg*2;
#pragma unroll
            for (int half = 0; half < 2; half++) {
                int t = t0 + rowA + mt*16 + g + half*8;
                size_t addr = (((size_t)b*64 + f)*1024 + t)*32 + co;
                float v0 = acc[mt][nt][half*2 + 0] + bs[co];
                float v1 = acc[mt][nt][half*2 + 1] + bs[co + 1];
                if (hasres) {
                    float2 rv = *(const float2*)(res + addr);
                    v0 += rv.x; v1 += rv.y;
                }
                v0 = fmaxf(v0, 0.f); v1 = fmaxf(v1, 0.f);
                *(float2*)(out + addr) = make_float2(v0, v1);
                vv[mt][nt][half*2]   = v0;
                vv[mt][nt][half*2+1] = v1;
            }
        }
    }

    if (hash) {
#pragma unroll
        for (int mt = 0; mt < 2; mt++) {
#pragma unroll
            for (int nt = 0; nt < 4; nt++) {
                int wd = ksperm(nt*4 + tg);
#pragma unroll
                for (int half = 0; half < 2; half++) {
                    int tl = rowA + mt*16 + g + half*8;
                    A1[fi*RC_SLAB + tl*24 + wd] = packhi(vv[mt][nt][half*2], vv[mt][nt][half*2+1]);
                    A2[fi*RC_SLAB + tl*24 + wd] = packlo(vv[mt][nt][half*2], vv[mt][nt][half*2+1]);
                }
            }
        }
        __syncthreads();
#pragma unroll
        for (int l = 0; l < 4; l++) {
            int idx = tid + l*256;
            int pf  = idx >> 9;
            int rr  = (idx >> 2) & 127;
            int q   = idx & 3;
            size_t posb = ((size_t)b*64 + f0 + pf)*1024 + t0;
            *(uint4*)&oh1[(posb + rr)*16 + q*4] = *(uint4*)&A1[pf*RC_SLAB + rr*24 + q*4];
            *(uint4*)&oh2[(posb + rr)*16 + q*4] = *(uint4*)&A2[pf*RC_SLAB + rr*24 + q*4];
        }
    }
}

// ============================================================
// fused transpose + LN(2048) -> xnT fp16 pairs
// ============================================================
__global__ void transpose_ln_kernel(const float* __restrict__ in,
                                    const float* __restrict__ g,
                                    const float* __restrict__ bb,
                                    uint32_t* __restrict__ outT) {
    __shared__ float tile[64][33];
    __shared__ float rs[256], rs2[256];
    int t = blockIdx.x, b = blockIdx.y;
    int tid = threadIdx.x;
    float s = 0.f, s2 = 0.f;
    for (int i = tid; i < 512; i += 256) {
        int fq = i >> 3, c4 = (i & 7)*4;
        float4 v = *(const float4*)(in + (((size_t)b*64 + fq)*1024 + t)*32 + c4);
        tile[fq][c4]   = v.x; tile[fq][c4+1] = v.y;
        tile[fq][c4+2] = v.z; tile[fq][c4+3] = v.w;
        s  += v.x + v.y + v.z + v.w;
        s2 += v.x*v.x + v.y*v.y + v.z*v.z + v.w*v.w;
    }
    rs[tid] = s; rs2[tid] = s2;
    __syncthreads();
    for (int o = 128; o > 0; o >>= 1) {
        if (tid < o) { rs[tid] += rs[tid+o]; rs2[tid] += rs2[tid+o]; }
        __syncthreads();
    }
    float mean = rs[0] * (1.f/2048.f);
    float var  = rs2[0] * (1.f/2048.f) - mean*mean;
    float inv  = rsqrtf(var + EPSV);
    size_t ob = ((size_t)t*16 + b)*1024;
    for (int i = tid*2; i < 2048; i += 512) {
        int c = i >> 6, ff = i & 63;
        float v0 = (tile[ff    ][c] - mean)*inv*g[i]   + bb[i];
        float v1 = (tile[ff + 1][c] - mean)*inv*g[i+1] + bb[i+1];
        outT[ob + (i >> 1)] = packhi(v0, v1);
    }
}

// ============================================================
// LN(1024): fp32 (rx path) + fp16 pairs (GEMM A)
// ============================================================
__global__ void ln_kernel(const float* __restrict__ in,
                          const float* __restrict__ g,
                          const float* __restrict__ bb,
                          float* __restrict__ out,
                          uint32_t* __restrict__ outT) {
    const int W = 1024;
    int row = blockIdx.x;
    int tid = threadIdx.x;
    const float* x = in + (size_t)row * W;
    float4 v4 = *(const float4*)(x + tid*4);
    float s  = v4.x + v4.y + v4.z + v4.w;
    float s2 = v4.x*v4.x + v4.y*v4.y + v4.z*v4.z + v4.w*v4.w;
    __shared__ float rs[256], rs2[256];
    rs[tid] = s; rs2[tid] = s2;
    __syncthreads();
    for (int o = 128; o > 0; o >>= 1) {
        if (tid < o) { rs[tid] += rs[tid+o]; rs2[tid] += rs2[tid+o]; }
        __syncthreads();
    }
    float mean = rs[0] * (1.f/1024.f);
    float var  = rs2[0] * (1.f/1024.f) - mean * mean;
    float inv  = rsqrtf(var + EPSV);
    int i = tid*4;
    float4 gg = *(const float4*)(g + i);
    float4 bv = *(const float4*)(bb + i);
    float r0 = (v4.x - mean)*inv*gg.x + bv.x;
    float r1 = (v4.y - mean)*inv*gg.y + bv.y;
    float r2 = (v4.z - mean)*inv*gg.z + bv.z;
    float r3 = (v4.w - mean)*inv*gg.w + bv.w;
    *(float4*)(out + (size_t)row*W + i) = make_float4(r0, r1, r2, r3);
    uint2 pw = make_uint2(packhi(r0, r1), packhi(r2, r3));
    *(uint2*)&outT[(size_t)row*512 + tid*2] = pw;
}

// ============================================================
// FP16 GEMM: C[M,N] = A@B^T, A/BT fp16 pairs [row][Kw]
// BM=128,BN=128,BK=32 (16 words); 2-stage cp.async
// out: fp32 (Cf) or fp16 pairs (Ch)
// ============================================================
#define HGT (128*20)      // words per tile
#define HGBUF (2*HGT)     // per stage (A+B) = 5120 words; 2 stages = 40960 B

__global__ __launch_bounds__(256)
void hgemm_kernel(const uint32_t* __restrict__ A,
                  const uint32_t* __restrict__ BT,
                  float* __restrict__ Cf,
                  uint32_t* __restrict__ Ch,
                  int M, int N, int Kw) {
    uint32_t* gsm = (uint32_t*)dynsmem;
    int tid  = threadIdx.x;
    int lane = tid & 31, warp = tid >> 5;
    int m0 = blockIdx.y * 128, n0 = blockIdx.x * 128;
    int wm = (warp >> 1) * 32;
    int wn = (warp & 1) * 64;
    int g  = lane >> 2, tg = lane & 3;

    float acc[2][8][4];
#pragma unroll
    for (int mt = 0; mt < 2; mt++)
#pragma unroll
        for (int nt = 0; nt < 8; nt++)
#pragma unroll
            for (int i = 0; i < 4; i++) acc[mt][nt][i] = 0.f;

#define HG_STAGE(k0w_, buf_) do {                                             \
    uint32_t* as_ = gsm + (buf_)*HGBUF;                                       \
    uint32_t* bs_ = as_ + HGT;                                                \
    _Pragma("unroll")                                                         \
    for (int l = 0; l < 2; l++) {                                             \
        int idx = tid + l*256;                                                \
        int r = idx >> 2, gq = idx & 3;                                       \
        cpa16(as_ + r*20 + gq*4, A + (size_t)(m0 + r)*Kw + (k0w_) + gq*4);    \
        cpa16(bs_ + r*20 + gq*4, BT + (size_t)(n0 + r)*Kw + (k0w_) + gq*4);   \
    }                                                                         \
    asm volatile("cp.async.commit_group;\n");                                 \
} while (0)

    HG_STAGE(0, 0);
    int cur = 0;
    for (int k0w = 0; k0w < Kw; k0w += 16) {
        bool hn = (k0w + 16) < Kw;
        if (hn) {
            HG_STAGE(k0w + 16, cur ^ 1);
            asm volatile("cp.async.wait_group 1;\n");
        } else {
            asm volatile("cp.async.wait_group 0;\n");
        }
        __syncthreads();
        const uint32_t* asc = gsm + cur*HGBUF;
        const uint32_t* bsc = asc + HGT;
#pragma unroll
        for (int kc = 0; kc < 2; kc++) {
            int kb = kc * 8;
            uint32_t af[2][4];
#pragma unroll
            for (int mt = 0; mt < 2; mt++) {
                int row = wm + mt*16 + g;
                af[mt][0] = asc[(row    )*20 + kb + tg];
                af[mt][1] = asc[(row + 8)*20 + kb + tg];
                af[mt][2] = asc[(row    )*20 + kb + tg + 4];
                af[mt][3] = asc[(row + 8)*20 + kb + tg + 4];
            }
            uint32_t bf[8][2];
#pragma unroll
            for (int nt = 0; nt < 8; nt++) {
                int col = wn + nt*8 + g;
                bf[nt][0] = bsc[col*20 + kb + tg];
                bf[nt][1] = bsc[col*20 + kb + tg + 4];
            }
#pragma unroll
            for (int mt = 0; mt < 2; mt++)
#pragma unroll
                for (int nt = 0; nt < 8; nt++)
                    mma_f16(acc[mt][nt], af[mt], bf[nt]);
        }
        __syncthreads();
        cur ^= 1;
    }
#undef HG_STAGE

#pragma unroll
    for (int mt = 0; mt < 2; mt++) {
        int row = m0 + wm + mt*16 + g;
#pragma unroll
        for (int nt = 0; nt < 8; nt++) {
            int base = n0 + wn + nt*8;
            float o0 = acc[mt][nt][0], o1 = acc[mt][nt][1];
            float o2 = acc[mt][nt][2], o3 = acc[mt][nt][3];
            if (Ch) {
                int colp = (base >> 1) + tg;
                Ch[(size_t)row*128 + colp]       = packhi(o0, o1);
                Ch[(size_t)(row + 8)*128 + colp] = packhi(o2, o3);
            } else {
                int col = base + tg*2;
                *(float2*)&Cf[(size_t)row * N + col]       = make_float2(o0, o1);
                *(float2*)&Cf[(size_t)(row + 8) * N + col] = make_float2(o2, o3);
            }
        }
    }
}

// ============================================================
// SRU (R14 config): 128 blocks x 128 thr
// ============================================================
__device__ __forceinline__ float sigmf(float x) {
    return __fdividef(1.f, 1.f + __expf(-x));
}

template <int KK>
__global__ __launch_bounds__(128)
void sru2_kernel(const float* __restrict__ U,
                 const float* __restrict__ xn,
                 const float* __restrict__ vc,
                 const float* __restrict__ bias,
                 float* __restrict__ out) {
    float* sm = (float*)dynsmem;
    float* ub = sm;
    float* xb = sm + 2*8*KK*128;

    const int tj = threadIdx.x;
    const int bx = blockIdx.x;
    const int d  = bx >> 6;
    const int b  = (bx >> 2) & 15;
    const int jq = bx & 3;
    const int j  = jq*128 + tj;
    const int RW = 2*KK*512;

    float vf = vc[d*1024 + j],   vr = vc[d*1024 + 512 + j];
    float bf = bias[d*1024 + j], br = bias[d*1024 + 512 + j];

#define SRU_LOAD_CHUNK(cc, buf) do {                                          \
    int s0 = (cc)*8;                                                          \
    for (int idx = tj; idx < 8*KK*32; idx += 128) {                           \
        int i = idx / (KK*32);                                                \
        int o = idx - i*(KK*32);                                              \
        int gi = o >> 5, gw = o & 31;                                         \
        int t = d ? (1023 - (s0+i)) : (s0+i);                                 \
        const float* src = U + ((size_t)t*16 + b)*RW + d*KK*512               \
                             + gi*512 + jq*128 + gw*4;                        \
        cpa16(ub + ((size_t)((buf)*8 + i)*KK + gi)*128 + gw*4, src);          \
    }                                                                         \
    if (KK == 3) {                                                            \
        for (int idx = tj; idx < 256; idx += 128) {                           \
            int i = idx >> 5, gw = idx & 31;                                  \
            int t = d ? (1023 - (s0+i)) : (s0+i);                             \
            const float* src = xn + ((size_t)t*16 + b)*1024 + d*512           \
                                  + jq*128 + gw*4;                            \
            cpa16(xb + ((buf)*8 + i)*128 + gw*4, src);                        \
        }                                                                     \
    }                                                                         \
    asm volatile("cp.async.commit_group;\n");                                 \
} while (0)

    SRU_LOAD_CHUNK(0, 0);
    float c = 0.f;
    for (int ch = 0; ch < 128; ch++) {
        int buf = ch & 1;
        if (ch < 127) {
            SRU_LOAD_CHUNK(ch + 1, buf ^ 1);
            asm volatile("cp.async.wait_group 1;\n");
        } else {
            asm volatile("cp.async.wait_group 0;\n");
        }
        __syncthreads();
#pragma unroll
        for (int i = 0; i < 8; i++) {
            int s = ch*8 + i;
            int t = d ? (1023 - s) : s;
            const float* us = ub + (size_t)(buf*8 + i)*KK*128;
            float a0 = us[tj], a1 = us[128 + tj], a2 = us[256 + tj];
            float rx = (KK == 4) ? us[384 + tj] : xb[(buf*8 + i)*128 + tj];
            float f = sigmf(fmaf(vf, c, a1) + bf);
            c = fmaf(f, c - a0, a0);
            float r = sigmf(fmaf(vr, c, a2) + br);
            out[((size_t)t*16 + b)*1024 + d*512 + j] = fmaf(r, c - rx, rx);
        }
        __syncthreads();
    }
#undef SRU_LOAD_CHUNK
}

// ============================================================
// final v2: 4 rows per block
// ============================================================
__global__ void final_kernel(const float* __restrict__ s,
                             const float* __restrict__ g,
                             const float* __restrict__ bb,
                             const float* __restrict__ cw,
                             float* __restrict__ out) {
    int tid = threadIdx.x;
    __shared__ float rs[256], rs2[256];
    __shared__ float sacc[30];

    for (int rr = 0; rr < 4; rr++) {
        int row = blockIdx.x*4 + rr;
        int t = row >> 4, b = row & 15;
        const float* x = s + (size_t)row * 1024;

        float4 v4 = *(const float4*)(x + tid*4);
        float sm = v4.x + v4.y + v4.z + v4.w;
        float s2 = v4.x*v4.x + v4.y*v4.y + v4.z*v4.z + v4.w*v4.w;
        rs[tid] = sm; rs2[tid] = s2;
        __syncthreads();
        for (int o = 128; o > 0; o >>= 1) {
            if (tid < o) { rs[tid] += rs[tid+o]; rs2[tid] += rs2[tid+o]; }
            __syncthreads();
        }
        float mean = rs[0] * (1.f/1024.f);
        float var  = rs2[0] * (1.f/1024.f) - mean*mean;
        float inv  = rsqrtf(var + EPSV);

        float acc[30];
#pragma unroll
        for (int k = 0; k < 30; k++) acc[k] = 0.f;
        for (int dd = tid; dd < 1024; dd += 256) {
            float v = (x[dd] - mean)*inv*g[dd] + bb[dd];
            const float* cwr = cw + dd*30;
#pragma unroll
            for (int k = 0; k < 30; k++)
                acc[k] = fmaf(v, cwr[k], acc[k]);
        }

        if (tid < 30) sacc[tid] = 0.f;
        __syncthreads();
#pragma unroll
        for (int k = 0; k < 30; k++) {
            float v = acc[k];
#pragma unroll
            for (int o = 16; o > 0; o >>= 1)
                v += __shfl_down_sync(0xffffffffu, v, o);
            if ((tid & 31) == 0) atomicAdd(&sacc[k], v);
        }
        __syncthreads();
        if (tid < 30)
            out[((size_t)b*1024 + t)*30 + tid] = sacc[tid];
        __syncthreads();
    }
}

// ============================================================
// host orchestration
// ============================================================
extern "C" void kernel_launch(void* const* d_in, const int* in_sizes, int n_in,
                              void* d_out, int out_size) {
    const float* x       = (const float*)d_in[0];
    const float* conv0_w = (const float*)d_in[1];
    const float* conv0_b = (const float*)d_in[2];
    const float* rc1w = (const float*)d_in[3];
    const float* rc1b = (const float*)d_in[4];
    const float* rb1g = (const float*)d_in[5];
    const float* rb1b = (const float*)d_in[6];
    const float* rb1m = (const float*)d_in[7];
    const float* rb1v = (const float*)d_in[8];
    const float* rc2w = (const float*)d_in[9];
    const float* rc2b = (const float*)d_in[10];
    const float* rb2g = (const float*)d_in[11];
    const float* rb2b = (const float*)d_in[12];
    const float* rb2m = (const float*)d_in[13];
    const float* rb2v = (const float*)d_in[14];
    const float* ln0g = (const float*)d_in[15];
    const float* ln0b = (const float*)d_in[16];
    const float* wproj0 = (const float*)d_in[17];
    const float* w0   = (const float*)d_in[18];
    const float* vc0  = (const float*)d_in[19];
    const float* bias0= (const float*)d_in[20];
    const float* lng  = (const float*)d_in[21];
    const float* lnb  = (const float*)d_in[22];
    const float* wproj= (const float*)d_in[23];
    const float* w    = (const float*)d_in[24];
    const float* vc   = (const float*)d_in[25];
    const float* bias = (const float*)d_in[26];
    const float* clng = (const float*)d_in[27];
    const float* clnb = (const float*)d_in[28];
    const float* clsw = (const float*)d_in[29];

    float *bufA, *bufB, *xn, *U, *sa, *sb, *bias2;
    uint32_t *xnT, *tmp, *w1, *w2, *h1A, *h2A, *h1B, *h2B, *wpT, *wwT;
    cudaGetSymbolAddress((void**)&bufA,  g_bufA);
    cudaGetSymbolAddress((void**)&bufB,  g_bufB);
    cudaGetSymbolAddress((void**)&xn,    g_xn);
    cudaGetSymbolAddress((void**)&xnT,   g_xnT);
    cudaGetSymbolAddress((void**)&tmp,   g_tmp);
    cudaGetSymbolAddress((void**)&U,     g_U);
    cudaGetSymbolAddress((void**)&sa,    g_sa);
    cudaGetSymbolAddress((void**)&sb,    g_sb);
    cudaGetSymbolAddress((void**)&w1,    g_w1);
    cudaGetSymbolAddress((void**)&w2,    g_w2);
    cudaGetSymbolAddress((void**)&bias2, g_bias2);
    cudaGetSymbolAddress((void**)&h1A,   g_h1A);
    cudaGetSymbolAddress((void**)&h2A,   g_h2A);
    cudaGetSymbolAddress((void**)&h1B,   g_h1B);
    cudaGetSymbolAddress((void**)&h2B,   g_h2B);
    cudaGetSymbolAddress((void**)&wpT,   g_wpT);
    cudaGetSymbolAddress((void**)&wwT,   g_wwT);

    cudaFuncSetAttribute(resconv_mma_kernel,
                         cudaFuncAttributeMaxDynamicSharedMemorySize, RC_WORDS*4);
    cudaFuncSetAttribute(hgemm_kernel,
                         cudaFuncAttributeMaxDynamicSharedMemorySize, 2*HGBUF*4);
    cudaFuncSetAttribute(sru2_kernel<4>,
                         cudaFuncAttributeMaxDynamicSharedMemorySize, 32768);
    cudaFuncSetAttribute(sru2_kernel<3>,
                         cudaFuncAttributeMaxDynamicSharedMemorySize, 32768);

    // ---- weight prep: 2 launches ----
    trT_all_kernel<<<4608, dim3(32, 8)>>>(wproj0, w0, wproj, w, wpT, wwT);
    prep_conv_all_kernel<<<dim3(5, 6), 1024>>>(rc1w, rc1b, rb1g, rb1b, rb1m, rb1v,
                                               rc2w, rc2b, rb2g, rb2b, rb2m, rb2v,
                                               w1, w2, bias2);

    // ---- conv front-end ----
    conv0_kernel<<<dim3(4, 64, 16), 256>>>(x, conv0_w, conv0_b, bufA, h1A, h2A);

    dim3 rcgrid(8, 32, 16);
    for (int i = 0; i < 3; i++) {
        resconv_mma_kernel<<<rcgrid, 256, RC_WORDS*4>>>(h1A, h2A,
            w1 + (2*i)*4864, w2 + (2*i)*4864, bias2 + (2*i)*32,
            nullptr, bufB, h1B, h2B);
        resconv_mma_kernel<<<rcgrid, 256, RC_WORDS*4>>>(h1B, h2B,
            w1 + (2*i+1)*4864, w2 + (2*i+1)*4864, bias2 + (2*i+1)*32,
            bufA, bufA, h1A, h2A);
    }

    // ---- transpose+LN(2048) ----
    transpose_ln_kernel<<<dim3(1024, 16), 256>>>(bufA, ln0g, ln0b, xnT);

    // ---- SRU layer 0 (k=4) ----
    hgemm_kernel<<<dim3(2, 128), 256, 2*HGBUF*4>>>(xnT, wpT, nullptr, tmp, NROWS, 256, 1024);
    hgemm_kernel<<<dim3(32, 128), 256, 2*HGBUF*4>>>(tmp, wwT, U, nullptr, NROWS, 4096, 128);
    sru2_kernel<4><<<128, 128, 32768>>>(U, xn, vc0, bias0, sa);

    // ---- SRU layers 1-3 (k=3) ----
    float* cur = sa;
    float* nxt = sb;
    for (int i = 0; i < 3; i++) {
        ln_kernel<<<NROWS, 256>>>(cur, lng + i*1024, lnb + i*1024, xn, xnT);
        hgemm_kernel<<<dim3(2, 128), 256, 2*HGBUF*4>>>(xnT, wpT + 262144 + i*131072,
                                                       nullptr, tmp, NROWS, 256, 512);
        hgemm_kernel<<<dim3(24, 128), 256, 2*HGBUF*4>>>(tmp, wwT + 524288 + i*393216,
                                                        U, nullptr, NROWS, 3072, 128);
        sru2_kernel<3><<<128, 128, 32768>>>(U, xn, vc + i*2048, bias + i*2048, nxt);
        float* t2 = cur; cur = nxt; nxt = t2;
    }

    // ---- final LN + classifier ----
    final_kernel<<<NROWS/4, 256>>>(cur, clng, clnb, clsw, (float*)d_out);
}

// round 16
// speedup vs baseline: 1.1644x; 1.0203x over previous
#include <cuda_runtime.h>
#include <cuda_fp16.h>
#include <math.h>
#include <stdint.h>

#define EPSV 1e-5f
#define PP 256
#define NROWS 16384

extern __shared__ char dynsmem[];

// ---- scratch ----
__device__ float g_xn[NROWS*2048];
__device__ uint32_t g_xnT[NROWS*1024];     // fp16-pair LN out (GEMM1 A)
__device__ uint32_t g_tmp[NROWS*128];      // fp16-pair GEMM1 out (GEMM2 A)
__device__ float g_U[NROWS*4096];
__device__ float g_sa[NROWS*1024];
__device__ float g_sb[NROWS*1024];
__device__ uint32_t g_w1[6*32*152];
__device__ uint32_t g_w2[6*32*152];
__device__ float g_bias2[6*32];
__device__ uint32_t g_h1A[16*64*1024*16];
__device__ uint32_t g_h2A[16*64*1024*16];
__device__ uint32_t g_h1B[16*64*1024*16];
__device__ uint32_t g_h2B[16*64*1024*16];
__device__ uint32_t g_wpT[262144 + 3*131072];
__device__ uint32_t g_wwT[524288 + 3*393216];

__device__ __forceinline__ void cpa16(void* smem, const void* gmem) {
    uint32_t s = (uint32_t)__cvta_generic_to_shared(smem);
    asm volatile("cp.async.cg.shared.global [%0], [%1], 16;\n" :: "r"(s), "l"(gmem));
}
__device__ __forceinline__ void cpa16z(void* smem, const void* gmem, bool ok) {
    uint32_t s = (uint32_t)__cvta_generic_to_shared(smem);
    int sz = ok ? 16 : 0;
    asm volatile("cp.async.cg.shared.global [%0], [%1], 16, %2;\n" :: "r"(s), "l"(gmem), "r"(sz));
}
__device__ __forceinline__ int ksperm(int k) {
    return (k & ~7) | (((k & 3) << 1) | ((k >> 2) & 1));
}
__device__ __forceinline__ uint32_t packhi(float a, float b) {
    __half2 h = __halves2half2(__float2half_rn(a), __float2half_rn(b));
    return *(uint32_t*)&h;
}
__device__ __forceinline__ uint32_t packlo(float a, float b) {
    __half ha = __float2half_rn(a), hb = __float2half_rn(b);
    __half2 l = __halves2half2(__float2half_rn(a - __half2float(ha)),
                               __float2half_rn(b - __half2float(hb)));
    return *(uint32_t*)&l;
}

// ============================================================
// ALL GEMM weight transposes -> fp16 pairs [n][K/2]
// ============================================================
__global__ void trT_all_kernel(const float* __restrict__ wproj0,
                               const float* __restrict__ w0,
                               const float* __restrict__ wproj,
                               const float* __restrict__ w,
                               uint32_t* __restrict__ wpT,
                               uint32_t* __restrict__ wwT) {
    int bid = blockIdx.x;
    const float* W; uint32_t* WT; int K, N, nx, base;
    if (bid < 512)        { W = wproj0; WT = wpT;  K = 2048; N = 256;  nx = 8;   base = 0; }
    else if (bid < 1536)  { W = w0;     WT = wwT;  K = 256;  N = 4096; nx = 128; base = 512; }
    else if (bid < 2304)  {
        int i = (bid - 1536) >> 8;
        W = wproj + (size_t)i*262144; WT = wpT + 262144 + i*131072;
        K = 1024; N = 256; nx = 8; base = 1536 + i*256;
    } else {
        int i = (bid - 2304) / 768;
        W = w + (size_t)i*786432; WT = wwT + 524288 + i*393216;
        K = 256; N = 3072; nx = 96; base = 2304 + i*768;
    }
    int r = bid - base;
    int n0 = (r % nx) * 32, k0 = (r / nx) * 32;
    int Kw = K >> 1;

    __shared__ float tile[32][33];
    int tx = threadIdx.x, ty = threadIdx.y;
#pragma unroll
    for (int i = 0; i < 4; i++)
        tile[ty + 8*i][tx] = W[(size_t)(k0 + ty + 8*i)*N + n0 + tx];
    __syncthreads();
#pragma unroll
    for (int i = 0; i < 2; i++) {
        int kp = ty + 8*i;
        WT[(size_t)(n0 + tx)*Kw + (k0 >> 1) + kp] =
            packhi(tile[2*kp][tx], tile[2*kp + 1][tx]);
    }
}

// ============================================================
// conv0 -> packed fp16 hi/lo ONLY (no fp32 stream)
// ============================================================
__global__ void conv0_kernel(const float* __restrict__ x,
                             const float* __restrict__ w,
                             const float* __restrict__ cb,
                             uint32_t* __restrict__ oh1,
                             uint32_t* __restrict__ oh2) {
    __shared__ float ws[288];
    __shared__ float bs[32];
    int tid = threadIdx.x;
    for (int i = tid; i < 288; i += 256) ws[(i % 9)*32 + i/9] = w[i];
    if (tid < 32) bs[tid] = cb[tid];
    __syncthreads();

    int to = blockIdx.x * 256 + tid;
    int fo = blockIdx.y;
    int b  = blockIdx.z;

    float acc[32];
#pragma unroll
    for (int q = 0; q < 32; q++) acc[q] = bs[q];

#pragma unroll
    for (int df = 0; df < 3; df++) {
        int xi = 2*fo + df - 1;
        if (xi < 0 || xi >= 128) continue;
#pragma unroll
        for (int dt = 0; dt < 3; dt++) {
            int ti = 2*to + dt - 1;
            if (ti < 0 || ti >= 2048) continue;
            float v = x[((size_t)b*128 + xi)*2048 + ti];
            int j = df*3 + dt;
#pragma unroll
            for (int q = 0; q < 8; q++) {
                float4 w4 = *(const float4*)&ws[j*32 + q*4];
                acc[q*4+0] = fmaf(v, w4.x, acc[q*4+0]);
                acc[q*4+1] = fmaf(v, w4.y, acc[q*4+1]);
                acc[q*4+2] = fmaf(v, w4.z, acc[q*4+2]);
                acc[q*4+3] = fmaf(v, w4.w, acc[q*4+3]);
            }
        }
    }
    size_t pos = ((size_t)b*64 + fo)*1024 + to;
    uint32_t hw_[16], lw_[16];
#pragma unroll
    for (int p = 0; p < 16; p++) {
        int ps = ksperm(p);
        hw_[ps] = packhi(acc[2*p], acc[2*p+1]);
        lw_[ps] = packlo(acc[2*p], acc[2*p+1]);
    }
#pragma unroll
    for (int q = 0; q < 4; q++) {
        *(uint4*)&oh1[pos*16 + q*4] = *(uint4*)&hw_[q*4];
        *(uint4*)&oh2[pos*16 + q*4] = *(uint4*)&lw_[q*4];
    }
}

// ============================================================
// prep ALL 6 conv layers: [co][kk'] layout, stride 152
// ============================================================
__global__ void prep_conv_all_kernel(const float* __restrict__ rc1w,
                                     const float* __restrict__ rc1b,
                                     const float* __restrict__ rb1g,
                                     const float* __restrict__ rb1b,
                                     const float* __restrict__ rb1m,
                                     const float* __restrict__ rb1v,
                                     const float* __restrict__ rc2w,
                                     const float* __restrict__ rc2b,
                                     const float* __restrict__ rb2g,
                                     const float* __restrict__ rb2b,
                                     const float* __restrict__ rb2m,
                                     const float* __restrict__ rb2v,
                                     uint32_t* __restrict__ w1,
                                     uint32_t* __restrict__ w2,
                                     float* __restrict__ bias2) {
    int layer = blockIdx.y;
    int bi = layer >> 1, sec = layer & 1;
    const float* w   = (sec ? rc2w : rc1w) + bi*9216;
    const float* cb  = (sec ? rc2b : rc1b) + bi*32;
    const float* g   = (sec ? rb2g : rb1g) + bi*32;
    const float* bt  = (sec ? rb2b : rb1b) + bi*32;
    const float* m   = (sec ? rb2m : rb1m) + bi*32;
    const float* v   = (sec ? rb2v : rb1v) + bi*32;
    uint32_t* o1 = w1 + layer*4864;
    uint32_t* o2 = w2 + layer*4864;
    float* ob = bias2 + layer*32;

    int i = blockIdx.x * blockDim.x + threadIdx.x;
    if (i < 4608) {
        int co = i & 31, kk = i >> 5, j = kk >> 4, ci2 = kk & 15;
        float scale = g[co] * rsqrtf(v[co] + EPSV);
        float f0 = w[co*288 + (2*ci2    )*9 + j] * scale;
        float f1 = w[co*288 + (2*ci2 + 1)*9 + j] * scale;
        int kks = ksperm(kk);
        o1[co*152 + kks] = packhi(f0, f1);
        o2[co*152 + kks] = packlo(f0, f1);
    }
    if (i < 32) {
        float scale = g[i] * rsqrtf(v[i] + EPSV);
        ob[i] = bt[i] + (cb[i] - m[i]) * scale;
    }
}

// ============================================================
// residual conv: packs in, packs out; res reconstructed hi+lo
// ============================================================
__device__ __forceinline__ void mma_f16(float* c, const uint32_t* a, const uint32_t* b) {
    asm volatile(
        "mma.sync.aligned.m16n8k16.row.col.f32.f16.f16.f32 "
        "{%0,%1,%2,%3}, {%4,%5,%6,%7}, {%8,%9}, {%0,%1,%2,%3};\n"
        : "+f"(c[0]), "+f"(c[1]), "+f"(c[2]), "+f"(c[3])
        : "r"(a[0]), "r"(a[1]), "r"(a[2]), "r"(a[3]), "r"(b[0]), "r"(b[1]));
}

#define RC_SLAB  3120
#define RC_A1 0
#define RC_A2 12480
#define RC_W1 24960
#define RC_W2 29824
#define RC_WORDS 34688

__global__ __launch_bounds__(256)
void resconv_mma_kernel(const uint32_t* __restrict__ ih1,
                        const uint32_t* __restrict__ ih2,
                        const uint32_t* __restrict__ w1g,
                        const uint32_t* __restrict__ w2g,
                        const float* __restrict__ bias2,
                        const uint32_t* __restrict__ rh1,
                        const uint32_t* __restrict__ rh2,
                        uint32_t* __restrict__ oh1,
                        uint32_t* __restrict__ oh2) {
    uint32_t* sm = (uint32_t*)dynsmem;
    uint32_t* A1 = sm + RC_A1;
    uint32_t* A2 = sm + RC_A2;
    uint32_t* W1 = sm + RC_W1;
    uint32_t* W2 = sm + RC_W2;
    __shared__ float bs[32];

    int tid = threadIdx.x;
    int t0 = blockIdx.x * 128;
    int f0 = blockIdx.y * 2;
    int b  = blockIdx.z;
    if (tid < 32) bs[tid] = bias2[tid];

    for (int i = tid; i < 1216; i += 256) {
        cpa16(W1 + i*4, w1g + i*4);
        cpa16(W2 + i*4, w2g + i*4);
    }
    for (int idx = tid; idx < 2080; idx += 256) {
        int s = idx / 520, rem = idx - s*520;
        int r = rem >> 2, gq = rem & 3;
        int xi = f0 - 1 + s;
        int t  = t0 - 1 + r;
        bool ok = (xi >= 0) && (xi < 64) && (t >= 0) && (t < 1024);
        size_t off = ok ? ((((size_t)b*64 + xi)*1024 + t)*16 + gq*4) : 0;
        int dst = s*RC_SLAB + r*24 + gq*4;
        cpa16z(A1 + dst, ih1 + off, ok);
        cpa16z(A2 + dst, ih2 + off, ok);
    }
    asm volatile("cp.async.commit_group;\n");
    asm volatile("cp.async.wait_group 0;\n");
    __syncthreads();

    int lane = tid & 31, wid = tid >> 5;
    int fi = wid >> 2, w4 = wid & 3;
    int f  = f0 + fi;
    int g = lane >> 2, tg = lane & 3;
    int rowA = w4 * 32;

    float acc[2][4][4];
#pragma unroll
    for (int mt = 0; mt < 2; mt++)
#pragma unroll
        for (int nt = 0; nt < 4; nt++)
#pragma unroll
            for (int i = 0; i < 4; i++) acc[mt][nt][i] = 0.f;

#pragma unroll
    for (int j = 0; j < 9; j++) {
        const int df = j / 3, dt = j % 3;
        const uint32_t* a1s = A1 + (fi + df)*RC_SLAB + (rowA + dt)*24;
        const uint32_t* a2s = A2 + (fi + df)*RC_SLAB + (rowA + dt)*24;
        const int wcol = j*16;
#pragma unroll
        for (int h = 0; h < 2; h++) {
            int kb = h*8 + 2*tg;
            uint32_t b1f[4][2], b2f[4][2];
#pragma unroll
            for (int nt = 0; nt < 4; nt++) {
                int co = nt*8 + g;
                uint2 b1 = *(const uint2*)&W1[co*152 + wcol + kb];
                uint2 b2 = *(const uint2*)&W2[co*152 + wcol + kb];
                b1f[nt][0] = b1.x; b1f[nt][1] = b1.y;
                b2f[nt][0] = b2.x; b2f[nt][1] = b2.y;
            }
#pragma unroll
            for (int mt = 0; mt < 2; mt++) {
                int rb = mt*16;
                uint32_t a1f[4], a2f[4];
                uint2 lo1 = *(const uint2*)&a1s[(rb + g    )*24 + kb];
                uint2 hi1 = *(const uint2*)&a1s[(rb + g + 8)*24 + kb];
                a1f[0] = lo1.x; a1f[2] = lo1.y; a1f[1] = hi1.x; a1f[3] = hi1.y;
                uint2 lo2 = *(const uint2*)&a2s[(rb + g    )*24 + kb];
                uint2 hi2 = *(const uint2*)&a2s[(rb + g + 8)*24 + kb];
                a2f[0] = lo2.x; a2f[2] = lo2.y; a2f[1] = hi2.x; a2f[3] = hi2.y;
#pragma unroll
                for (int nt = 0; nt < 4; nt++) {
                    mma_f16(acc[mt][nt], a1f, b1f[nt]);
                    mma_f16(acc[mt][nt], a2f, b1f[nt]);
                    mma_f16(acc[mt][nt], a1f, b2f[nt]);
                }
            }
        }
    }

    bool hasres = (rh1 != nullptr);
    __syncthreads();   // slabs no longer needed; reuse A1/A2 for packing

#pragma unroll
    for (int mt = 0; mt < 2; mt++) {
#pragma unroll
        for (int nt = 0; nt < 4; nt++) {
            int p  = nt*4 + tg;
            int wd = ksperm(p);
            int co = 2*p;
#pragma unroll
            for (int half = 0; half < 2; half++) {
                int tl = rowA + mt*16 + g + half*8;
                int t  = t0 + tl;
                float v0 = acc[mt][nt][half*2 + 0] + bs[co];
                float v1 = acc[mt][nt][half*2 + 1] + bs[co + 1];
                if (hasres) {
                    size_t widx = (((size_t)b*64 + f)*1024 + t)*16 + wd;
                    uint32_t r1 = rh1[widx], r2 = rh2[widx];
                    __half2 h1v = *(__half2*)&r1, h2v = *(__half2*)&r2;
                    v0 += __half2float(h1v.x) + __half2float(h2v.x);
                    v1 += __half2float(h1v.y) + __half2float(h2v.y);
                }
                v0 = fmaxf(v0, 0.f); v1 = fmaxf(v1, 0.f);
                A1[fi*RC_SLAB + tl*24 + wd] = packhi(v0, v1);
                A2[fi*RC_SLAB + tl*24 + wd] = packlo(v0, v1);
            }
        }
    }
    __syncthreads();
#pragma unroll
    for (int l = 0; l < 4; l++) {
        int idx = tid + l*256;
        int pf  = idx >> 9;
        int rr  = (idx >> 2) & 127;
        int q   = idx & 3;
        size_t posb = ((size_t)b*64 + f0 + pf)*1024 + t0;
        *(uint4*)&oh1[(posb + rr)*16 + q*4] = *(uint4*)&A1[pf*RC_SLAB + rr*24 + q*4];
        *(uint4*)&oh2[(posb + rr)*16 + q*4] = *(uint4*)&A2[pf*RC_SLAB + rr*24 + q*4];
    }
}

// ============================================================
// fused transpose + LN(2048), reads packs -> xnT fp16 pairs
// ============================================================
__global__ void transpose_ln_kernel(const uint32_t* __restrict__ ih1,
                                    const uint32_t* __restrict__ ih2,
                                    const float* __restrict__ g,
                                    const float* __restrict__ bb,
                                    uint32_t* __restrict__ outT) {
    __shared__ float tile[64][33];
    __shared__ float rs[256], rs2[256];
    int t = blockIdx.x, b = blockIdx.y;
    int tid = threadIdx.x;
    float s = 0.f, s2 = 0.f;
    for (int i = tid; i < 1024; i += 256) {
        int fq = i >> 4, p = i & 15;
        size_t base = (((size_t)b*64 + fq)*1024 + t)*16;
        uint32_t u1 = ih1[base + ksperm(p)];
        uint32_t u2 = ih2[base + ksperm(p)];
        __half2 a = *(__half2*)&u1, c2 = *(__half2*)&u2;
        float v0 = __half2float(a.x) + __half2float(c2.x);
        float v1 = __half2float(a.y) + __half2float(c2.y);
        tile[fq][2*p]     = v0;
        tile[fq][2*p + 1] = v1;
        s  += v0 + v1;
        s2 += v0*v0 + v1*v1;
    }
    rs[tid] = s; rs2[tid] = s2;
    __syncthreads();
    for (int o = 128; o > 0; o >>= 1) {
        if (tid < o) { rs[tid] += rs[tid+o]; rs2[tid] += rs2[tid+o]; }
        __syncthreads();
    }
    float mean = rs[0] * (1.f/2048.f);
    float var  = rs2[0] * (1.f/2048.f) - mean*mean;
    float inv  = rsqrtf(var + EPSV);
    size_t ob = ((size_t)t*16 + b)*1024;
    for (int i = tid*2; i < 2048; i += 512) {
        int c = i >> 6, ff = i & 63;
        float v0 = (tile[ff    ][c] - mean)*inv*g[i]   + bb[i];
        float v1 = (tile[ff + 1][c] - mean)*inv*g[i+1] + bb[i+1];
        outT[ob + (i >> 1)] = packhi(v0, v1);
    }
}

// ============================================================
// LN(1024): fp32 (rx path) + fp16 pairs (GEMM A)
// ============================================================
__global__ void ln_kernel(const float* __restrict__ in,
                          const float* __restrict__ g,
                          const float* __restrict__ bb,
                          float* __restrict__ out,
                          uint32_t* __restrict__ outT) {
    const int W = 1024;
    int row = blockIdx.x;
    int tid = threadIdx.x;
    const float* x = in + (size_t)row * W;
    float4 v4 = *(const float4*)(x + tid*4);
    float s  = v4.x + v4.y + v4.z + v4.w;
    float s2 = v4.x*v4.x + v4.y*v4.y + v4.z*v4.z + v4.w*v4.w;
    __shared__ float rs[256], rs2[256];
    rs[tid] = s; rs2[tid] = s2;
    __syncthreads();
    for (int o = 128; o > 0; o >>= 1) {
        if (tid < o) { rs[tid] += rs[tid+o]; rs2[tid] += rs2[tid+o]; }
        __syncthreads();
    }
    float mean = rs[0] * (1.f/1024.f);
    float var  = rs2[0] * (1.f/1024.f) - mean * mean;
    float inv  = rsqrtf(var + EPSV);
    int i = tid*4;
    float4 gg = *(const float4*)(g + i);
    float4 bv = *(const float4*)(bb + i);
    float r0 = (v4.x - mean)*inv*gg.x + bv.x;
    float r1 = (v4.y - mean)*inv*gg.y + bv.y;
    float r2 = (v4.z - mean)*inv*gg.z + bv.z;
    float r3 = (v4.w - mean)*inv*gg.w + bv.w;
    *(float4*)(out + (size_t)row*W + i) = make_float4(r0, r1, r2, r3);
    uint2 pw = make_uint2(packhi(r0, r1), packhi(r2, r3));
    *(uint2*)&outT[(size_t)row*512 + tid*2] = pw;
}

// ============================================================
// FP16 GEMM (R15 config)
// ============================================================
#define HGT (128*20)
#define HGBUF (2*HGT)

__global__ __launch_bounds__(256)
void hgemm_kernel(const uint32_t* __restrict__ A,
                  const uint32_t* __restrict__ BT,
                  float* __restrict__ Cf,
                  uint32_t* __restrict__ Ch,
                  int M, int N, int Kw) {
    uint32_t* gsm = (uint32_t*)dynsmem;
    int tid  = threadIdx.x;
    int lane = tid & 31, warp = tid >> 5;
    int m0 = blockIdx.y * 128, n0 = blockIdx.x * 128;
    int wm = (warp >> 1) * 32;
    int wn = (warp & 1) * 64;
    int g  = lane >> 2, tg = lane & 3;

    float acc[2][8][4];
#pragma unroll
    for (int mt = 0; mt < 2; mt++)
#pragma unroll
        for (int nt = 0; nt < 8; nt++)
#pragma unroll
            for (int i = 0; i < 4; i++) acc[mt][nt][i] = 0.f;

#define HG_STAGE(k0w_, buf_) do {                                             \
    uint32_t* as_ = gsm + (buf_)*HGBUF;                                       \
    uint32_t* bs_ = as_ + HGT;                                                \
    _Pragma("unroll")                                                         \
    for (int l = 0; l < 2; l++) {                                             \
        int idx = tid + l*256;                                                \
        int r = idx >> 2, gq = idx & 3;                                       \
        cpa16(as_ + r*20 + gq*4, A + (size_t)(m0 + r)*Kw + (k0w_) + gq*4);    \
        cpa16(bs_ + r*20 + gq*4, BT + (size_t)(n0 + r)*Kw + (k0w_) + gq*4);   \
    }                                                                         \
    asm volatile("cp.async.commit_group;\n");                                 \
} while (0)

    HG_STAGE(0, 0);
    int cur = 0;
    for (int k0w = 0; k0w < Kw; k0w += 16) {
        bool hn = (k0w + 16) < Kw;
        if (hn) {
            HG_STAGE(k0w + 16, cur ^ 1);
            asm volatile("cp.async.wait_group 1;\n");
        } else {
            asm volatile("cp.async.wait_group 0;\n");
        }
        __syncthreads();
        const uint32_t* asc = gsm + cur*HGBUF;
        const uint32_t* bsc = asc + HGT;
#pragma unroll
        for (int kc = 0; kc < 2; kc++) {
            int kb = kc * 8;
            uint32_t af[2][4];
#pragma unroll
            for (int mt = 0; mt < 2; mt++) {
                int row = wm + mt*16 + g;
                af[mt][0] = asc[(row    )*20 + kb + tg];
                af[mt][1] = asc[(row + 8)*20 + kb + tg];
                af[mt][2] = asc[(row    )*20 + kb + tg + 4];
                af[mt][3] = asc[(row + 8)*20 + kb + tg + 4];
            }
            uint32_t bf[8][2];
#pragma unroll
            for (int nt = 0; nt < 8; nt++) {
                int col = wn + nt*8 + g;
                bf[nt][0] = bsc[col*20 + kb + tg];
                bf[nt][1] = bsc[col*20 + kb + tg + 4];
            }
#pragma unroll
            for (int mt = 0; mt < 2; mt++)
#pragma unroll
                for (int nt = 0; nt < 8; nt++)
                    mma_f16(acc[mt][nt], af[mt], bf[nt]);
        }
        __syncthreads();
        cur ^= 1;
    }
#undef HG_STAGE

#pragma unroll
    for (int mt = 0; mt < 2; mt++) {
        int row = m0 + wm + mt*16 + g;
#pragma unroll
        for (int nt = 0; nt < 8; nt++) {
            int base = n0 + wn + nt*8;
            float o0 = acc[mt][nt][0], o1 = acc[mt][nt][1];
            float o2 = acc[mt][nt][2], o3 = acc[mt][nt][3];
            if (Ch) {
                int colp = (base >> 1) + tg;
                Ch[(size_t)row*128 + colp]       = packhi(o0, o1);
                Ch[(size_t)(row + 8)*128 + colp] = packhi(o2, o3);
            } else {
                int col = base + tg*2;
                *(float2*)&Cf[(size_t)row * N + col]       = make_float2(o0, o1);
                *(float2*)&Cf[(size_t)(row + 8) * N + col] = make_float2(o2, o3);
            }
        }
    }
}

// ============================================================
// SRU (R14 config): 128 blocks x 128 thr
// ============================================================
__device__ __forceinline__ float sigmf(float x) {
    return __fdividef(1.f, 1.f + __expf(-x));
}

template <int KK>
__global__ __launch_bounds__(128)
void sru2_kernel(const float* __restrict__ U,
                 const float* __restrict__ xn,
                 const float* __restrict__ vc,
                 const float* __restrict__ bias,
                 float* __restrict__ out) {
    float* sm = (float*)dynsmem;
    float* ub = sm;
    float* xb = sm + 2*8*KK*128;

    const int tj = threadIdx.x;
    const int bx = blockIdx.x;
    const int d  = bx >> 6;
    const int b  = (bx >> 2) & 15;
    const int jq = bx & 3;
    const int j  = jq*128 + tj;
    const int RW = 2*KK*512;

    float vf = vc[d*1024 + j],   vr = vc[d*1024 + 512 + j];
    float bf = bias[d*1024 + j], br = bias[d*1024 + 512 + j];

#define SRU_LOAD_CHUNK(cc, buf) do {                                          \
    int s0 = (cc)*8;                                                          \
    for (int idx = tj; idx < 8*KK*32; idx += 128) {                           \
        int i = idx / (KK*32);                                                \
        int o = idx - i*(KK*32);                                              \
        int gi = o >> 5, gw = o & 31;                                         \
        int t = d ? (1023 - (s0+i)) : (s0+i);                                 \
        const float* src = U + ((size_t)t*16 + b)*RW + d*KK*512               \
                             + gi*512 + jq*128 + gw*4;                        \
        cpa16(ub + ((size_t)((buf)*8 + i)*KK + gi)*128 + gw*4, src);          \
    }                                                                         \
    if (KK == 3) {                                                            \
        for (int idx = tj; idx < 256; idx += 128) {                           \
            int i = idx >> 5, gw = idx & 31;                                  \
            int t = d ? (1023 - (s0+i)) : (s0+i);                             \
            const float* src = xn + ((size_t)t*16 + b)*1024 + d*512           \
                                  + jq*128 + gw*4;                            \
            cpa16(xb + ((buf)*8 + i)*128 + gw*4, src);                        \
        }                                                                     \
    }                                                                         \
    asm volatile("cp.async.commit_group;\n");                                 \
} while (0)

    SRU_LOAD_CHUNK(0, 0);
    float c = 0.f;
    for (int ch = 0; ch < 128; ch++) {
        int buf = ch & 1;
        if (ch < 127) {
            SRU_LOAD_CHUNK(ch + 1, buf ^ 1);
            asm volatile("cp.async.wait_group 1;\n");
        } else {
            asm volatile("cp.async.wait_group 0;\n");
        }
        __syncthreads();
#pragma unroll
        for (int i = 0; i < 8; i++) {
            int s = ch*8 + i;
            int t = d ? (1023 - s) : s;
            const float* us = ub + (size_t)(buf*8 + i)*KK*128;
            float a0 = us[tj], a1 = us[128 + tj], a2 = us[256 + tj];
            float rx = (KK == 4) ? us[384 + tj] : xb[(buf*8 + i)*128 + tj];
            float f = sigmf(fmaf(vf, c, a1) + bf);
            c = fmaf(f, c - a0, a0);
            float r = sigmf(fmaf(vr, c, a2) + br);
            out[((size_t)t*16 + b)*1024 + d*512 + j] = fmaf(r, c - rx, rx);
        }
        __syncthreads();
    }
#undef SRU_LOAD_CHUNK
}

// ============================================================
// final v3: 8 rows per block (cls_w L1 reuse)
// ============================================================
__global__ void final_kernel(const float* __restrict__ s,
                             const float* __restrict__ g,
                             const float* __restrict__ bb,
                             const float* __restrict__ cw,
                             float* __restrict__ out) {
    int tid = threadIdx.x;
    __shared__ float rs[256], rs2[256];
    __shared__ float sacc[30];

    for (int rr = 0; rr < 8; rr++) {
        int row = blockIdx.x*8 + rr;
        int t = row >> 4, b = row & 15;
        const float* x = s + (size_t)row * 1024;

        float4 v4 = *(const float4*)(x + tid*4);
        float sm = v4.x + v4.y + v4.z + v4.w;
        float s2 = v4.x*v4.x + v4.y*v4.y + v4.z*v4.z + v4.w*v4.w;
        rs[tid] = sm; rs2[tid] = s2;
        __syncthreads();
        for (int o = 128; o > 0; o >>= 1) {
            if (tid < o) { rs[tid] += rs[tid+o]; rs2[tid] += rs2[tid+o]; }
            __syncthreads();
        }
        float mean = rs[0] * (1.f/1024.f);
        float var  = rs2[0] * (1.f/1024.f) - mean*mean;
        float inv  = rsqrtf(var + EPSV);

        float acc[30];
#pragma unroll
        for (int k = 0; k < 30; k++) acc[k] = 0.f;
        for (int dd = tid; dd < 1024; dd += 256) {
            float v = (x[dd] - mean)*inv*g[dd] + bb[dd];
            const float* cwr = cw + dd*30;
#pragma unroll
            for (int k = 0; k < 30; k++)
                acc[k] = fmaf(v, cwr[k], acc[k]);
        }

        if (tid < 30) sacc[tid] = 0.f;
        __syncthreads();
#pragma unroll
        for (int k = 0; k < 30; k++) {
            float v = acc[k];
#pragma unroll
            for (int o = 16; o > 0; o >>= 1)
                v += __shfl_down_sync(0xffffffffu, v, o);
            if ((tid & 31) == 0) atomicAdd(&sacc[k], v);
        }
        __syncthreads();
        if (tid < 30)
            out[((size_t)b*1024 + t)*30 + tid] = sacc[tid];
        __syncthreads();
    }
}

// ============================================================
// host orchestration
// ============================================================
extern "C" void kernel_launch(void* const* d_in, const int* in_sizes, int n_in,
                              void* d_out, int out_size) {
    const float* x       = (const float*)d_in[0];
    const float* conv0_w = (const float*)d_in[1];
    const float* conv0_b = (const float*)d_in[2];
    const float* rc1w = (const float*)d_in[3];
    const float* rc1b = (const float*)d_in[4];
    const float* rb1g = (const float*)d_in[5];
    const float* rb1b = (const float*)d_in[6];
    const float* rb1m = (const float*)d_in[7];
    const float* rb1v = (const float*)d_in[8];
    const float* rc2w = (const float*)d_in[9];
    const float* rc2b = (const float*)d_in[10];
    const float* rb2g = (const float*)d_in[11];
    const float* rb2b = (const float*)d_in[12];
    const float* rb2m = (const float*)d_in[13];
    const float* rb2v = (const float*)d_in[14];
    const float* ln0g = (const float*)d_in[15];
    const float* ln0b = (const float*)d_in[16];
    const float* wproj0 = (const float*)d_in[17];
    const float* w0   = (const float*)d_in[18];
    const float* vc0  = (const float*)d_in[19];
    const float* bias0= (const float*)d_in[20];
    const float* lng  = (const float*)d_in[21];
    const float* lnb  = (const float*)d_in[22];
    const float* wproj= (const float*)d_in[23];
    const float* w    = (const float*)d_in[24];
    const float* vc   = (const float*)d_in[25];
    const float* bias = (const float*)d_in[26];
    const float* clng = (const float*)d_in[27];
    const float* clnb = (const float*)d_in[28];
    const float* clsw = (const float*)d_in[29];

    float *xn, *U, *sa, *sb, *bias2;
    uint32_t *xnT, *tmp, *w1, *w2, *h1A, *h2A, *h1B, *h2B, *wpT, *wwT;
    cudaGetSymbolAddress((void**)&xn,    g_xn);
    cudaGetSymbolAddress((void**)&xnT,   g_xnT);
    cudaGetSymbolAddress((void**)&tmp,   g_tmp);
    cudaGetSymbolAddress((void**)&U,     g_U);
    cudaGetSymbolAddress((void**)&sa,    g_sa);
    cudaGetSymbolAddress((void**)&sb,    g_sb);
    cudaGetSymbolAddress((void**)&w1,    g_w1);
    cudaGetSymbolAddress((void**)&w2,    g_w2);
    cudaGetSymbolAddress((void**)&bias2, g_bias2);
    cudaGetSymbolAddress((void**)&h1A,   g_h1A);
    cudaGetSymbolAddress((void**)&h2A,   g_h2A);
    cudaGetSymbolAddress((void**)&h1B,   g_h1B);
    cudaGetSymbolAddress((void**)&h2B,   g_h2B);
    cudaGetSymbolAddress((void**)&wpT,   g_wpT);
    cudaGetSymbolAddress((void**)&wwT,   g_wwT);

    cudaFuncSetAttribute(resconv_mma_kernel,
                         cudaFuncAttributeMaxDynamicSharedMemorySize, RC_WORDS*4);
    cudaFuncSetAttribute(hgemm_kernel,
                         cudaFuncAttributeMaxDynamicSharedMemorySize, 2*HGBUF*4);
    cudaFuncSetAttribute(sru2_kernel<4>,
                         cudaFuncAttributeMaxDynamicSharedMemorySize, 32768);
    cudaFuncSetAttribute(sru2_kernel<3>,
                         cudaFuncAttributeMaxDynamicSharedMemorySize, 32768);

    // ---- weight prep ----
    trT_all_kernel<<<4608, dim3(32, 8)>>>(wproj0, w0, wproj, w, wpT, wwT);
    prep_conv_all_kernel<<<dim3(5, 6), 1024>>>(rc1w, rc1b, rb1g, rb1b, rb1m, rb1v,
                                               rc2w, rc2b, rb2g, rb2b, rb2m, rb2v,
                                               w1, w2, bias2);

    // ---- conv front-end (packs only) ----
    conv0_kernel<<<dim3(4, 64, 16), 256>>>(x, conv0_w, conv0_b, h1A, h2A);

    dim3 rcgrid(8, 32, 16);
    for (int i = 0; i < 3; i++) {
        resconv_mma_kernel<<<rcgrid, 256, RC_WORDS*4>>>(h1A, h2A,
            w1 + (2*i)*4864, w2 + (2*i)*4864, bias2 + (2*i)*32,
            nullptr, nullptr, h1B, h2B);
        resconv_mma_kernel<<<rcgrid, 256, RC_WORDS*4>>>(h1B, h2B,
            w1 + (2*i+1)*4864, w2 + (2*i+1)*4864, bias2 + (2*i+1)*32,
            h1A, h2A, h1A, h2A);
    }

    // ---- transpose+LN(2048) from packs ----
    transpose_ln_kernel<<<dim3(1024, 16), 256>>>(h1A, h2A, ln0g, ln0b, xnT);

    // ---- SRU layer 0 (k=4) ----
    hgemm_kernel<<<dim3(2, 128), 256, 2*HGBUF*4>>>(xnT, wpT, nullptr, tmp, NROWS, 256, 1024);
    hgemm_kernel<<<dim3(32, 128), 256, 2*HGBUF*4>>>(tmp, wwT, U, nullptr, NROWS, 4096, 128);
    sru2_kernel<4><<<128, 128, 32768>>>(U, xn, vc0, bias0, sa);

    // ---- SRU layers 1-3 (k=3) ----
    float* cur = sa;
    float* nxt = sb;
    for (int i = 0; i < 3; i++) {
        ln_kernel<<<NROWS, 256>>>(cur, lng + i*1024, lnb + i*1024, xn, xnT);
        hgemm_kernel<<<dim3(2, 128), 256, 2*HGBUF*4>>>(xnT, wpT + 262144 + i*131072,
                                                       nullptr, tmp, NROWS, 256, 512);
        hgemm_kernel<<<dim3(24, 128), 256, 2*HGBUF*4>>>(tmp, wwT + 524288 + i*393216,
                                                        U, nullptr, NROWS, 3072, 128);
        sru2_kernel<3><<<128, 128, 32768>>>(U, xn, vc + i*2048, bias + i*2048, nxt);
        float* t2 = cur; cur = nxt; nxt = t2;
    }

    // ---- final LN + classifier ----
    final_kernel<<<NROWS/8, 256>>>(cur, clng, clnb, clsw, (float*)d_out);
}

// round 17
// speedup vs baseline: 1.1912x; 1.0230x over previous
#include <cuda_runtime.h>
#include <cuda_fp16.h>
#include <math.h>
#include <stdint.h>

#define EPSV 1e-5f
#define PP 256
#define NROWS 16384

extern __shared__ char dynsmem[];

// ---- scratch ----
__device__ float g_xn[NROWS*2048];
__device__ uint32_t g_xnT[NROWS*1024];     // fp16-pair LN out (GEMM1 A)
__device__ uint32_t g_tmp[NROWS*128];      // fp16-pair GEMM1 out (GEMM2 A)
__device__ uint32_t g_U[NROWS*2048];       // fp16-pair GEMM2 out (SRU input)
__device__ float g_sa[NROWS*1024];
__device__ float g_sb[NROWS*1024];
__device__ uint32_t g_w1[6*32*152];
__device__ uint32_t g_w2[6*32*152];
__device__ float g_bias2[6*32];
__device__ uint32_t g_h1A[16*64*1024*16];
__device__ uint32_t g_h2A[16*64*1024*16];
__device__ uint32_t g_h1B[16*64*1024*16];
__device__ uint32_t g_h2B[16*64*1024*16];
__device__ uint32_t g_wpT[262144 + 3*131072];
__device__ uint32_t g_wwT[524288 + 3*393216];

__device__ __forceinline__ void cpa16(void* smem, const void* gmem) {
    uint32_t s = (uint32_t)__cvta_generic_to_shared(smem);
    asm volatile("cp.async.cg.shared.global [%0], [%1], 16;\n" :: "r"(s), "l"(gmem));
}
__device__ __forceinline__ void cpa16z(void* smem, const void* gmem, bool ok) {
    uint32_t s = (uint32_t)__cvta_generic_to_shared(smem);
    int sz = ok ? 16 : 0;
    asm volatile("cp.async.cg.shared.global [%0], [%1], 16, %2;\n" :: "r"(s), "l"(gmem), "r"(sz));
}
__device__ __forceinline__ int ksperm(int k) {
    return (k & ~7) | (((k & 3) << 1) | ((k >> 2) & 1));
}
__device__ __forceinline__ uint32_t packhi(float a, float b) {
    __half2 h = __halves2half2(__float2half_rn(a), __float2half_rn(b));
    return *(uint32_t*)&h;
}
__device__ __forceinline__ uint32_t packlo(float a, float b) {
    __half ha = __float2half_rn(a), hb = __float2half_rn(b);
    __half2 l = __halves2half2(__float2half_rn(a - __half2float(ha)),
                               __float2half_rn(b - __half2float(hb)));
    return *(uint32_t*)&l;
}

// ============================================================
// ALL GEMM weight transposes -> fp16 pairs [n][K/2]
// ============================================================
__global__ void trT_all_kernel(const float* __restrict__ wproj0,
                               const float* __restrict__ w0,
                               const float* __restrict__ wproj,
                               const float* __restrict__ w,
                               uint32_t* __restrict__ wpT,
                               uint32_t* __restrict__ wwT) {
    int bid = blockIdx.x;
    const float* W; uint32_t* WT; int K, N, nx, base;
    if (bid < 512)        { W = wproj0; WT = wpT;  K = 2048; N = 256;  nx = 8;   base = 0; }
    else if (bid < 1536)  { W = w0;     WT = wwT;  K = 256;  N = 4096; nx = 128; base = 512; }
    else if (bid < 2304)  {
        int i = (bid - 1536) >> 8;
        W = wproj + (size_t)i*262144; WT = wpT + 262144 + i*131072;
        K = 1024; N = 256; nx = 8; base = 1536 + i*256;
    } else {
        int i = (bid - 2304) / 768;
        W = w + (size_t)i*786432; WT = wwT + 524288 + i*393216;
        K = 256; N = 3072; nx = 96; base = 2304 + i*768;
    }
    int r = bid - base;
    int n0 = (r % nx) * 32, k0 = (r / nx) * 32;
    int Kw = K >> 1;

    __shared__ float tile[32][33];
    int tx = threadIdx.x, ty = threadIdx.y;
#pragma unroll
    for (int i = 0; i < 4; i++)
        tile[ty + 8*i][tx] = W[(size_t)(k0 + ty + 8*i)*N + n0 + tx];
    __syncthreads();
#pragma unroll
    for (int i = 0; i < 2; i++) {
        int kp = ty + 8*i;
        WT[(size_t)(n0 + tx)*Kw + (k0 >> 1) + kp] =
            packhi(tile[2*kp][tx], tile[2*kp + 1][tx]);
    }
}

// ============================================================
// conv0 -> packed fp16 hi/lo
// ============================================================
__global__ void conv0_kernel(const float* __restrict__ x,
                             const float* __restrict__ w,
                             const float* __restrict__ cb,
                             uint32_t* __restrict__ oh1,
                             uint32_t* __restrict__ oh2) {
    __shared__ float ws[288];
    __shared__ float bs[32];
    int tid = threadIdx.x;
    for (int i = tid; i < 288; i += 256) ws[(i % 9)*32 + i/9] = w[i];
    if (tid < 32) bs[tid] = cb[tid];
    __syncthreads();

    int to = blockIdx.x * 256 + tid;
    int fo = blockIdx.y;
    int b  = blockIdx.z;

    float acc[32];
#pragma unroll
    for (int q = 0; q < 32; q++) acc[q] = bs[q];

#pragma unroll
    for (int df = 0; df < 3; df++) {
        int xi = 2*fo + df - 1;
        if (xi < 0 || xi >= 128) continue;
#pragma unroll
        for (int dt = 0; dt < 3; dt++) {
            int ti = 2*to + dt - 1;
            if (ti < 0 || ti >= 2048) continue;
            float v = x[((size_t)b*128 + xi)*2048 + ti];
            int j = df*3 + dt;
#pragma unroll
            for (int q = 0; q < 8; q++) {
                float4 w4 = *(const float4*)&ws[j*32 + q*4];
                acc[q*4+0] = fmaf(v, w4.x, acc[q*4+0]);
                acc[q*4+1] = fmaf(v, w4.y, acc[q*4+1]);
                acc[q*4+2] = fmaf(v, w4.z, acc[q*4+2]);
                acc[q*4+3] = fmaf(v, w4.w, acc[q*4+3]);
            }
        }
    }
    size_t pos = ((size_t)b*64 + fo)*1024 + to;
    uint32_t hw_[16], lw_[16];
#pragma unroll
    for (int p = 0; p < 16; p++) {
        int ps = ksperm(p);
        hw_[ps] = packhi(acc[2*p], acc[2*p+1]);
        lw_[ps] = packlo(acc[2*p], acc[2*p+1]);
    }
#pragma unroll
    for (int q = 0; q < 4; q++) {
        *(uint4*)&oh1[pos*16 + q*4] = *(uint4*)&hw_[q*4];
        *(uint4*)&oh2[pos*16 + q*4] = *(uint4*)&lw_[q*4];
    }
}

// ============================================================
// prep ALL 6 conv layers
// ============================================================
__global__ void prep_conv_all_kernel(const float* __restrict__ rc1w,
                                     const float* __restrict__ rc1b,
                                     const float* __restrict__ rb1g,
                                     const float* __restrict__ rb1b,
                                     const float* __restrict__ rb1m,
                                     const float* __restrict__ rb1v,
                                     const float* __restrict__ rc2w,
                                     const float* __restrict__ rc2b,
                                     const float* __restrict__ rb2g,
                                     const float* __restrict__ rb2b,
                                     const float* __restrict__ rb2m,
                                     const float* __restrict__ rb2v,
                                     uint32_t* __restrict__ w1,
                                     uint32_t* __restrict__ w2,
                                     float* __restrict__ bias2) {
    int layer = blockIdx.y;
    int bi = layer >> 1, sec = layer & 1;
    const float* w   = (sec ? rc2w : rc1w) + bi*9216;
    const float* cb  = (sec ? rc2b : rc1b) + bi*32;
    const float* g   = (sec ? rb2g : rb1g) + bi*32;
    const float* bt  = (sec ? rb2b : rb1b) + bi*32;
    const float* m   = (sec ? rb2m : rb1m) + bi*32;
    const float* v   = (sec ? rb2v : rb1v) + bi*32;
    uint32_t* o1 = w1 + layer*4864;
    uint32_t* o2 = w2 + layer*4864;
    float* ob = bias2 + layer*32;

    int i = blockIdx.x * blockDim.x + threadIdx.x;
    if (i < 4608) {
        int co = i & 31, kk = i >> 5, j = kk >> 4, ci2 = kk & 15;
        float scale = g[co] * rsqrtf(v[co] + EPSV);
        float f0 = w[co*288 + (2*ci2    )*9 + j] * scale;
        float f1 = w[co*288 + (2*ci2 + 1)*9 + j] * scale;
        int kks = ksperm(kk);
        o1[co*152 + kks] = packhi(f0, f1);
        o2[co*152 + kks] = packlo(f0, f1);
    }
    if (i < 32) {
        float scale = g[i] * rsqrtf(v[i] + EPSV);
        ob[i] = bt[i] + (cb[i] - m[i]) * scale;
    }
}

// ============================================================
// residual conv (R16 config, unchanged)
// ============================================================
__device__ __forceinline__ void mma_f16(float* c, const uint32_t* a, const uint32_t* b) {
    asm volatile(
        "mma.sync.aligned.m16n8k16.row.col.f32.f16.f16.f32 "
        "{%0,%1,%2,%3}, {%4,%5,%6,%7}, {%8,%9}, {%0,%1,%2,%3};\n"
        : "+f"(c[0]), "+f"(c[1]), "+f"(c[2]), "+f"(c[3])
        : "r"(a[0]), "r"(a[1]), "r"(a[2]), "r"(a[3]), "r"(b[0]), "r"(b[1]));
}

#define RC_SLAB  3120
#define RC_A1 0
#define RC_A2 12480
#define RC_W1 24960
#define RC_W2 29824
#define RC_WORDS 34688

__global__ __launch_bounds__(256)
void resconv_mma_kernel(const uint32_t* __restrict__ ih1,
                        const uint32_t* __restrict__ ih2,
                        const uint32_t* __restrict__ w1g,
                        const uint32_t* __restrict__ w2g,
                        const float* __restrict__ bias2,
                        const uint32_t* __restrict__ rh1,
                        const uint32_t* __restrict__ rh2,
                        uint32_t* __restrict__ oh1,
                        uint32_t* __restrict__ oh2) {
    uint32_t* sm = (uint32_t*)dynsmem;
    uint32_t* A1 = sm + RC_A1;
    uint32_t* A2 = sm + RC_A2;
    uint32_t* W1 = sm + RC_W1;
    uint32_t* W2 = sm + RC_W2;
    __shared__ float bs[32];

    int tid = threadIdx.x;
    int t0 = blockIdx.x * 128;
    int f0 = blockIdx.y * 2;
    int b  = blockIdx.z;
    if (tid < 32) bs[tid] = bias2[tid];

    for (int i = tid; i < 1216; i += 256) {
        cpa16(W1 + i*4, w1g + i*4);
        cpa16(W2 + i*4, w2g + i*4);
    }
    for (int idx = tid; idx < 2080; idx += 256) {
        int s = idx / 520, rem = idx - s*520;
        int r = rem >> 2, gq = rem & 3;
        int xi = f0 - 1 + s;
        int t  = t0 - 1 + r;
        bool ok = (xi >= 0) && (xi < 64) && (t >= 0) && (t < 1024);
        size_t off = ok ? ((((size_t)b*64 + xi)*1024 + t)*16 + gq*4) : 0;
        int dst = s*RC_SLAB + r*24 + gq*4;
        cpa16z(A1 + dst, ih1 + off, ok);
        cpa16z(A2 + dst, ih2 + off, ok);
    }
    asm volatile("cp.async.commit_group;\n");
    asm volatile("cp.async.wait_group 0;\n");
    __syncthreads();

    int lane = tid & 31, wid = tid >> 5;
    int fi = wid >> 2, w4 = wid & 3;
    int f  = f0 + fi;
    int g = lane >> 2, tg = lane & 3;
    int rowA = w4 * 32;

    float acc[2][4][4];
#pragma unroll
    for (int mt = 0; mt < 2; mt++)
#pragma unroll
        for (int nt = 0; nt < 4; nt++)
#pragma unroll
            for (int i = 0; i < 4; i++) acc[mt][nt][i] = 0.f;

#pragma unroll
    for (int j = 0; j < 9; j++) {
        const int df = j / 3, dt = j % 3;
        const uint32_t* a1s = A1 + (fi + df)*RC_SLAB + (rowA + dt)*24;
        const uint32_t* a2s = A2 + (fi + df)*RC_SLAB + (rowA + dt)*24;
        const int wcol = j*16;
#pragma unroll
        for (int h = 0; h < 2; h++) {
            int kb = h*8 + 2*tg;
            uint32_t b1f[4][2], b2f[4][2];
#pragma unroll
            for (int nt = 0; nt < 4; nt++) {
                int co = nt*8 + g;
                uint2 b1 = *(const uint2*)&W1[co*152 + wcol + kb];
                uint2 b2 = *(const uint2*)&W2[co*152 + wcol + kb];
                b1f[nt][0] = b1.x; b1f[nt][1] = b1.y;
                b2f[nt][0] = b2.x; b2f[nt][1] = b2.y;
            }
#pragma unroll
            for (int mt = 0; mt < 2; mt++) {
                int rb = mt*16;
                uint32_t a1f[4], a2f[4];
                uint2 lo1 = *(const uint2*)&a1s[(rb + g    )*24 + kb];
                uint2 hi1 = *(const uint2*)&a1s[(rb + g + 8)*24 + kb];
                a1f[0] = lo1.x; a1f[2] = lo1.y; a1f[1] = hi1.x; a1f[3] = hi1.y;
                uint2 lo2 = *(const uint2*)&a2s[(rb + g    )*24 + kb];
                uint2 hi2 = *(const uint2*)&a2s[(rb + g + 8)*24 + kb];
                a2f[0] = lo2.x; a2f[2] = lo2.y; a2f[1] = hi2.x; a2f[3] = hi2.y;
#pragma unroll
                for (int nt = 0; nt < 4; nt++) {
                    mma_f16(acc[mt][nt], a1f, b1f[nt]);
                    mma_f16(acc[mt][nt], a2f, b1f[nt]);
                    mma_f16(acc[mt][nt], a1f, b2f[nt]);
                }
            }
        }
    }

    bool hasres = (rh1 != nullptr);
    __syncthreads();

#pragma unroll
    for (int mt = 0; mt < 2; mt++) {
#pragma unroll
        for (int nt = 0; nt < 4; nt++) {
            int p  = nt*4 + tg;
            int wd = ksperm(p);
            int co = 2*p;
#pragma unroll
            for (int half = 0; half < 2; half++) {
                int tl = rowA + mt*16 + g + half*8;
                int t  = t0 + tl;
                float v0 = acc[mt][nt][half*2 + 0] + bs[co];
                float v1 = acc[mt][nt][half*2 + 1] + bs[co + 1];
                if (hasres) {
                    size_t widx = (((size_t)b*64 + f)*1024 + t)*16 + wd;
                    uint32_t r1 = rh1[widx], r2 = rh2[widx];
                    __half2 h1v = *(__half2*)&r1, h2v = *(__half2*)&r2;
                    v0 += __half2float(h1v.x) + __half2float(h2v.x);
                    v1 += __half2float(h1v.y) + __half2float(h2v.y);
                }
                v0 = fmaxf(v0, 0.f); v1 = fmaxf(v1, 0.f);
                A1[fi*RC_SLAB + tl*24 + wd] = packhi(v0, v1);
                A2[fi*RC_SLAB + tl*24 + wd] = packlo(v0, v1);
            }
        }
    }
    __syncthreads();
#pragma unroll
    for (int l = 0; l < 4; l++) {
        int idx = tid + l*256;
        int pf  = idx >> 9;
        int rr  = (idx >> 2) & 127;
        int q   = idx & 3;
        size_t posb = ((size_t)b*64 + f0 + pf)*1024 + t0;
        *(uint4*)&oh1[(posb + rr)*16 + q*4] = *(uint4*)&A1[pf*RC_SLAB + rr*24 + q*4];
        *(uint4*)&oh2[(posb + rr)*16 + q*4] = *(uint4*)&A2[pf*RC_SLAB + rr*24 + q*4];
    }
}

// ============================================================
// fused transpose + LN(2048), reads packs -> xnT fp16 pairs
// ============================================================
__global__ void transpose_ln_kernel(const uint32_t* __restrict__ ih1,
                                    const uint32_t* __restrict__ ih2,
                                    const float* __restrict__ g,
                                    const float* __restrict__ bb,
                                    uint32_t* __restrict__ outT) {
    __shared__ float tile[64][33];
    __shared__ float rs[256], rs2[256];
    int t = blockIdx.x, b = blockIdx.y;
    int tid = threadIdx.x;
    float s = 0.f, s2 = 0.f;
    for (int i = tid; i < 1024; i += 256) {
        int fq = i >> 4, p = i & 15;
        size_t base = (((size_t)b*64 + fq)*1024 + t)*16;
        uint32_t u1 = ih1[base + ksperm(p)];
        uint32_t u2 = ih2[base + ksperm(p)];
        __half2 a = *(__half2*)&u1, c2 = *(__half2*)&u2;
        float v0 = __half2float(a.x) + __half2float(c2.x);
        float v1 = __half2float(a.y) + __half2float(c2.y);
        tile[fq][2*p]     = v0;
        tile[fq][2*p + 1] = v1;
        s  += v0 + v1;
        s2 += v0*v0 + v1*v1;
    }
    rs[tid] = s; rs2[tid] = s2;
    __syncthreads();
    for (int o = 128; o > 0; o >>= 1) {
        if (tid < o) { rs[tid] += rs[tid+o]; rs2[tid] += rs2[tid+o]; }
        __syncthreads();
    }
    float mean = rs[0] * (1.f/2048.f);
    float var  = rs2[0] * (1.f/2048.f) - mean*mean;
    float inv  = rsqrtf(var + EPSV);
    size_t ob = ((size_t)t*16 + b)*1024;
    for (int i = tid*2; i < 2048; i += 512) {
        int c = i >> 6, ff = i & 63;
        float v0 = (tile[ff    ][c] - mean)*inv*g[i]   + bb[i];
        float v1 = (tile[ff + 1][c] - mean)*inv*g[i+1] + bb[i+1];
        outT[ob + (i >> 1)] = packhi(v0, v1);
    }
}

// ============================================================
// LN(1024): fp32 (rx path) + fp16 pairs (GEMM A)
// ============================================================
__global__ void ln_kernel(const float* __restrict__ in,
                          const float* __restrict__ g,
                          const float* __restrict__ bb,
                          float* __restrict__ out,
                          uint32_t* __restrict__ outT) {
    const int W = 1024;
    int row = blockIdx.x;
    int tid = threadIdx.x;
    const float* x = in + (size_t)row * W;
    float4 v4 = *(const float4*)(x + tid*4);
    float s  = v4.x + v4.y + v4.z + v4.w;
    float s2 = v4.x*v4.x + v4.y*v4.y + v4.z*v4.z + v4.w*v4.w;
    __shared__ float rs[256], rs2[256];
    rs[tid] = s; rs2[tid] = s2;
    __syncthreads();
    for (int o = 128; o > 0; o >>= 1) {
        if (tid < o) { rs[tid] += rs[tid+o]; rs2[tid] += rs2[tid+o]; }
        __syncthreads();
    }
    float mean = rs[0] * (1.f/1024.f);
    float var  = rs2[0] * (1.f/1024.f) - mean * mean;
    float inv  = rsqrtf(var + EPSV);
    int i = tid*4;
    float4 gg = *(const float4*)(g + i);
    float4 bv = *(const float4*)(bb + i);
    float r0 = (v4.x - mean)*inv*gg.x + bv.x;
    float r1 = (v4.y - mean)*inv*gg.y + bv.y;
    float r2 = (v4.z - mean)*inv*gg.z + bv.z;
    float r3 = (v4.w - mean)*inv*gg.w + bv.w;
    *(float4*)(out + (size_t)row*W + i) = make_float4(r0, r1, r2, r3);
    uint2 pw = make_uint2(packhi(r0, r1), packhi(r2, r3));
    *(uint2*)&outT[(size_t)row*512 + tid*2] = pw;
}

// ============================================================
// FP16 GEMM; output always packed fp16 pairs [row][N/2]
// ============================================================
#define HGT (128*20)
#define HGBUF (2*HGT)

__global__ __launch_bounds__(256)
void hgemm_kernel(const uint32_t* __restrict__ A,
                  const uint32_t* __restrict__ BT,
                  uint32_t* __restrict__ Ch,
                  int M, int N, int Kw) {
    uint32_t* gsm = (uint32_t*)dynsmem;
    int tid  = threadIdx.x;
    int lane = tid & 31, warp = tid >> 5;
    int m0 = blockIdx.y * 128, n0 = blockIdx.x * 128;
    int wm = (warp >> 1) * 32;
    int wn = (warp & 1) * 64;
    int g  = lane >> 2, tg = lane & 3;
    int Nw = N >> 1;

    float acc[2][8][4];
#pragma unroll
    for (int mt = 0; mt < 2; mt++)
#pragma unroll
        for (int nt = 0; nt < 8; nt++)
#pragma unroll
            for (int i = 0; i < 4; i++) acc[mt][nt][i] = 0.f;

#define HG_STAGE(k0w_, buf_) do {                                             \
    uint32_t* as_ = gsm + (buf_)*HGBUF;                                       \
    uint32_t* bs_ = as_ + HGT;                                                \
    _Pragma("unroll")                                                         \
    for (int l = 0; l < 2; l++) {                                             \
        int idx = tid + l*256;                                                \
        int r = idx >> 2, gq = idx & 3;                                       \
        cpa16(as_ + r*20 + gq*4, A + (size_t)(m0 + r)*Kw + (k0w_) + gq*4);    \
        cpa16(bs_ + r*20 + gq*4, BT + (size_t)(n0 + r)*Kw + (k0w_) + gq*4);   \
    }                                                                         \
    asm volatile("cp.async.commit_group;\n");                                 \
} while (0)

    HG_STAGE(0, 0);
    int cur = 0;
    for (int k0w = 0; k0w < Kw; k0w += 16) {
        bool hn = (k0w + 16) < Kw;
        if (hn) {
            HG_STAGE(k0w + 16, cur ^ 1);
            asm volatile("cp.async.wait_group 1;\n");
        } else {
            asm volatile("cp.async.wait_group 0;\n");
        }
        __syncthreads();
        const uint32_t* asc = gsm + cur*HGBUF;
        const uint32_t* bsc = asc + HGT;
#pragma unroll
        for (int kc = 0; kc < 2; kc++) {
            int kb = kc * 8;
            uint32_t af[2][4];
#pragma unroll
            for (int mt = 0; mt < 2; mt++) {
                int row = wm + mt*16 + g;
                af[mt][0] = asc[(row    )*20 + kb + tg];
                af[mt][1] = asc[(row + 8)*20 + kb + tg];
                af[mt][2] = asc[(row    )*20 + kb + tg + 4];
                af[mt][3] = asc[(row + 8)*20 + kb + tg + 4];
            }
            uint32_t bf[8][2];
#pragma unroll
            for (int nt = 0; nt < 8; nt++) {
                int col = wn + nt*8 + g;
                bf[nt][0] = bsc[col*20 + kb + tg];
                bf[nt][1] = bsc[col*20 + kb + tg + 4];
            }
#pragma unroll
            for (int mt = 0; mt < 2; mt++)
#pragma unroll
                for (int nt = 0; nt < 8; nt++)
                    mma_f16(acc[mt][nt], af[mt], bf[nt]);
        }
        __syncthreads();
        cur ^= 1;
    }
#undef HG_STAGE

#pragma unroll
    for (int mt = 0; mt < 2; mt++) {
        int row = m0 + wm + mt*16 + g;
#pragma unroll
        for (int nt = 0; nt < 8; nt++) {
            int colp = ((n0 + wn + nt*8) >> 1) + tg;
            Ch[(size_t)row*Nw + colp]       = packhi(acc[mt][nt][0], acc[mt][nt][1]);
            Ch[(size_t)(row + 8)*Nw + colp] = packhi(acc[mt][nt][2], acc[mt][nt][3]);
        }
    }
}

// ============================================================
// SRU: U is fp16 pairs; 128 blocks x 128 thr
// ============================================================
__device__ __forceinline__ float sigmf(float x) {
    return __fdividef(1.f, 1.f + __expf(-x));
}

template <int KK>
__global__ __launch_bounds__(128)
void sru2_kernel(const uint32_t* __restrict__ U,
                 const float* __restrict__ xn,
                 const float* __restrict__ vc,
                 const float* __restrict__ bias,
                 float* __restrict__ out) {
    uint32_t* ub = (uint32_t*)dynsmem;              // [2][8][KK*64] words
    float* xb = (float*)(ub + 2*8*KK*64);           // [2][8][128] (KK==3)

    const int tj = threadIdx.x;
    const int bx = blockIdx.x;
    const int d  = bx >> 6;
    const int b  = (bx >> 2) & 15;
    const int jq = bx & 3;
    const int j  = jq*128 + tj;
    const int RWW = KK*512;   // words per row (N/2)

    float vf = vc[d*1024 + j],   vr = vc[d*1024 + 512 + j];
    float bf = bias[d*1024 + j], br = bias[d*1024 + 512 + j];

#define SRU_LOAD_CHUNK(cc, buf) do {                                          \
    int s0 = (cc)*8;                                                          \
    for (int idx = tj; idx < 8*KK*16; idx += 128) {                           \
        int i = idx / (KK*16);                                                \
        int o = idx - i*(KK*16);                                              \
        int gi = o >> 4, gw = o & 15;                                         \
        int t = d ? (1023 - (s0+i)) : (s0+i);                                 \
        const uint32_t* src = U + ((size_t)t*16 + b)*RWW + d*KK*256           \
                                + gi*256 + jq*64 + gw*4;                      \
        cpa16(ub + ((size_t)((buf)*8 + i)*KK + gi)*64 + gw*4, src);           \
    }                                                                         \
    if (KK == 3) {                                                            \
        for (int idx = tj; idx < 256; idx += 128) {                           \
            int i = idx >> 5, gw = idx & 31;                                  \
            int t = d ? (1023 - (s0+i)) : (s0+i);                             \
            const float* src = xn + ((size_t)t*16 + b)*1024 + d*512           \
                                  + jq*128 + gw*4;                            \
            cpa16(xb + ((buf)*8 + i)*128 + gw*4, src);                        \
        }                                                                     \
    }                                                                         \
    asm volatile("cp.async.commit_group;\n");                                 \
} while (0)

    SRU_LOAD_CHUNK(0, 0);
    float c = 0.f;
    for (int ch = 0; ch < 128; ch++) {
        int buf = ch & 1;
        if (ch < 127) {
            SRU_LOAD_CHUNK(ch + 1, buf ^ 1);
            asm volatile("cp.async.wait_group 1;\n");
        } else {
            asm volatile("cp.async.wait_group 0;\n");
        }
        __syncthreads();
#pragma unroll
        for (int i = 0; i < 8; i++) {
            int s = ch*8 + i;
            int t = d ? (1023 - s) : s;
            const __half* us = (const __half*)(ub + (size_t)(buf*8 + i)*KK*64);
            float a0 = __half2float(us[tj]);
            float a1 = __half2float(us[128 + tj]);
            float a2 = __half2float(us[256 + tj]);
            float rx = (KK == 4) ? __half2float(us[384 + tj])
                                 : xb[(buf*8 + i)*128 + tj];
            float f = sigmf(fmaf(vf, c, a1) + bf);
            c = fmaf(f, c - a0, a0);
            float r = sigmf(fmaf(vr, c, a2) + br);
            out[((size_t)t*16 + b)*1024 + d*512 + j] = fmaf(r, c - rx, rx);
        }
        __syncthreads();
    }
#undef SRU_LOAD_CHUNK
}

// ============================================================
// final v3: 8 rows per block
// ============================================================
__global__ void final_kernel(const float* __restrict__ s,
                             const float* __restrict__ g,
                             const float* __restrict__ bb,
                             const float* __restrict__ cw,
                             float* __restrict__ out) {
    int tid = threadIdx.x;
    __shared__ float rs[256], rs2[256];
    __shared__ float sacc[30];

    for (int rr = 0; rr < 8; rr++) {
        int row = blockIdx.x*8 + rr;
        int t = row >> 4, b = row & 15;
        const float* x = s + (size_t)row * 1024;

        float4 v4 = *(const float4*)(x + tid*4);
        float sm = v4.x + v4.y + v4.z + v4.w;
        float s2 = v4.x*v4.x + v4.y*v4.y + v4.z*v4.z + v4.w*v4.w;
        rs[tid] = sm; rs2[tid] = s2;
        __syncthreads();
        for (int o = 128; o > 0; o >>= 1) {
            if (tid < o) { rs[tid] += rs[tid+o]; rs2[tid] += rs2[tid+o]; }
            __syncthreads();
        }
        float mean = rs[0] * (1.f/1024.f);
        float var  = rs2[0] * (1.f/1024.f) - mean*mean;
        float inv  = rsqrtf(var + EPSV);

        float acc[30];
#pragma unroll
        for (int k = 0; k < 30; k++) acc[k] = 0.f;
        for (int dd = tid; dd < 1024; dd += 256) {
            float v = (x[dd] - mean)*inv*g[dd] + bb[dd];
            const float* cwr = cw + dd*30;
#pragma unroll
            for (int k = 0; k < 30; k++)
                acc[k] = fmaf(v, cwr[k], acc[k]);
        }

        if (tid < 30) sacc[tid] = 0.f;
        __syncthreads();
#pragma unroll
        for (int k = 0; k < 30; k++) {
            float v = acc[k];
#pragma unroll
            for (int o = 16; o > 0; o >>= 1)
                v += __shfl_down_sync(0xffffffffu, v, o);
            if ((tid & 31) == 0) atomicAdd(&sacc[k], v);
        }
        __syncthreads();
        if (tid < 30)
            out[((size_t)b*1024 + t)*30 + tid] = sacc[tid];
        __syncthreads();
    }
}

// ============================================================
// host orchestration
// ============================================================
extern "C" void kernel_launch(void* const* d_in, const int* in_sizes, int n_in,
                              void* d_out, int out_size) {
    const float* x       = (const float*)d_in[0];
    const float* conv0_w = (const float*)d_in[1];
    const float* conv0_b = (const float*)d_in[2];
    const float* rc1w = (const float*)d_in[3];
    const float* rc1b = (const float*)d_in[4];
    const float* rb1g = (const float*)d_in[5];
    const float* rb1b = (const float*)d_in[6];
    const float* rb1m = (const float*)d_in[7];
    const float* rb1v = (const float*)d_in[8];
    const float* rc2w = (const float*)d_in[9];
    const float* rc2b = (const float*)d_in[10];
    const float* rb2g = (const float*)d_in[11];
    const float* rb2b = (const float*)d_in[12];
    const float* rb2m = (const float*)d_in[13];
    const float* rb2v = (const float*)d_in[14];
    const float* ln0g = (const float*)d_in[15];
    const float* ln0b = (const float*)d_in[16];
    const float* wproj0 = (const float*)d_in[17];
    const float* w0   = (const float*)d_in[18];
    const float* vc0  = (const float*)d_in[19];
    const float* bias0= (const float*)d_in[20];
    const float* lng  = (const float*)d_in[21];
    const float* lnb  = (const float*)d_in[22];
    const float* wproj= (const float*)d_in[23];
    const float* w    = (const float*)d_in[24];
    const float* vc   = (const float*)d_in[25];
    const float* bias = (const float*)d_in[26];
    const float* clng = (const float*)d_in[27];
    const float* clnb = (const float*)d_in[28];
    const float* clsw = (const float*)d_in[29];

    float *xn, *sa, *sb, *bias2;
    uint32_t *xnT, *tmp, *U, *w1, *w2, *h1A, *h2A, *h1B, *h2B, *wpT, *wwT;
    cudaGetSymbolAddress((void**)&xn,    g_xn);
    cudaGetSymbolAddress((void**)&xnT,   g_xnT);
    cudaGetSymbolAddress((void**)&tmp,   g_tmp);
    cudaGetSymbolAddress((void**)&U,     g_U);
    cudaGetSymbolAddress((void**)&sa,    g_sa);
    cudaGetSymbolAddress((void**)&sb,    g_sb);
    cudaGetSymbolAddress((void**)&w1,    g_w1);
    cudaGetSymbolAddress((void**)&w2,    g_w2);
    cudaGetSymbolAddress((void**)&bias2, g_bias2);
    cudaGetSymbolAddress((void**)&h1A,   g_h1A);
    cudaGetSymbolAddress((void**)&h2A,   g_h2A);
    cudaGetSymbolAddress((void**)&h1B,   g_h1B);
    cudaGetSymbolAddress((void**)&h2B,   g_h2B);
    cudaGetSymbolAddress((void**)&wpT,   g_wpT);
    cudaGetSymbolAddress((void**)&wwT,   g_wwT);

    cudaFuncSetAttribute(resconv_mma_kernel,
                         cudaFuncAttributeMaxDynamicSharedMemorySize, RC_WORDS*4);
    cudaFuncSetAttribute(hgemm_kernel,
                         cudaFuncAttributeMaxDynamicSharedMemorySize, 2*HGBUF*4);
    cudaFuncSetAttribute(sru2_kernel<4>,
                         cudaFuncAttributeMaxDynamicSharedMemorySize, 24576);
    cudaFuncSetAttribute(sru2_kernel<3>,
                         cudaFuncAttributeMaxDynamicSharedMemorySize, 24576);

    // ---- weight prep ----
    trT_all_kernel<<<4608, dim3(32, 8)>>>(wproj0, w0, wproj, w, wpT, wwT);
    prep_conv_all_kernel<<<dim3(5, 6), 1024>>>(rc1w, rc1b, rb1g, rb1b, rb1m, rb1v,
                                               rc2w, rc2b, rb2g, rb2b, rb2m, rb2v,
                                               w1, w2, bias2);

    // ---- conv front-end ----
    conv0_kernel<<<dim3(4, 64, 16), 256>>>(x, conv0_w, conv0_b, h1A, h2A);

    dim3 rcgrid(8, 32, 16);
    for (int i = 0; i < 3; i++) {
        resconv_mma_kernel<<<rcgrid, 256, RC_WORDS*4>>>(h1A, h2A,
            w1 + (2*i)*4864, w2 + (2*i)*4864, bias2 + (2*i)*32,
            nullptr, nullptr, h1B, h2B);
        resconv_mma_kernel<<<rcgrid, 256, RC_WORDS*4>>>(h1B, h2B,
            w1 + (2*i+1)*4864, w2 + (2*i+1)*4864, bias2 + (2*i+1)*32,
            h1A, h2A, h1A, h2A);
    }

    // ---- transpose+LN(2048) ----
    transpose_ln_kernel<<<dim3(1024, 16), 256>>>(h1A, h2A, ln0g, ln0b, xnT);

    // ---- SRU layer 0 (k=4) ----
    hgemm_kernel<<<dim3(2, 128), 256, 2*HGBUF*4>>>(xnT, wpT, tmp, NROWS, 256, 1024);
    hgemm_kernel<<<dim3(32, 128), 256, 2*HGBUF*4>>>(tmp, wwT, U, NROWS, 4096, 128);
    sru2_kernel<4><<<128, 128, 24576>>>(U, xn, vc0, bias0, sa);

    // ---- SRU layers 1-3 (k=3) ----
    float* cur = sa;
    float* nxt = sb;
    for (int i = 0; i < 3; i++) {
        ln_kernel<<<NROWS, 256>>>(cur, lng + i*1024, lnb + i*1024, xn, xnT);
        hgemm_kernel<<<dim3(2, 128), 256, 2*HGBUF*4>>>(xnT, wpT + 262144 + i*131072,
                                                       tmp, NROWS, 256, 512);
        hgemm_kernel<<<dim3(24, 128), 256, 2*HGBUF*4>>>(tmp, wwT + 524288 + i*393216,
                                                        U, NROWS, 3072, 128);
        sru2_kernel<3><<<128, 128, 24576>>>(U, xn, vc + i*2048, bias + i*2048, nxt);
        float* t2 = cur; cur = nxt; nxt = t2;
    }

    // ---- final LN + classifier ----
    final_kernel<<<NROWS/8, 256>>>(cur, clng, clnb, clsw, (float*)d_out);
}